// round 1
// baseline (speedup 1.0000x reference)
#include <cuda_runtime.h>
#include <cuda_bf16.h>
#include <math.h>

// ---------------- problem constants ----------------
#define B_    2
#define L_    2048
#define DM    1024          // d_model
#define DI    2048          // d_inner
#define NH    32            // nheads
#define HD    64            // headdim
#define DS    128           // d_state
#define CONVD 2304          // conv dim = DI + 2*DS
#define DPROJ 4384          // 2*DI + 2*DS + NH
#define NCH   8             // chunks per batch
#define CH    256           // chunk length
#define ROWS  4096          // B_*L_

// ---------------- scratch (device globals; no allocation allowed) ----------------
__device__ float g_u[ROWS * DM];                    // rmsnorm(x)
__device__ float g_zx[(size_t)ROWS * DPROJ];        // in_proj output
__device__ float g_xbc[(size_t)ROWS * CONVD];       // conv+silu output
__device__ float g_dt[ROWS * NH];                   // softplus(dt)
__device__ float g_acs[B_ * NH * NCH * CH];         // cumsum(dt*A) per chunk
__device__ float g_states[(size_t)B_ * NCH * NH * HD * DS];
__device__ float g_init[(size_t)B_ * NCH * NH * HD * DS];
__device__ float g_cb[(size_t)B_ * NCH * CH * CH];  // Cm @ Bm^T per chunk
__device__ float g_y[(size_t)ROWS * DI];            // y (pre/post gated-norm)

// ---------------- helpers ----------------
__device__ __forceinline__ float blockReduceSum256(float v) {
    __shared__ float ws[8];
    __shared__ float tot;
    int lane = threadIdx.x & 31, wid = threadIdx.x >> 5;
#pragma unroll
    for (int o = 16; o; o >>= 1) v += __shfl_xor_sync(0xffffffffu, v, o);
    if (lane == 0) ws[wid] = v;
    __syncthreads();
    if (threadIdx.x == 0) {
        float s = 0.f;
#pragma unroll
        for (int i = 0; i < 8; i++) s += ws[i];
        tot = s;
    }
    __syncthreads();
    return tot;
}

// ---------------- K1: rmsnorm(x) -> g_u ----------------
__global__ void rmsnorm_x_kernel(const float* __restrict__ x,
                                 const float* __restrict__ w) {
    int row = blockIdx.x, tid = threadIdx.x;
    const float* xr = x + (size_t)row * DM;
    float vals[4];
    float local = 0.f;
#pragma unroll
    for (int i = 0; i < 4; i++) {
        float v = xr[tid + i * 256];
        vals[i] = v;
        local += v * v;
    }
    float tot = blockReduceSum256(local);
    float r = rsqrtf(tot / (float)DM + 1e-5f);
#pragma unroll
    for (int i = 0; i < 4; i++) {
        int d = tid + i * 256;
        g_u[(size_t)row * DM + d] = vals[i] * r * w[d];
    }
}

// ---------------- generic NT SGEMM: C[M,N] = A[M,K] * B[N,K]^T (+residual) -----
// 128x128 tile, K-step 8, 256 threads, 8x8 per thread. M must be multiple of 128,
// K multiple of 8. N guarded.
__global__ __launch_bounds__(256) void sgemm_nt(const float* __restrict__ A,
                                                const float* __restrict__ B,
                                                float* __restrict__ C,
                                                const float* __restrict__ resid,
                                                int M, int N, int K, int addRes) {
    __shared__ float As[8][128];
    __shared__ float Bs[8][128];
    int tid = threadIdx.x;
    int bm = blockIdx.y * 128, bn = blockIdx.x * 128;
    int tx = tid & 15, ty = tid >> 4;
    int lr = tid >> 1;
    int lc = (tid & 1) * 4;

    float acc[8][8];
#pragma unroll
    for (int i = 0; i < 8; i++)
#pragma unroll
        for (int j = 0; j < 8; j++) acc[i][j] = 0.f;

    const float* Aptr = A + (size_t)(bm + lr) * K + lc;
    const float* Bptr = B + (size_t)(bn + lr) * K + lc;
    bool bok = (bn + lr) < N;

    for (int k0 = 0; k0 < K; k0 += 8) {
        float4 av = *(const float4*)(Aptr + k0);
        float4 bv = make_float4(0.f, 0.f, 0.f, 0.f);
        if (bok) bv = *(const float4*)(Bptr + k0);
        As[lc + 0][lr] = av.x; As[lc + 1][lr] = av.y;
        As[lc + 2][lr] = av.z; As[lc + 3][lr] = av.w;
        Bs[lc + 0][lr] = bv.x; Bs[lc + 1][lr] = bv.y;
        Bs[lc + 2][lr] = bv.z; Bs[lc + 3][lr] = bv.w;
        __syncthreads();
#pragma unroll
        for (int kk = 0; kk < 8; kk++) {
            float4 a0 = *(const float4*)&As[kk][ty * 8];
            float4 a1 = *(const float4*)&As[kk][ty * 8 + 4];
            float4 b0 = *(const float4*)&Bs[kk][tx * 8];
            float4 b1 = *(const float4*)&Bs[kk][tx * 8 + 4];
            float a[8] = {a0.x, a0.y, a0.z, a0.w, a1.x, a1.y, a1.z, a1.w};
            float b[8] = {b0.x, b0.y, b0.z, b0.w, b1.x, b1.y, b1.z, b1.w};
#pragma unroll
            for (int i = 0; i < 8; i++)
#pragma unroll
                for (int j = 0; j < 8; j++) acc[i][j] += a[i] * b[j];
        }
        __syncthreads();
    }

#pragma unroll
    for (int i = 0; i < 8; i++) {
        int m = bm + ty * 8 + i;
#pragma unroll
        for (int j = 0; j < 8; j++) {
            int n = bn + tx * 8 + j;
            if (n < N) {
                float v = acc[i][j];
                if (addRes) v += resid[(size_t)m * N + n];
                C[(size_t)m * N + n] = v;
            }
        }
    }
}

// ---------------- K3: depthwise causal conv (width 4) + bias + silu ----------
__global__ void conv_silu_kernel(const float* __restrict__ conv_w,
                                 const float* __restrict__ conv_b) {
    int idx = blockIdx.x * blockDim.x + threadIdx.x;  // ROWS*CONVD
    int c = idx % CONVD;
    int row = idx / CONVD;
    int l = row & (L_ - 1);
    const float* w = conv_w + c * 4;
    float acc = conv_b[c];
#pragma unroll
    for (int j = 0; j < 4; j++) {
        int ls = l - 3 + j;
        if (ls >= 0)
            acc += w[j] * g_zx[(size_t)(row - 3 + j) * DPROJ + DI + c];
    }
    float s = acc / (1.f + __expf(-acc));
    g_xbc[(size_t)row * CONVD + c] = s;
}

// ---------------- K4: dt = softplus(dt_raw + dt_bias) ----------
__global__ void dt_kernel(const float* __restrict__ dt_bias) {
    int idx = blockIdx.x * blockDim.x + threadIdx.x;  // ROWS*NH
    int h = idx & (NH - 1);
    int row = idx >> 5;
    float v = g_zx[(size_t)row * DPROJ + (DI + CONVD) + h] + dt_bias[h];
    float sp = (v > 20.f) ? v : log1pf(__expf(v));
    g_dt[row * NH + h] = sp;
}

// ---------------- K5: per-chunk cumsum of a = dt * A ----------
__global__ void acs_kernel(const float* __restrict__ A_log) {
    int bid = blockIdx.x;  // (b*NH + h)*NCH + c
    int b = bid >> 8, h = (bid >> 3) & 31, c = bid & 7;
    int l = threadIdx.x;
    int row = b * L_ + c * CH + l;
    float A = -__expf(A_log[h]);
    __shared__ float s[CH];
    s[l] = g_dt[row * NH + h] * A;
    __syncthreads();
#pragma unroll
    for (int off = 1; off < CH; off <<= 1) {
        float v = (l >= off) ? s[l - off] : 0.f;
        __syncthreads();
        s[l] += v;
        __syncthreads();
    }
    g_acs[bid * CH + l] = s[l];
}

// ---------------- K6: per-chunk states[p,n] = sum_l decay*xd[l,p]*B[l,n] -----
__global__ __launch_bounds__(256) void states_kernel() {
    int bid = blockIdx.x;  // (b*NCH + c)*NH + h
    int b = bid >> 8, c = (bid >> 5) & 7, h = bid & 31;
    int tid = threadIdx.x;
    int tx = tid & 15, ty = tid >> 4;
    __shared__ float xdw[16][64];
    __shared__ float bs[16][128];
    __shared__ float coef[16];
    int base = ((b * NH + h) * NCH + c) * CH;
    float acs_last = g_acs[base + CH - 1];
    int rowbase = b * L_ + c * CH;

    float acc[4][8];
#pragma unroll
    for (int i = 0; i < 4; i++)
#pragma unroll
        for (int j = 0; j < 8; j++) acc[i][j] = 0.f;

    for (int l0 = 0; l0 < CH; l0 += 16) {
        __syncthreads();
        if (tid < 16) {
            int row = rowbase + l0 + tid;
            coef[tid] = g_dt[row * NH + h] * __expf(acs_last - g_acs[base + l0 + tid]);
        }
        __syncthreads();
#pragma unroll
        for (int e = tid; e < 16 * 64; e += 256) {
            int ll = e >> 6, p = e & 63;
            int row = rowbase + l0 + ll;
            xdw[ll][p] = g_xbc[(size_t)row * CONVD + h * HD + p] * coef[ll];
        }
#pragma unroll
        for (int e = tid; e < 16 * 128; e += 256) {
            int ll = e >> 7, n = e & 127;
            int row = rowbase + l0 + ll;
            bs[ll][n] = g_xbc[(size_t)row * CONVD + DI + n];
        }
        __syncthreads();
#pragma unroll
        for (int ll = 0; ll < 16; ll++) {
            float4 a4 = *(const float4*)&xdw[ll][ty * 4];
            float4 b0 = *(const float4*)&bs[ll][tx * 8];
            float4 b1 = *(const float4*)&bs[ll][tx * 8 + 4];
            float a[4] = {a4.x, a4.y, a4.z, a4.w};
            float bb[8] = {b0.x, b0.y, b0.z, b0.w, b1.x, b1.y, b1.z, b1.w};
#pragma unroll
            for (int i = 0; i < 4; i++)
#pragma unroll
                for (int j = 0; j < 8; j++) acc[i][j] += a[i] * bb[j];
        }
    }
    size_t out = (size_t)bid * HD * DS;
#pragma unroll
    for (int i = 0; i < 4; i++)
#pragma unroll
        for (int j = 0; j < 8; j++)
            g_states[out + (size_t)(ty * 4 + i) * DS + tx * 8 + j] = acc[i][j];
}

// ---------------- K7: chunk recurrence (serial over 8 chunks) ----------
__global__ void recur_kernel() {
    int idx = blockIdx.x * blockDim.x + threadIdx.x;  // B_*NH*HD*DS
    int n = idx & 127;
    int p = (idx >> 7) & 63;
    int h = (idx >> 13) & 31;
    int b = idx >> 18;
    float run = 0.f;
#pragma unroll
    for (int c = 0; c < NCH; c++) {
        size_t sidx = ((size_t)((b * NCH + c) * NH + h) * HD + p) * DS + n;
        g_init[sidx] = run;
        float cs = g_acs[((b * NH + h) * NCH + c) * CH + CH - 1];
        run = run * __expf(cs) + g_states[sidx];
    }
}

// ---------------- K8: CB[l,s] = Cm[l]·Bm[s] per (b,c) ----------
__global__ __launch_bounds__(256) void cb_kernel() {
    int z = blockIdx.z;  // b*NCH + c
    int b = z >> 3, c = z & 7;
    int l0 = blockIdx.y * 64, s0 = blockIdx.x * 64;
    int tid = threadIdx.x;
    int tx = tid & 15, ty = tid >> 4;
    __shared__ float ct[16][64];
    __shared__ float bt[16][64];
    int rowbase = b * L_ + c * CH;
    float acc[4][4];
#pragma unroll
    for (int i = 0; i < 4; i++)
#pragma unroll
        for (int j = 0; j < 4; j++) acc[i][j] = 0.f;

    for (int k0 = 0; k0 < DS; k0 += 16) {
        __syncthreads();
#pragma unroll
        for (int e = tid; e < 1024; e += 256) {
            int kk = e & 15, i = e >> 4;
            ct[kk][i] = g_xbc[(size_t)(rowbase + l0 + i) * CONVD + DI + DS + k0 + kk];
            bt[kk][i] = g_xbc[(size_t)(rowbase + s0 + i) * CONVD + DI + k0 + kk];
        }
        __syncthreads();
#pragma unroll
        for (int kk = 0; kk < 16; kk++) {
            float4 a4 = *(const float4*)&ct[kk][ty * 4];
            float4 b4 = *(const float4*)&bt[kk][tx * 4];
            float a[4] = {a4.x, a4.y, a4.z, a4.w};
            float bb[4] = {b4.x, b4.y, b4.z, b4.w};
#pragma unroll
            for (int i = 0; i < 4; i++)
#pragma unroll
                for (int j = 0; j < 4; j++) acc[i][j] += a[i] * bb[j];
        }
    }
#pragma unroll
    for (int i = 0; i < 4; i++)
#pragma unroll
        for (int j = 0; j < 4; j++)
            g_cb[((size_t)z * CH + l0 + ty * 4 + i) * CH + s0 + tx * 4 + j] = acc[i][j];
}

// ---------------- K9: Y = Y_off + Y_diag + D*xh per (b,c,h) ----------
__global__ __launch_bounds__(256) void y_kernel(const float* __restrict__ Dvec) {
    int bid = blockIdx.x;  // (b*NCH + c)*NH + h
    int b = bid >> 8, c = (bid >> 5) & 7, h = bid & 31;
    int tid = threadIdx.x;
    int tx = tid & 7, ty = tid >> 3;  // tx: 8 p-groups, ty: 32 l-groups
    __shared__ float acs_s[CH];
    __shared__ float mt[CH][17];
    __shared__ float xt[16][68];
    int base = ((b * NH + h) * NCH + c) * CH;
    acs_s[tid] = g_acs[base + tid];
    int rowbase = b * L_ + c * CH;
    float Dh = Dvec[h];
    size_t initbase = (size_t)bid * HD * DS;

    float acc[8][8];
#pragma unroll
    for (int i = 0; i < 8; i++)
#pragma unroll
        for (int j = 0; j < 8; j++) acc[i][j] = 0.f;

    // Phase 1: Y_off = Cm @ init_state^T  (scaled by exp(acs[l]) afterwards)
    for (int n0 = 0; n0 < DS; n0 += 16) {
        __syncthreads();
        {
            int l = tid;
            const float* cm = &g_xbc[(size_t)(rowbase + l) * CONVD + DI + DS + n0];
#pragma unroll
            for (int nn = 0; nn < 16; nn++) mt[l][nn] = cm[nn];
        }
#pragma unroll
        for (int e = tid; e < 1024; e += 256) {
            int p = e >> 4, nn = e & 15;
            xt[nn][p] = g_init[initbase + (size_t)p * DS + n0 + nn];
        }
        __syncthreads();
#pragma unroll
        for (int nn = 0; nn < 16; nn++) {
            float4 x0 = *(const float4*)&xt[nn][tx * 8];
            float4 x1 = *(const float4*)&xt[nn][tx * 8 + 4];
            float xv[8] = {x0.x, x0.y, x0.z, x0.w, x1.x, x1.y, x1.z, x1.w};
            float mv[8];
#pragma unroll
            for (int i = 0; i < 8; i++) mv[i] = mt[ty * 8 + i][nn];
#pragma unroll
            for (int i = 0; i < 8; i++)
#pragma unroll
                for (int j = 0; j < 8; j++) acc[i][j] += mv[i] * xv[j];
        }
    }
    // scale by exp(acs[l])
#pragma unroll
    for (int i = 0; i < 8; i++) {
        float el = __expf(acs_s[ty * 8 + i]);
#pragma unroll
        for (int j = 0; j < 8; j++) acc[i][j] *= el;
    }

    // Phase 2: Y_diag = (CB ∘ L) @ xd
    for (int s0 = 0; s0 < CH; s0 += 16) {
        __syncthreads();
        {
            int l = tid;
            float al = acs_s[l];
            const float* cbr = &g_cb[((size_t)(b * NCH + c) * CH + l) * CH + s0];
#pragma unroll
            for (int ss = 0; ss < 16; ss++) {
                int s = s0 + ss;
                mt[l][ss] = (s <= l) ? cbr[ss] * __expf(al - acs_s[s]) : 0.f;
            }
        }
#pragma unroll
        for (int e = tid; e < 1024; e += 256) {
            int ss = e >> 6, p = e & 63;
            int row = rowbase + s0 + ss;
            xt[ss][p] = g_xbc[(size_t)row * CONVD + h * HD + p] * g_dt[row * NH + h];
        }
        __syncthreads();
        if (s0 <= ty * 8 + 7) {
#pragma unroll
            for (int ss = 0; ss < 16; ss++) {
                float4 x0 = *(const float4*)&xt[ss][tx * 8];
                float4 x1 = *(const float4*)&xt[ss][tx * 8 + 4];
                float xv[8] = {x0.x, x0.y, x0.z, x0.w, x1.x, x1.y, x1.z, x1.w};
                float mv[8];
#pragma unroll
                for (int i = 0; i < 8; i++) mv[i] = mt[ty * 8 + i][ss];
#pragma unroll
                for (int i = 0; i < 8; i++)
#pragma unroll
                    for (int j = 0; j < 8; j++) acc[i][j] += mv[i] * xv[j];
            }
        }
    }

    // epilogue: + D*xh, write y
#pragma unroll
    for (int i = 0; i < 8; i++) {
        int row = rowbase + ty * 8 + i;
#pragma unroll
        for (int j = 0; j < 8; j++) {
            int p = tx * 8 + j;
            float xh = g_xbc[(size_t)row * CONVD + h * HD + p];
            g_y[(size_t)row * DI + h * HD + p] = acc[i][j] + Dh * xh;
        }
    }
}

// ---------------- K10: gated rmsnorm: y = rmsnorm(y * silu(z)) * gnorm_w ------
__global__ void gated_norm_kernel(const float* __restrict__ gw) {
    int row = blockIdx.x, tid = threadIdx.x;
    __shared__ float buf[DI];
    float local = 0.f;
#pragma unroll
    for (int d = tid; d < DI; d += 256) {
        float z = g_zx[(size_t)row * DPROJ + d];
        float y = g_y[(size_t)row * DI + d];
        float v = y * (z / (1.f + __expf(-z)));
        buf[d] = v;
        local += v * v;
    }
    float tot = blockReduceSum256(local);
    float r = rsqrtf(tot / (float)DI + 1e-5f);
#pragma unroll
    for (int d = tid; d < DI; d += 256)
        g_y[(size_t)row * DI + d] = buf[d] * r * gw[d];
}

// ---------------- launch ----------------
extern "C" void kernel_launch(void* const* d_in, const int* in_sizes, int n_in,
                              void* d_out, int out_size) {
    const float* x         = (const float*)d_in[0];
    const float* norm_w    = (const float*)d_in[1];
    const float* in_proj_w = (const float*)d_in[2];
    const float* conv_w    = (const float*)d_in[3];
    const float* conv_b    = (const float*)d_in[4];
    const float* dt_bias   = (const float*)d_in[5];
    const float* A_log     = (const float*)d_in[6];
    const float* Dv        = (const float*)d_in[7];
    const float* gnorm_w   = (const float*)d_in[8];
    const float* out_proj_w= (const float*)d_in[9];
    float* out = (float*)d_out;

    float *pu, *pzx, *py;
    cudaGetSymbolAddress((void**)&pu, g_u);
    cudaGetSymbolAddress((void**)&pzx, g_zx);
    cudaGetSymbolAddress((void**)&py, g_y);

    rmsnorm_x_kernel<<<ROWS, 256>>>(x, norm_w);
    sgemm_nt<<<dim3((DPROJ + 127) / 128, ROWS / 128), 256>>>(
        pu, in_proj_w, pzx, nullptr, ROWS, DPROJ, DM, 0);
    conv_silu_kernel<<<(ROWS * CONVD) / 256, 256>>>(conv_w, conv_b);
    dt_kernel<<<(ROWS * NH) / 256, 256>>>(dt_bias);
    acs_kernel<<<B_ * NH * NCH, 256>>>(A_log);
    states_kernel<<<B_ * NCH * NH, 256>>>();
    recur_kernel<<<(B_ * NH * HD * DS) / 256, 256>>>();
    cb_kernel<<<dim3(4, 4, B_ * NCH), 256>>>();
    y_kernel<<<B_ * NCH * NH, 256>>>(Dv);
    gated_norm_kernel<<<ROWS, 256>>>(gnorm_w);
    sgemm_nt<<<dim3(DM / 128, ROWS / 128), 256>>>(
        py, out_proj_w, out, x, ROWS, DM, DI, 1);
}

// round 2
// speedup vs baseline: 1.3364x; 1.3364x over previous
#include <cuda_runtime.h>
#include <cuda_bf16.h>
#include <math.h>

// ---------------- problem constants ----------------
#define B_    2
#define L_    2048
#define DM    1024          // d_model
#define DI    2048          // d_inner
#define NH    32            // nheads
#define HD    64            // headdim
#define DS    128           // d_state
#define CONVD 2304          // conv dim = DI + 2*DS
#define DPROJ 4384          // 2*DI + 2*DS + NH
#define NCH   8             // chunks per batch
#define CH    256           // chunk length
#define ROWS  4096          // B_*L_

// ---------------- scratch (device globals; no allocation allowed) ----------------
__device__ float g_u[ROWS * DM];                    // rmsnorm(x)
__device__ float g_zx[(size_t)ROWS * DPROJ];        // in_proj output
__device__ float g_xbc[(size_t)ROWS * CONVD];       // conv+silu output
__device__ float g_dt[ROWS * NH];                   // softplus(dt)
__device__ float g_acs[B_ * NH * NCH * CH];         // cumsum(dt*A) per chunk
__device__ float g_states[(size_t)B_ * NCH * NH * HD * DS];
__device__ float g_init[(size_t)B_ * NCH * NH * HD * DS];
__device__ float g_cb[(size_t)B_ * NCH * CH * CH];  // Cm @ Bm^T per chunk
__device__ float g_y[(size_t)ROWS * DI];            // y (pre/post gated-norm)

// ---------------- helpers ----------------
__device__ __forceinline__ float blockReduceSum256(float v) {
    __shared__ float ws[8];
    __shared__ float tot;
    int lane = threadIdx.x & 31, wid = threadIdx.x >> 5;
#pragma unroll
    for (int o = 16; o; o >>= 1) v += __shfl_xor_sync(0xffffffffu, v, o);
    if (lane == 0) ws[wid] = v;
    __syncthreads();
    if (threadIdx.x == 0) {
        float s = 0.f;
#pragma unroll
        for (int i = 0; i < 8; i++) s += ws[i];
        tot = s;
    }
    __syncthreads();
    return tot;
}

__device__ __forceinline__ unsigned tf32_rna(float v) {
    unsigned r;
    asm("cvt.rna.tf32.f32 %0, %1;" : "=r"(r) : "f"(v));
    return r;
}

__device__ __forceinline__ void mma_tf32(float* d, const unsigned* a, const unsigned* b) {
    asm volatile(
        "mma.sync.aligned.m16n8k8.row.col.f32.tf32.tf32.f32 "
        "{%0,%1,%2,%3}, {%4,%5,%6,%7}, {%8,%9}, {%0,%1,%2,%3};"
        : "+f"(d[0]), "+f"(d[1]), "+f"(d[2]), "+f"(d[3])
        : "r"(a[0]), "r"(a[1]), "r"(a[2]), "r"(a[3]), "r"(b[0]), "r"(b[1]));
}

// ---------------- K1: rmsnorm(x) -> g_u ----------------
__global__ void rmsnorm_x_kernel(const float* __restrict__ x,
                                 const float* __restrict__ w) {
    int row = blockIdx.x, tid = threadIdx.x;
    const float* xr = x + (size_t)row * DM;
    float vals[4];
    float local = 0.f;
#pragma unroll
    for (int i = 0; i < 4; i++) {
        float v = xr[tid + i * 256];
        vals[i] = v;
        local += v * v;
    }
    float tot = blockReduceSum256(local);
    float r = rsqrtf(tot / (float)DM + 1e-5f);
#pragma unroll
    for (int i = 0; i < 4; i++) {
        int d = tid + i * 256;
        g_u[(size_t)row * DM + d] = vals[i] * r * w[d];
    }
}

// ---------------- tensor-core NT GEMM (3xTF32): C[M,N]=A[M,K]*B[N,K]^T (+res) --
// 128x128 block tile, k-step 16, 256 threads = 8 warps (2 in M x 4 in N),
// warp tile 64x32 (4 m16-tiles x 4 n8-tiles). M%128==0, K%16==0, N guarded.
#define KSTEP 16
#define SPAD  4
__global__ __launch_bounds__(256) void mma_nt(const float* __restrict__ A,
                                              const float* __restrict__ B,
                                              float* __restrict__ C,
                                              const float* __restrict__ resid,
                                              int M, int N, int K, int addRes) {
    __shared__ __align__(16) float As[128][KSTEP + SPAD];
    __shared__ __align__(16) float Bs[128][KSTEP + SPAD];
    int tid = threadIdx.x;
    int warp = tid >> 5, lane = tid & 31;
    int wm = warp & 1, wn = warp >> 1;  // 2 x 4
    int bm = blockIdx.y * 128, bn = blockIdx.x * 128;
    int g = lane >> 2, tg = lane & 3;

    float acc[4][4][4];
#pragma unroll
    for (int mt = 0; mt < 4; mt++)
#pragma unroll
        for (int nt = 0; nt < 4; nt++)
#pragma unroll
            for (int q = 0; q < 4; q++) acc[mt][nt][q] = 0.f;

    int lrow = tid >> 2;        // 0..63
    int lcol = (tid & 3) * 4;   // 0,4,8,12
    const float* Ap0 = A + (size_t)(bm + lrow) * K + lcol;
    const float* Ap1 = A + (size_t)(bm + 64 + lrow) * K + lcol;
    const float* Bp0 = B + (size_t)(bn + lrow) * K + lcol;
    const float* Bp1 = B + (size_t)(bn + 64 + lrow) * K + lcol;
    bool bok0 = (bn + lrow) < N, bok1 = (bn + 64 + lrow) < N;
    const float4 z4 = make_float4(0.f, 0.f, 0.f, 0.f);

    float4 ra0 = *(const float4*)Ap0;
    float4 ra1 = *(const float4*)Ap1;
    float4 rb0 = bok0 ? *(const float4*)Bp0 : z4;
    float4 rb1 = bok1 ? *(const float4*)Bp1 : z4;

    for (int k0 = 0; k0 < K; k0 += KSTEP) {
        *(float4*)&As[lrow][lcol] = ra0;
        *(float4*)&As[64 + lrow][lcol] = ra1;
        *(float4*)&Bs[lrow][lcol] = rb0;
        *(float4*)&Bs[64 + lrow][lcol] = rb1;
        __syncthreads();
        int kn = k0 + KSTEP;
        if (kn < K) {
            ra0 = *(const float4*)(Ap0 + kn);
            ra1 = *(const float4*)(Ap1 + kn);
            rb0 = bok0 ? *(const float4*)(Bp0 + kn) : z4;
            rb1 = bok1 ? *(const float4*)(Bp1 + kn) : z4;
        }
#pragma unroll
        for (int kk = 0; kk < KSTEP; kk += 8) {
            unsigned ahi[4][4], alo[4][4];
#pragma unroll
            for (int mt = 0; mt < 4; mt++) {
                int r = wm * 64 + mt * 16 + g;
#pragma unroll
                for (int q = 0; q < 4; q++) {
                    int rr = r + (q & 1) * 8;
                    int cc = kk + tg + (q >> 1) * 4;
                    float v = As[rr][cc];
                    unsigned hi = tf32_rna(v);
                    float lo = v - __uint_as_float(hi);
                    ahi[mt][q] = hi;
                    alo[mt][q] = tf32_rna(lo);
                }
            }
            unsigned bhi[4][2], blo[4][2];
#pragma unroll
            for (int nt = 0; nt < 4; nt++) {
                int n = wn * 32 + nt * 8 + g;
#pragma unroll
                for (int q = 0; q < 2; q++) {
                    float v = Bs[n][kk + tg + q * 4];
                    unsigned hi = tf32_rna(v);
                    float lo = v - __uint_as_float(hi);
                    bhi[nt][q] = hi;
                    blo[nt][q] = tf32_rna(lo);
                }
            }
#pragma unroll
            for (int mt = 0; mt < 4; mt++)
#pragma unroll
                for (int nt = 0; nt < 4; nt++) {
                    mma_tf32(acc[mt][nt], ahi[mt], bhi[nt]);
                    mma_tf32(acc[mt][nt], ahi[mt], blo[nt]);
                    mma_tf32(acc[mt][nt], alo[mt], bhi[nt]);
                }
        }
        __syncthreads();
    }

#pragma unroll
    for (int mt = 0; mt < 4; mt++) {
        int row = bm + wm * 64 + mt * 16 + g;
#pragma unroll
        for (int nt = 0; nt < 4; nt++) {
            int col = bn + wn * 32 + nt * 8 + tg * 2;
            if (col < N) {
                float* a = acc[mt][nt];
                size_t i0 = (size_t)row * N + col;
                size_t i1 = (size_t)(row + 8) * N + col;
                if (addRes) {
                    a[0] += resid[i0]; a[1] += resid[i0 + 1];
                    a[2] += resid[i1]; a[3] += resid[i1 + 1];
                }
                C[i0] = a[0]; C[i0 + 1] = a[1];
                C[i1] = a[2]; C[i1 + 1] = a[3];
            }
        }
    }
}

// ---------------- K3: depthwise causal conv (width 4) + bias + silu ----------
__global__ void conv_silu_kernel(const float* __restrict__ conv_w,
                                 const float* __restrict__ conv_b) {
    int idx = blockIdx.x * blockDim.x + threadIdx.x;  // ROWS*CONVD
    int c = idx % CONVD;
    int row = idx / CONVD;
    int l = row & (L_ - 1);
    const float* w = conv_w + c * 4;
    float acc = conv_b[c];
#pragma unroll
    for (int j = 0; j < 4; j++) {
        int ls = l - 3 + j;
        if (ls >= 0)
            acc += w[j] * g_zx[(size_t)(row - 3 + j) * DPROJ + DI + c];
    }
    float s = acc / (1.f + __expf(-acc));
    g_xbc[(size_t)row * CONVD + c] = s;
}

// ---------------- K4: dt = softplus(dt_raw + dt_bias) ----------
__global__ void dt_kernel(const float* __restrict__ dt_bias) {
    int idx = blockIdx.x * blockDim.x + threadIdx.x;  // ROWS*NH
    int h = idx & (NH - 1);
    int row = idx >> 5;
    float v = g_zx[(size_t)row * DPROJ + (DI + CONVD) + h] + dt_bias[h];
    float sp = (v > 20.f) ? v : log1pf(__expf(v));
    g_dt[row * NH + h] = sp;
}

// ---------------- K5: per-chunk cumsum of a = dt * A ----------
__global__ void acs_kernel(const float* __restrict__ A_log) {
    int bid = blockIdx.x;  // (b*NH + h)*NCH + c
    int b = bid >> 8, h = (bid >> 3) & 31, c = bid & 7;
    int l = threadIdx.x;
    int row = b * L_ + c * CH + l;
    float A = -__expf(A_log[h]);
    __shared__ float s[CH];
    s[l] = g_dt[row * NH + h] * A;
    __syncthreads();
#pragma unroll
    for (int off = 1; off < CH; off <<= 1) {
        float v = (l >= off) ? s[l - off] : 0.f;
        __syncthreads();
        s[l] += v;
        __syncthreads();
    }
    g_acs[bid * CH + l] = s[l];
}

// ---------------- K6: per-chunk states[p,n] = sum_l decay*xd[l,p]*B[l,n] -----
__global__ __launch_bounds__(256) void states_kernel() {
    int bid = blockIdx.x;  // (b*NCH + c)*NH + h
    int b = bid >> 8, c = (bid >> 5) & 7, h = bid & 31;
    int tid = threadIdx.x;
    int tx = tid & 15, ty = tid >> 4;
    __shared__ float xdw[16][64];
    __shared__ float bs[16][128];
    __shared__ float coef[16];
    int base = ((b * NH + h) * NCH + c) * CH;
    float acs_last = g_acs[base + CH - 1];
    int rowbase = b * L_ + c * CH;

    float acc[4][8];
#pragma unroll
    for (int i = 0; i < 4; i++)
#pragma unroll
        for (int j = 0; j < 8; j++) acc[i][j] = 0.f;

    for (int l0 = 0; l0 < CH; l0 += 16) {
        __syncthreads();
        if (tid < 16) {
            int row = rowbase + l0 + tid;
            coef[tid] = g_dt[row * NH + h] * __expf(acs_last - g_acs[base + l0 + tid]);
        }
        __syncthreads();
#pragma unroll
        for (int e = tid; e < 16 * 64; e += 256) {
            int ll = e >> 6, p = e & 63;
            int row = rowbase + l0 + ll;
            xdw[ll][p] = g_xbc[(size_t)row * CONVD + h * HD + p] * coef[ll];
        }
#pragma unroll
        for (int e = tid; e < 16 * 128; e += 256) {
            int ll = e >> 7, n = e & 127;
            int row = rowbase + l0 + ll;
            bs[ll][n] = g_xbc[(size_t)row * CONVD + DI + n];
        }
        __syncthreads();
#pragma unroll
        for (int ll = 0; ll < 16; ll++) {
            float4 a4 = *(const float4*)&xdw[ll][ty * 4];
            float4 b0 = *(const float4*)&bs[ll][tx * 8];
            float4 b1 = *(const float4*)&bs[ll][tx * 8 + 4];
            float a[4] = {a4.x, a4.y, a4.z, a4.w};
            float bb[8] = {b0.x, b0.y, b0.z, b0.w, b1.x, b1.y, b1.z, b1.w};
#pragma unroll
            for (int i = 0; i < 4; i++)
#pragma unroll
                for (int j = 0; j < 8; j++) acc[i][j] += a[i] * bb[j];
        }
    }
    size_t out = (size_t)bid * HD * DS;
#pragma unroll
    for (int i = 0; i < 4; i++)
#pragma unroll
        for (int j = 0; j < 8; j++)
            g_states[out + (size_t)(ty * 4 + i) * DS + tx * 8 + j] = acc[i][j];
}

// ---------------- K7: chunk recurrence (serial over 8 chunks) ----------
__global__ void recur_kernel() {
    int idx = blockIdx.x * blockDim.x + threadIdx.x;  // B_*NH*HD*DS
    int n = idx & 127;
    int p = (idx >> 7) & 63;
    int h = (idx >> 13) & 31;
    int b = idx >> 18;
    float run = 0.f;
#pragma unroll
    for (int c = 0; c < NCH; c++) {
        size_t sidx = ((size_t)((b * NCH + c) * NH + h) * HD + p) * DS + n;
        g_init[sidx] = run;
        float cs = g_acs[((b * NH + h) * NCH + c) * CH + CH - 1];
        run = run * __expf(cs) + g_states[sidx];
    }
}

// ---------------- K8: CB[l,s] = Cm[l]·Bm[s] per (b,c) ----------
__global__ __launch_bounds__(256) void cb_kernel() {
    int z = blockIdx.z;  // b*NCH + c
    int b = z >> 3, c = z & 7;
    int l0 = blockIdx.y * 64, s0 = blockIdx.x * 64;
    int tid = threadIdx.x;
    int tx = tid & 15, ty = tid >> 4;
    __shared__ float ct[16][64];
    __shared__ float bt[16][64];
    int rowbase = b * L_ + c * CH;
    float acc[4][4];
#pragma unroll
    for (int i = 0; i < 4; i++)
#pragma unroll
        for (int j = 0; j < 4; j++) acc[i][j] = 0.f;

    for (int k0 = 0; k0 < DS; k0 += 16) {
        __syncthreads();
#pragma unroll
        for (int e = tid; e < 1024; e += 256) {
            int kk = e & 15, i = e >> 4;
            ct[kk][i] = g_xbc[(size_t)(rowbase + l0 + i) * CONVD + DI + DS + k0 + kk];
            bt[kk][i] = g_xbc[(size_t)(rowbase + s0 + i) * CONVD + DI + k0 + kk];
        }
        __syncthreads();
#pragma unroll
        for (int kk = 0; kk < 16; kk++) {
            float4 a4 = *(const float4*)&ct[kk][ty * 4];
            float4 b4 = *(const float4*)&bt[kk][tx * 4];
            float a[4] = {a4.x, a4.y, a4.z, a4.w};
            float bb[4] = {b4.x, b4.y, b4.z, b4.w};
#pragma unroll
            for (int i = 0; i < 4; i++)
#pragma unroll
                for (int j = 0; j < 4; j++) acc[i][j] += a[i] * bb[j];
        }
    }
#pragma unroll
    for (int i = 0; i < 4; i++)
#pragma unroll
        for (int j = 0; j < 4; j++)
            g_cb[((size_t)z * CH + l0 + ty * 4 + i) * CH + s0 + tx * 4 + j] = acc[i][j];
}

// ---------------- K9: Y = Y_off + Y_diag + D*xh per (b,c,h) ----------
__global__ __launch_bounds__(256) void y_kernel(const float* __restrict__ Dvec) {
    int bid = blockIdx.x;  // (b*NCH + c)*NH + h
    int b = bid >> 8, c = (bid >> 5) & 7, h = bid & 31;
    int tid = threadIdx.x;
    int tx = tid & 7, ty = tid >> 3;  // tx: 8 p-groups, ty: 32 l-groups
    __shared__ float acs_s[CH];
    __shared__ float mt[CH][17];
    __shared__ float xt[16][68];
    int base = ((b * NH + h) * NCH + c) * CH;
    acs_s[tid] = g_acs[base + tid];
    int rowbase = b * L_ + c * CH;
    float Dh = Dvec[h];
    size_t initbase = (size_t)bid * HD * DS;

    float acc[8][8];
#pragma unroll
    for (int i = 0; i < 8; i++)
#pragma unroll
        for (int j = 0; j < 8; j++) acc[i][j] = 0.f;

    // Phase 1: Y_off = Cm @ init_state^T  (scaled by exp(acs[l]) afterwards)
    for (int n0 = 0; n0 < DS; n0 += 16) {
        __syncthreads();
        {
            int l = tid;
            const float* cm = &g_xbc[(size_t)(rowbase + l) * CONVD + DI + DS + n0];
#pragma unroll
            for (int nn = 0; nn < 16; nn++) mt[l][nn] = cm[nn];
        }
#pragma unroll
        for (int e = tid; e < 1024; e += 256) {
            int p = e >> 4, nn = e & 15;
            xt[nn][p] = g_init[initbase + (size_t)p * DS + n0 + nn];
        }
        __syncthreads();
#pragma unroll
        for (int nn = 0; nn < 16; nn++) {
            float4 x0 = *(const float4*)&xt[nn][tx * 8];
            float4 x1 = *(const float4*)&xt[nn][tx * 8 + 4];
            float xv[8] = {x0.x, x0.y, x0.z, x0.w, x1.x, x1.y, x1.z, x1.w};
            float mv[8];
#pragma unroll
            for (int i = 0; i < 8; i++) mv[i] = mt[ty * 8 + i][nn];
#pragma unroll
            for (int i = 0; i < 8; i++)
#pragma unroll
                for (int j = 0; j < 8; j++) acc[i][j] += mv[i] * xv[j];
        }
    }
#pragma unroll
    for (int i = 0; i < 8; i++) {
        float el = __expf(acs_s[ty * 8 + i]);
#pragma unroll
        for (int j = 0; j < 8; j++) acc[i][j] *= el;
    }

    // Phase 2: Y_diag = (CB ∘ L) @ xd
    for (int s0 = 0; s0 < CH; s0 += 16) {
        __syncthreads();
        {
            int l = tid;
            float al = acs_s[l];
            const float* cbr = &g_cb[((size_t)(b * NCH + c) * CH + l) * CH + s0];
#pragma unroll
            for (int ss = 0; ss < 16; ss++) {
                int s = s0 + ss;
                mt[l][ss] = (s <= l) ? cbr[ss] * __expf(al - acs_s[s]) : 0.f;
            }
        }
#pragma unroll
        for (int e = tid; e < 1024; e += 256) {
            int ss = e >> 6, p = e & 63;
            int row = rowbase + s0 + ss;
            xt[ss][p] = g_xbc[(size_t)row * CONVD + h * HD + p] * g_dt[row * NH + h];
        }
        __syncthreads();
        if (s0 <= ty * 8 + 7) {
#pragma unroll
            for (int ss = 0; ss < 16; ss++) {
                float4 x0 = *(const float4*)&xt[ss][tx * 8];
                float4 x1 = *(const float4*)&xt[ss][tx * 8 + 4];
                float xv[8] = {x0.x, x0.y, x0.z, x0.w, x1.x, x1.y, x1.z, x1.w};
                float mv[8];
#pragma unroll
                for (int i = 0; i < 8; i++) mv[i] = mt[ty * 8 + i][ss];
#pragma unroll
                for (int i = 0; i < 8; i++)
#pragma unroll
                    for (int j = 0; j < 8; j++) acc[i][j] += mv[i] * xv[j];
            }
        }
    }

    // epilogue: + D*xh, write y
#pragma unroll
    for (int i = 0; i < 8; i++) {
        int row = rowbase + ty * 8 + i;
#pragma unroll
        for (int j = 0; j < 8; j++) {
            int p = tx * 8 + j;
            float xh = g_xbc[(size_t)row * CONVD + h * HD + p];
            g_y[(size_t)row * DI + h * HD + p] = acc[i][j] + Dh * xh;
        }
    }
}

// ---------------- K10: gated rmsnorm: y = rmsnorm(y * silu(z)) * gnorm_w ------
__global__ void gated_norm_kernel(const float* __restrict__ gw) {
    int row = blockIdx.x, tid = threadIdx.x;
    __shared__ float buf[DI];
    float local = 0.f;
#pragma unroll
    for (int d = tid; d < DI; d += 256) {
        float z = g_zx[(size_t)row * DPROJ + d];
        float y = g_y[(size_t)row * DI + d];
        float v = y * (z / (1.f + __expf(-z)));
        buf[d] = v;
        local += v * v;
    }
    float tot = blockReduceSum256(local);
    float r = rsqrtf(tot / (float)DI + 1e-5f);
#pragma unroll
    for (int d = tid; d < DI; d += 256)
        g_y[(size_t)row * DI + d] = buf[d] * r * gw[d];
}

// ---------------- launch ----------------
extern "C" void kernel_launch(void* const* d_in, const int* in_sizes, int n_in,
                              void* d_out, int out_size) {
    const float* x         = (const float*)d_in[0];
    const float* norm_w    = (const float*)d_in[1];
    const float* in_proj_w = (const float*)d_in[2];
    const float* conv_w    = (const float*)d_in[3];
    const float* conv_b    = (const float*)d_in[4];
    const float* dt_bias   = (const float*)d_in[5];
    const float* A_log     = (const float*)d_in[6];
    const float* Dv        = (const float*)d_in[7];
    const float* gnorm_w   = (const float*)d_in[8];
    const float* out_proj_w= (const float*)d_in[9];
    float* out = (float*)d_out;

    float *pu, *pzx, *py;
    cudaGetSymbolAddress((void**)&pu, g_u);
    cudaGetSymbolAddress((void**)&pzx, g_zx);
    cudaGetSymbolAddress((void**)&py, g_y);

    rmsnorm_x_kernel<<<ROWS, 256>>>(x, norm_w);
    mma_nt<<<dim3((DPROJ + 127) / 128, ROWS / 128), 256>>>(
        pu, in_proj_w, pzx, nullptr, ROWS, DPROJ, DM, 0);
    conv_silu_kernel<<<(ROWS * CONVD) / 256, 256>>>(conv_w, conv_b);
    dt_kernel<<<(ROWS * NH) / 256, 256>>>(dt_bias);
    acs_kernel<<<B_ * NH * NCH, 256>>>(A_log);
    states_kernel<<<B_ * NCH * NH, 256>>>();
    recur_kernel<<<(B_ * NH * HD * DS) / 256, 256>>>();
    cb_kernel<<<dim3(4, 4, B_ * NCH), 256>>>();
    y_kernel<<<B_ * NCH * NH, 256>>>(Dv);
    gated_norm_kernel<<<ROWS, 256>>>(gnorm_w);
    mma_nt<<<dim3(DM / 128, ROWS / 128), 256>>>(
        py, out_proj_w, out, x, ROWS, DM, DI, 1);
}

// round 4
// speedup vs baseline: 1.6367x; 1.2247x over previous
#include <cuda_runtime.h>
#include <cuda_bf16.h>
#include <math.h>
#include <stdint.h>

// ---------------- problem constants ----------------
#define B_    2
#define L_    2048
#define DM    1024          // d_model
#define DI    2048          // d_inner
#define NH    32            // nheads
#define HD    64            // headdim
#define DS    128           // d_state
#define CONVD 2304          // conv dim = DI + 2*DS
#define DPROJ 4384          // 2*DI + 2*DS + NH
#define NCH   8             // chunks per batch
#define CH    256           // chunk length
#define ROWS  4096          // B_*L_

// ---------------- scratch (device globals; no allocation allowed) ----------------
__device__ float g_u[ROWS * DM];                    // rmsnorm(x)
__device__ float g_zx[(size_t)ROWS * DPROJ];        // in_proj output
__device__ float g_xbc[(size_t)ROWS * CONVD];       // conv+silu output
__device__ float g_dt[ROWS * NH];                   // softplus(dt)
__device__ float g_acs[B_ * NH * NCH * CH];         // cumsum(dt*A) per chunk
__device__ float g_states[(size_t)B_ * NCH * NH * HD * DS];
__device__ float g_init[(size_t)B_ * NCH * NH * HD * DS];
__device__ float g_cb[(size_t)B_ * NCH * CH * CH];  // Cm @ Bm^T per chunk
__device__ float g_y[(size_t)ROWS * DI];            // y (pre/post gated-norm)

// ---------------- helpers ----------------
__device__ __forceinline__ float blockReduceSum256(float v) {
    __shared__ float ws[8];
    __shared__ float tot;
    int lane = threadIdx.x & 31, wid = threadIdx.x >> 5;
#pragma unroll
    for (int o = 16; o; o >>= 1) v += __shfl_xor_sync(0xffffffffu, v, o);
    if (lane == 0) ws[wid] = v;
    __syncthreads();
    if (threadIdx.x == 0) {
        float s = 0.f;
#pragma unroll
        for (int i = 0; i < 8; i++) s += ws[i];
        tot = s;
    }
    __syncthreads();
    return tot;
}

__device__ __forceinline__ uint32_t pack_bf16(float a, float b) {
    __nv_bfloat162 h = __floats2bfloat162_rn(a, b);
    return *(uint32_t*)&h;
}

// m16n8k16 row.col bf16 MMA, fp32 accumulate
__device__ __forceinline__ void mma_bf16(float* d, const uint32_t* a, const uint32_t* b) {
    asm volatile(
        "mma.sync.aligned.m16n8k16.row.col.f32.bf16.bf16.f32 "
        "{%0,%1,%2,%3}, {%4,%5,%6,%7}, {%8,%9}, {%0,%1,%2,%3};"
        : "+f"(d[0]), "+f"(d[1]), "+f"(d[2]), "+f"(d[3])
        : "r"(a[0]), "r"(a[1]), "r"(a[2]), "r"(a[3]), "r"(b[0]), "r"(b[1]));
}

// ---------------- K1: rmsnorm(x) -> g_u ----------------
__global__ void rmsnorm_x_kernel(const float* __restrict__ x,
                                 const float* __restrict__ w) {
    int row = blockIdx.x, tid = threadIdx.x;
    const float* xr = x + (size_t)row * DM;
    float vals[4];
    float local = 0.f;
#pragma unroll
    for (int i = 0; i < 4; i++) {
        float v = xr[tid + i * 256];
        vals[i] = v;
        local += v * v;
    }
    float tot = blockReduceSum256(local);
    float r = rsqrtf(tot / (float)DM + 1e-5f);
#pragma unroll
    for (int i = 0; i < 4; i++) {
        int d = tid + i * 256;
        g_u[(size_t)row * DM + d] = vals[i] * r * w[d];
    }
}

// ------- tensor-core NT GEMM (3-term bf16 split): C = A[M,K]*B[N,K]^T (+res) --
// 128x128 block tile, K-slab 32, 256 threads = 8 warps (2 M x 4 N),
// warp tile 64x32 (4 m16 x 4 n8). fp32 -> bf16 hi/lo split ONCE at smem fill.
// smem tiles hold packed bf16x2 words: [128 rows][16 k-pairs] + pad 4.
#define KSL   32
#define SPADU 4
__global__ __launch_bounds__(256) void mma_nt_bf16(const float* __restrict__ A,
                                                   const float* __restrict__ B,
                                                   float* __restrict__ C,
                                                   const float* __restrict__ resid,
                                                   int M, int N, int K, int addRes) {
    __shared__ uint32_t Ah[128][16 + SPADU];
    __shared__ uint32_t Al[128][16 + SPADU];
    __shared__ uint32_t Bh[128][16 + SPADU];
    __shared__ uint32_t Bl[128][16 + SPADU];
    int tid = threadIdx.x;
    int warp = tid >> 5, lane = tid & 31;
    int wm = warp & 1, wn = warp >> 1;  // 2 x 4
    int bm = blockIdx.y * 128, bn = blockIdx.x * 128;
    int g = lane >> 2, tg = lane & 3;

    float acc[4][4][4];
#pragma unroll
    for (int mt = 0; mt < 4; mt++)
#pragma unroll
        for (int nt = 0; nt < 4; nt++)
#pragma unroll
            for (int q = 0; q < 4; q++) acc[mt][nt][q] = 0.f;

    int lrow = tid >> 1;             // 0..127
    int lhalf = (tid & 1) * 16;      // 0 / 16 floats
    const float* Ap = A + (size_t)(bm + lrow) * K + lhalf;
    const float* Bp = B + (size_t)(bn + lrow) * K + lhalf;
    bool bok = (bn + lrow) < N;
    const float4 z4 = make_float4(0.f, 0.f, 0.f, 0.f);

    float4 ra[4], rb[4];
#pragma unroll
    for (int c = 0; c < 4; c++) {
        ra[c] = *(const float4*)(Ap + c * 4);
        rb[c] = bok ? *(const float4*)(Bp + c * 4) : z4;
    }

    for (int k0 = 0; k0 < K; k0 += KSL) {
        // ---- split hi/lo and store packed ----
#pragma unroll
        for (int c = 0; c < 4; c++) {
            int col = (lhalf >> 1) + c * 2;  // u32 col
            float4 v = ra[c];
            float hx = __bfloat162float(__float2bfloat16(v.x));
            float hy = __bfloat162float(__float2bfloat16(v.y));
            float hz = __bfloat162float(__float2bfloat16(v.z));
            float hw = __bfloat162float(__float2bfloat16(v.w));
            Ah[lrow][col] = pack_bf16(v.x, v.y);
            Ah[lrow][col + 1] = pack_bf16(v.z, v.w);
            Al[lrow][col] = pack_bf16(v.x - hx, v.y - hy);
            Al[lrow][col + 1] = pack_bf16(v.z - hz, v.w - hw);
            v = rb[c];
            hx = __bfloat162float(__float2bfloat16(v.x));
            hy = __bfloat162float(__float2bfloat16(v.y));
            hz = __bfloat162float(__float2bfloat16(v.z));
            hw = __bfloat162float(__float2bfloat16(v.w));
            Bh[lrow][col] = pack_bf16(v.x, v.y);
            Bh[lrow][col + 1] = pack_bf16(v.z, v.w);
            Bl[lrow][col] = pack_bf16(v.x - hx, v.y - hy);
            Bl[lrow][col + 1] = pack_bf16(v.z - hz, v.w - hw);
        }
        __syncthreads();
        // ---- prefetch next slab ----
        int kn = k0 + KSL;
        if (kn < K) {
#pragma unroll
            for (int c = 0; c < 4; c++) {
                ra[c] = *(const float4*)(Ap + kn + c * 4);
                rb[c] = bok ? *(const float4*)(Bp + kn + c * 4) : z4;
            }
        }
        // ---- 2 k16 steps ----
#pragma unroll
        for (int kk = 0; kk < 16; kk += 8) {
            uint32_t ahi[4][4], alo[4][4];
#pragma unroll
            for (int mt = 0; mt < 4; mt++) {
                int r = wm * 64 + mt * 16 + g;
                ahi[mt][0] = Ah[r][kk + tg];
                ahi[mt][1] = Ah[r + 8][kk + tg];
                ahi[mt][2] = Ah[r][kk + tg + 4];
                ahi[mt][3] = Ah[r + 8][kk + tg + 4];
                alo[mt][0] = Al[r][kk + tg];
                alo[mt][1] = Al[r + 8][kk + tg];
                alo[mt][2] = Al[r][kk + tg + 4];
                alo[mt][3] = Al[r + 8][kk + tg + 4];
            }
            uint32_t bhi[4][2], blo[4][2];
#pragma unroll
            for (int nt = 0; nt < 4; nt++) {
                int n = wn * 32 + nt * 8 + g;
                bhi[nt][0] = Bh[n][kk + tg];
                bhi[nt][1] = Bh[n][kk + tg + 4];
                blo[nt][0] = Bl[n][kk + tg];
                blo[nt][1] = Bl[n][kk + tg + 4];
            }
#pragma unroll
            for (int mt = 0; mt < 4; mt++)
#pragma unroll
                for (int nt = 0; nt < 4; nt++) {
                    mma_bf16(acc[mt][nt], ahi[mt], bhi[nt]);
                    mma_bf16(acc[mt][nt], ahi[mt], blo[nt]);
                    mma_bf16(acc[mt][nt], alo[mt], bhi[nt]);
                }
        }
        __syncthreads();
    }

#pragma unroll
    for (int mt = 0; mt < 4; mt++) {
        int row = bm + wm * 64 + mt * 16 + g;
#pragma unroll
        for (int nt = 0; nt < 4; nt++) {
            int col = bn + wn * 32 + nt * 8 + tg * 2;
            if (col < N) {
                float* a = acc[mt][nt];
                size_t i0 = (size_t)row * N + col;
                size_t i1 = (size_t)(row + 8) * N + col;
                if (addRes) {
                    a[0] += resid[i0]; a[1] += resid[i0 + 1];
                    a[2] += resid[i1]; a[3] += resid[i1 + 1];
                }
                C[i0] = a[0]; C[i0 + 1] = a[1];
                C[i1] = a[2]; C[i1 + 1] = a[3];
            }
        }
    }
}

// ---------------- K3: depthwise causal conv (width 4) + bias + silu ----------
__global__ void conv_silu_kernel(const float* __restrict__ conv_w,
                                 const float* __restrict__ conv_b) {
    int idx = blockIdx.x * blockDim.x + threadIdx.x;  // ROWS*CONVD
    int c = idx % CONVD;
    int row = idx / CONVD;
    int l = row & (L_ - 1);
    const float* w = conv_w + c * 4;
    float acc = conv_b[c];
#pragma unroll
    for (int j = 0; j < 4; j++) {
        int ls = l - 3 + j;
        if (ls >= 0)
            acc += w[j] * g_zx[(size_t)(row - 3 + j) * DPROJ + DI + c];
    }
    float s = acc / (1.f + __expf(-acc));
    g_xbc[(size_t)row * CONVD + c] = s;
}

// ---------------- K4: dt = softplus(dt_raw + dt_bias) ----------
__global__ void dt_kernel(const float* __restrict__ dt_bias) {
    int idx = blockIdx.x * blockDim.x + threadIdx.x;  // ROWS*NH
    int h = idx & (NH - 1);
    int row = idx >> 5;
    float v = g_zx[(size_t)row * DPROJ + (DI + CONVD) + h] + dt_bias[h];
    float sp = (v > 20.f) ? v : log1pf(__expf(v));
    g_dt[row * NH + h] = sp;
}

// ---------------- K5: per-chunk cumsum of a = dt * A ----------
__global__ void acs_kernel(const float* __restrict__ A_log) {
    int bid = blockIdx.x;  // (b*NH + h)*NCH + c
    int b = bid >> 8, h = (bid >> 3) & 31, c = bid & 7;
    int l = threadIdx.x;
    int row = b * L_ + c * CH + l;
    float A = -__expf(A_log[h]);
    __shared__ float s[CH];
    s[l] = g_dt[row * NH + h] * A;
    __syncthreads();
#pragma unroll
    for (int off = 1; off < CH; off <<= 1) {
        float v = (l >= off) ? s[l - off] : 0.f;
        __syncthreads();
        s[l] += v;
        __syncthreads();
    }
    g_acs[bid * CH + l] = s[l];
}

// ---------------- K6: per-chunk states[p,n] = sum_l decay*xd[l,p]*B[l,n] -----
__global__ __launch_bounds__(256) void states_kernel() {
    int bid = blockIdx.x;  // (b*NCH + c)*NH + h
    int b = bid >> 8, c = (bid >> 5) & 7, h = bid & 31;
    int tid = threadIdx.x;
    int tx = tid & 15, ty = tid >> 4;
    __shared__ float xdw[16][64];
    __shared__ float bs[16][128];
    __shared__ float coef[16];
    int base = ((b * NH + h) * NCH + c) * CH;
    float acs_last = g_acs[base + CH - 1];
    int rowbase = b * L_ + c * CH;

    float acc[4][8];
#pragma unroll
    for (int i = 0; i < 4; i++)
#pragma unroll
        for (int j = 0; j < 8; j++) acc[i][j] = 0.f;

    for (int l0 = 0; l0 < CH; l0 += 16) {
        __syncthreads();
        if (tid < 16) {
            int row = rowbase + l0 + tid;
            coef[tid] = g_dt[row * NH + h] * __expf(acs_last - g_acs[base + l0 + tid]);
        }
        __syncthreads();
#pragma unroll
        for (int e = tid; e < 16 * 64; e += 256) {
            int ll = e >> 6, p = e & 63;
            int row = rowbase + l0 + ll;
            xdw[ll][p] = g_xbc[(size_t)row * CONVD + h * HD + p] * coef[ll];
        }
#pragma unroll
        for (int e = tid; e < 16 * 128; e += 256) {
            int ll = e >> 7, n = e & 127;
            int row = rowbase + l0 + ll;
            bs[ll][n] = g_xbc[(size_t)row * CONVD + DI + n];
        }
        __syncthreads();
#pragma unroll
        for (int ll = 0; ll < 16; ll++) {
            float4 a4 = *(const float4*)&xdw[ll][ty * 4];
            float4 b0 = *(const float4*)&bs[ll][tx * 8];
            float4 b1 = *(const float4*)&bs[ll][tx * 8 + 4];
            float a[4] = {a4.x, a4.y, a4.z, a4.w};
            float bb[8] = {b0.x, b0.y, b0.z, b0.w, b1.x, b1.y, b1.z, b1.w};
#pragma unroll
            for (int i = 0; i < 4; i++)
#pragma unroll
                for (int j = 0; j < 8; j++) acc[i][j] += a[i] * bb[j];
        }
    }
    size_t out = (size_t)bid * HD * DS;
#pragma unroll
    for (int i = 0; i < 4; i++)
#pragma unroll
        for (int j = 0; j < 8; j++)
            g_states[out + (size_t)(ty * 4 + i) * DS + tx * 8 + j] = acc[i][j];
}

// ---------------- K7: chunk recurrence (serial over 8 chunks) ----------
__global__ void recur_kernel() {
    int idx = blockIdx.x * blockDim.x + threadIdx.x;  // B_*NH*HD*DS
    int n = idx & 127;
    int p = (idx >> 7) & 63;
    int h = (idx >> 13) & 31;
    int b = idx >> 18;
    float run = 0.f;
#pragma unroll
    for (int c = 0; c < NCH; c++) {
        size_t sidx = ((size_t)((b * NCH + c) * NH + h) * HD + p) * DS + n;
        g_init[sidx] = run;
        float cs = g_acs[((b * NH + h) * NCH + c) * CH + CH - 1];
        run = run * __expf(cs) + g_states[sidx];
    }
}

// ---------------- K8: CB[l,s] = Cm[l]·Bm[s] per (b,c) ----------
__global__ __launch_bounds__(256) void cb_kernel() {
    int z = blockIdx.z;  // b*NCH + c
    int b = z >> 3, c = z & 7;
    int l0 = blockIdx.y * 64, s0 = blockIdx.x * 64;
    int tid = threadIdx.x;
    int tx = tid & 15, ty = tid >> 4;
    __shared__ float ct[16][64];
    __shared__ float bt[16][64];
    int rowbase = b * L_ + c * CH;
    float acc[4][4];
#pragma unroll
    for (int i = 0; i < 4; i++)
#pragma unroll
        for (int j = 0; j < 4; j++) acc[i][j] = 0.f;

    for (int k0 = 0; k0 < DS; k0 += 16) {
        __syncthreads();
#pragma unroll
        for (int e = tid; e < 1024; e += 256) {
            int kk = e & 15, i = e >> 4;
            ct[kk][i] = g_xbc[(size_t)(rowbase + l0 + i) * CONVD + DI + DS + k0 + kk];
            bt[kk][i] = g_xbc[(size_t)(rowbase + s0 + i) * CONVD + DI + k0 + kk];
        }
        __syncthreads();
#pragma unroll
        for (int kk = 0; kk < 16; kk++) {
            float4 a4 = *(const float4*)&ct[kk][ty * 4];
            float4 b4 = *(const float4*)&bt[kk][tx * 4];
            float a[4] = {a4.x, a4.y, a4.z, a4.w};
            float bb[4] = {b4.x, b4.y, b4.z, b4.w};
#pragma unroll
            for (int i = 0; i < 4; i++)
#pragma unroll
                for (int j = 0; j < 4; j++) acc[i][j] += a[i] * bb[j];
        }
    }
#pragma unroll
    for (int i = 0; i < 4; i++)
#pragma unroll
        for (int j = 0; j < 4; j++)
            g_cb[((size_t)z * CH + l0 + ty * 4 + i) * CH + s0 + tx * 4 + j] = acc[i][j];
}

// ---------------- K9: Y = Y_off + Y_diag + D*xh per (b,c,h) ----------
__global__ __launch_bounds__(256) void y_kernel(const float* __restrict__ Dvec) {
    int bid = blockIdx.x;  // (b*NCH + c)*NH + h
    int b = bid >> 8, c = (bid >> 5) & 7, h = bid & 31;
    int tid = threadIdx.x;
    int tx = tid & 7, ty = tid >> 3;  // tx: 8 p-groups, ty: 32 l-groups
    __shared__ float acs_s[CH];
    __shared__ float mt[CH][17];
    __shared__ float xt[16][68];
    int base = ((b * NH + h) * NCH + c) * CH;
    acs_s[tid] = g_acs[base + tid];
    int rowbase = b * L_ + c * CH;
    float Dh = Dvec[h];
    size_t initbase = (size_t)bid * HD * DS;

    float acc[8][8];
#pragma unroll
    for (int i = 0; i < 8; i++)
#pragma unroll
        for (int j = 0; j < 8; j++) acc[i][j] = 0.f;

    // Phase 1: Y_off = Cm @ init_state^T  (scaled by exp(acs[l]) afterwards)
    for (int n0 = 0; n0 < DS; n0 += 16) {
        __syncthreads();
        {
            int l = tid;
            const float* cm = &g_xbc[(size_t)(rowbase + l) * CONVD + DI + DS + n0];
#pragma unroll
            for (int nn = 0; nn < 16; nn++) mt[l][nn] = cm[nn];
        }
#pragma unroll
        for (int e = tid; e < 1024; e += 256) {
            int p = e >> 4, nn = e & 15;
            xt[nn][p] = g_init[initbase + (size_t)p * DS + n0 + nn];
        }
        __syncthreads();
#pragma unroll
        for (int nn = 0; nn < 16; nn++) {
            float4 x0 = *(const float4*)&xt[nn][tx * 8];
            float4 x1 = *(const float4*)&xt[nn][tx * 8 + 4];
            float xv[8] = {x0.x, x0.y, x0.z, x0.w, x1.x, x1.y, x1.z, x1.w};
            float mv[8];
#pragma unroll
            for (int i = 0; i < 8; i++) mv[i] = mt[ty * 8 + i][nn];
#pragma unroll
            for (int i = 0; i < 8; i++)
#pragma unroll
                for (int j = 0; j < 8; j++) acc[i][j] += mv[i] * xv[j];
        }
    }
#pragma unroll
    for (int i = 0; i < 8; i++) {
        float el = __expf(acs_s[ty * 8 + i]);
#pragma unroll
        for (int j = 0; j < 8; j++) acc[i][j] *= el;
    }

    // Phase 2: Y_diag = (CB ∘ L) @ xd
    for (int s0 = 0; s0 < CH; s0 += 16) {
        __syncthreads();
        {
            int l = tid;
            float al = acs_s[l];
            const float* cbr = &g_cb[((size_t)(b * NCH + c) * CH + l) * CH + s0];
#pragma unroll
            for (int ss = 0; ss < 16; ss++) {
                int s = s0 + ss;
                mt[l][ss] = (s <= l) ? cbr[ss] * __expf(al - acs_s[s]) : 0.f;
            }
        }
#pragma unroll
        for (int e = tid; e < 1024; e += 256) {
            int ss = e >> 6, p = e & 63;
            int row = rowbase + s0 + ss;
            xt[ss][p] = g_xbc[(size_t)row * CONVD + h * HD + p] * g_dt[row * NH + h];
        }
        __syncthreads();
        if (s0 <= ty * 8 + 7) {
#pragma unroll
            for (int ss = 0; ss < 16; ss++) {
                float4 x0 = *(const float4*)&xt[ss][tx * 8];
                float4 x1 = *(const float4*)&xt[ss][tx * 8 + 4];
                float xv[8] = {x0.x, x0.y, x0.z, x0.w, x1.x, x1.y, x1.z, x1.w};
                float mv[8];
#pragma unroll
                for (int i = 0; i < 8; i++) mv[i] = mt[ty * 8 + i][ss];
#pragma unroll
                for (int i = 0; i < 8; i++)
#pragma unroll
                    for (int j = 0; j < 8; j++) acc[i][j] += mv[i] * xv[j];
            }
        }
    }

    // epilogue: + D*xh, write y
#pragma unroll
    for (int i = 0; i < 8; i++) {
        int row = rowbase + ty * 8 + i;
#pragma unroll
        for (int j = 0; j < 8; j++) {
            int p = tx * 8 + j;
            float xh = g_xbc[(size_t)row * CONVD + h * HD + p];
            g_y[(size_t)row * DI + h * HD + p] = acc[i][j] + Dh * xh;
        }
    }
}

// ---------------- K10: gated rmsnorm: y = rmsnorm(y * silu(z)) * gnorm_w ------
__global__ void gated_norm_kernel(const float* __restrict__ gw) {
    int row = blockIdx.x, tid = threadIdx.x;
    __shared__ float buf[DI];
    float local = 0.f;
#pragma unroll
    for (int d = tid; d < DI; d += 256) {
        float z = g_zx[(size_t)row * DPROJ + d];
        float y = g_y[(size_t)row * DI + d];
        float v = y * (z / (1.f + __expf(-z)));
        buf[d] = v;
        local += v * v;
    }
    float tot = blockReduceSum256(local);
    float r = rsqrtf(tot / (float)DI + 1e-5f);
#pragma unroll
    for (int d = tid; d < DI; d += 256)
        g_y[(size_t)row * DI + d] = buf[d] * r * gw[d];
}

// ---------------- launch ----------------
extern "C" void kernel_launch(void* const* d_in, const int* in_sizes, int n_in,
                              void* d_out, int out_size) {
    const float* x         = (const float*)d_in[0];
    const float* norm_w    = (const float*)d_in[1];
    const float* in_proj_w = (const float*)d_in[2];
    const float* conv_w    = (const float*)d_in[3];
    const float* conv_b    = (const float*)d_in[4];
    const float* dt_bias   = (const float*)d_in[5];
    const float* A_log     = (const float*)d_in[6];
    const float* Dv        = (const float*)d_in[7];
    const float* gnorm_w   = (const float*)d_in[8];
    const float* out_proj_w= (const float*)d_in[9];
    float* out = (float*)d_out;

    float *pu, *pzx, *py;
    cudaGetSymbolAddress((void**)&pu, g_u);
    cudaGetSymbolAddress((void**)&pzx, g_zx);
    cudaGetSymbolAddress((void**)&py, g_y);

    rmsnorm_x_kernel<<<ROWS, 256>>>(x, norm_w);
    mma_nt_bf16<<<dim3((DPROJ + 127) / 128, ROWS / 128), 256>>>(
        pu, in_proj_w, pzx, nullptr, ROWS, DPROJ, DM, 0);
    conv_silu_kernel<<<(ROWS * CONVD) / 256, 256>>>(conv_w, conv_b);
    dt_kernel<<<(ROWS * NH) / 256, 256>>>(dt_bias);
    acs_kernel<<<B_ * NH * NCH, 256>>>(A_log);
    states_kernel<<<B_ * NCH * NH, 256>>>();
    recur_kernel<<<(B_ * NH * HD * DS) / 256, 256>>>();
    cb_kernel<<<dim3(4, 4, B_ * NCH), 256>>>();
    y_kernel<<<B_ * NCH * NH, 256>>>(Dv);
    gated_norm_kernel<<<ROWS, 256>>>(gnorm_w);
    mma_nt_bf16<<<dim3(DM / 128, ROWS / 128), 256>>>(
        py, out_proj_w, out, x, ROWS, DM, DI, 1);
}

// round 5
// speedup vs baseline: 1.8818x; 1.1498x over previous
#include <cuda_runtime.h>
#include <cuda_bf16.h>
#include <math.h>
#include <stdint.h>

// ---------------- problem constants ----------------
#define B_    2
#define L_    2048
#define DM    1024          // d_model
#define DI    2048          // d_inner
#define NH    32            // nheads
#define HD    64            // headdim
#define DS    128           // d_state
#define CONVD 2304          // conv dim = DI + 2*DS
#define DPROJ 4384          // 2*DI + 2*DS + NH
#define NCH   8             // chunks per batch
#define CH    256           // chunk length
#define ROWS  4096          // B_*L_

// ---------------- scratch (device globals; no allocation allowed) ----------------
__device__ float g_zx[(size_t)ROWS * DPROJ];        // in_proj output
__device__ float g_xbc[(size_t)ROWS * CONVD];       // conv+silu output
__device__ float g_dt[ROWS * NH];                   // softplus(dt)
__device__ float g_acs[B_ * NH * NCH * CH];         // cumsum(dt*A) per chunk
__device__ float g_states[(size_t)B_ * NCH * NH * HD * DS];
__device__ float g_init[(size_t)B_ * NCH * NH * HD * DS];
__device__ float g_cb[(size_t)B_ * NCH * CH * CH];  // Cm @ Bm^T per chunk
__device__ float g_y[(size_t)ROWS * DI];            // y (pre gated-norm)

// packed bf16x2 hi/lo operand arrays
__device__ uint32_t g_uh[ROWS * DM / 2];            // rmsnorm(x) hi
__device__ uint32_t g_ul[ROWS * DM / 2];            // rmsnorm(x) lo
__device__ uint32_t g_yh[(size_t)ROWS * DI / 2];    // gated-norm(y) hi
__device__ uint32_t g_yl[(size_t)ROWS * DI / 2];    // gated-norm(y) lo
__device__ uint32_t g_wih[(size_t)DPROJ * DM / 2];  // in_proj_w hi
__device__ uint32_t g_wil[(size_t)DPROJ * DM / 2];  // in_proj_w lo
__device__ uint32_t g_woh[(size_t)DM * DI / 2];     // out_proj_w hi
__device__ uint32_t g_wol[(size_t)DM * DI / 2];     // out_proj_w lo

// ---------------- helpers ----------------
__device__ __forceinline__ float blockReduceSum256(float v) {
    __shared__ float ws[8];
    __shared__ float tot;
    int lane = threadIdx.x & 31, wid = threadIdx.x >> 5;
#pragma unroll
    for (int o = 16; o; o >>= 1) v += __shfl_xor_sync(0xffffffffu, v, o);
    if (lane == 0) ws[wid] = v;
    __syncthreads();
    if (threadIdx.x == 0) {
        float s = 0.f;
#pragma unroll
        for (int i = 0; i < 8; i++) s += ws[i];
        tot = s;
    }
    __syncthreads();
    return tot;
}

__device__ __forceinline__ uint32_t pack_bf16(float a, float b) {
    __nv_bfloat162 h = __floats2bfloat162_rn(a, b);
    return *(uint32_t*)&h;
}

__device__ __forceinline__ float bf16r(float v) {
    return __bfloat162float(__float2bfloat16(v));
}

__device__ __forceinline__ uint32_t smem_u32(const void* p) {
    uint32_t a;
    asm("{ .reg .u64 t; cvta.to.shared.u64 t, %1; cvt.u32.u64 %0, t; }"
        : "=r"(a) : "l"(p));
    return a;
}

// m16n8k16 row.col bf16 MMA, fp32 accumulate
__device__ __forceinline__ void mma_bf16(float* d, const uint32_t* a, const uint32_t* b) {
    asm volatile(
        "mma.sync.aligned.m16n8k16.row.col.f32.bf16.bf16.f32 "
        "{%0,%1,%2,%3}, {%4,%5,%6,%7}, {%8,%9}, {%0,%1,%2,%3};"
        : "+f"(d[0]), "+f"(d[1]), "+f"(d[2]), "+f"(d[3])
        : "r"(a[0]), "r"(a[1]), "r"(a[2]), "r"(a[3]), "r"(b[0]), "r"(b[1]));
}

__device__ __forceinline__ void cp16(uint32_t dst, const void* src, bool ok) {
    if (ok)
        asm volatile("cp.async.cg.shared.global [%0], [%1], 16;"
                     :: "r"(dst), "l"(src) : "memory");
    else
        asm volatile("cp.async.cg.shared.global [%0], [%1], 16, 0;"
                     :: "r"(dst), "l"(src) : "memory");
}

// ---------------- K0: split fp32 pairs -> bf16 hi/lo packed ----------
__global__ void cvt_pairs_kernel(const float* __restrict__ W,
                                 uint32_t* __restrict__ Wh,
                                 uint32_t* __restrict__ Wl, int npairs) {
    int i = blockIdx.x * blockDim.x + threadIdx.x;
    if (i < npairs) {
        float2 v = ((const float2*)W)[i];
        Wh[i] = pack_bf16(v.x, v.y);
        Wl[i] = pack_bf16(v.x - bf16r(v.x), v.y - bf16r(v.y));
    }
}

// ---------------- K1: rmsnorm(x) -> bf16 hi/lo ----------------
__global__ void rmsnorm_x_kernel(const float* __restrict__ x,
                                 const float* __restrict__ w) {
    int row = blockIdx.x, tid = threadIdx.x;
    const float4 v = ((const float4*)(x + (size_t)row * DM))[tid];
    const float4 wv = ((const float4*)w)[tid];
    float local = v.x * v.x + v.y * v.y + v.z * v.z + v.w * v.w;
    float tot = blockReduceSum256(local);
    float r = rsqrtf(tot / (float)DM + 1e-5f);
    float u0 = v.x * r * wv.x, u1 = v.y * r * wv.y;
    float u2 = v.z * r * wv.z, u3 = v.w * r * wv.w;
    int o = row * (DM / 2) + tid * 2;
    g_uh[o] = pack_bf16(u0, u1);
    g_uh[o + 1] = pack_bf16(u2, u3);
    g_ul[o] = pack_bf16(u0 - bf16r(u0), u1 - bf16r(u1));
    g_ul[o + 1] = pack_bf16(u2 - bf16r(u2), u3 - bf16r(u3));
}

// ------- tensor-core NT GEMM, preconverted bf16 hi/lo, cp.async 2-stage -------
// C[M,N] = A[M,K]*B[N,K]^T (+resid). 128x128 tile, K-slab 32, 256 thr, 8 warps.
// smem per stage: 4 arrays x 128 rows x 20 u32 (16 data + 4 pad).
#define UPS   (4 * 128 * 20)          // u32 per stage
#define GSMEM (2 * UPS * 4)           // bytes
__global__ __launch_bounds__(256) void mma_nt_pre(const uint32_t* __restrict__ Ahg,
                                                  const uint32_t* __restrict__ Alg,
                                                  const uint32_t* __restrict__ Bhg,
                                                  const uint32_t* __restrict__ Blg,
                                                  float* __restrict__ C,
                                                  const float* __restrict__ resid,
                                                  int M, int N, int K, int addRes) {
    extern __shared__ __align__(16) uint32_t S[];
    uint32_t sbase = smem_u32(S);
    int tid = threadIdx.x;
    int warp = tid >> 5, lane = tid & 31;
    int wm = warp & 1, wn = warp >> 1;  // 2 x 4
    int bm = blockIdx.y * 128, bn = blockIdx.x * 128;
    int g = lane >> 2, tg = lane & 3;
    int K2 = K >> 1;

    int lrow = tid >> 1, lhalf = tid & 1;     // row 0..127, 8-u32 half
    const uint32_t* pA[2] = {Ahg + (size_t)(bm + lrow) * K2 + lhalf * 8,
                             Alg + (size_t)(bm + lrow) * K2 + lhalf * 8};
    bool okB = (bn + lrow) < N;
    int brow = okB ? (bn + lrow) : 0;
    const uint32_t* pB[2] = {Bhg + (size_t)brow * K2 + lhalf * 8,
                             Blg + (size_t)brow * K2 + lhalf * 8};
    uint32_t dto = (uint32_t)(lrow * 20 + lhalf * 8) * 4;

    float acc[4][4][4];
#pragma unroll
    for (int mt = 0; mt < 4; mt++)
#pragma unroll
        for (int nt = 0; nt < 4; nt++)
#pragma unroll
            for (int q = 0; q < 4; q++) acc[mt][nt][q] = 0.f;

    int nslab = K >> 5;

    // issue loads for slab `sl` into stage `st`
    auto issue = [&](int st, int sl) {
        int ko = sl * 16;  // u32 offset within row
        uint32_t db = sbase + (uint32_t)(st * UPS) * 4 + dto;
#pragma unroll
        for (int t = 0; t < 2; t++) {
            cp16(db + (uint32_t)(t * 2560 * 4), pA[t] + ko, true);
            cp16(db + (uint32_t)(t * 2560 * 4) + 16, pA[t] + ko + 4, true);
            cp16(db + (uint32_t)((2 + t) * 2560 * 4), pB[t] + ko, okB);
            cp16(db + (uint32_t)((2 + t) * 2560 * 4) + 16, pB[t] + ko + 4, okB);
        }
        asm volatile("cp.async.commit_group;" ::: "memory");
    };

    issue(0, 0);
    int st = 0;
    for (int i = 0; i < nslab; i++) {
        if (i + 1 < nslab) {
            issue(st ^ 1, i + 1);
            asm volatile("cp.async.wait_group 1;" ::: "memory");
        } else {
            asm volatile("cp.async.wait_group 0;" ::: "memory");
        }
        __syncthreads();
        const uint32_t* Ah_ = S + st * UPS;
        const uint32_t* Al_ = Ah_ + 2560;
        const uint32_t* Bh_ = Al_ + 2560;
        const uint32_t* Bl_ = Bh_ + 2560;
#pragma unroll
        for (int kk = 0; kk < 16; kk += 8) {
            uint32_t ahi[4][4], alo[4][4];
#pragma unroll
            for (int mt = 0; mt < 4; mt++) {
                int r = wm * 64 + mt * 16 + g;
                ahi[mt][0] = Ah_[r * 20 + kk + tg];
                ahi[mt][1] = Ah_[(r + 8) * 20 + kk + tg];
                ahi[mt][2] = Ah_[r * 20 + kk + tg + 4];
                ahi[mt][3] = Ah_[(r + 8) * 20 + kk + tg + 4];
                alo[mt][0] = Al_[r * 20 + kk + tg];
                alo[mt][1] = Al_[(r + 8) * 20 + kk + tg];
                alo[mt][2] = Al_[r * 20 + kk + tg + 4];
                alo[mt][3] = Al_[(r + 8) * 20 + kk + tg + 4];
            }
            uint32_t bhi[4][2], blo[4][2];
#pragma unroll
            for (int nt = 0; nt < 4; nt++) {
                int n = wn * 32 + nt * 8 + g;
                bhi[nt][0] = Bh_[n * 20 + kk + tg];
                bhi[nt][1] = Bh_[n * 20 + kk + tg + 4];
                blo[nt][0] = Bl_[n * 20 + kk + tg];
                blo[nt][1] = Bl_[n * 20 + kk + tg + 4];
            }
#pragma unroll
            for (int mt = 0; mt < 4; mt++)
#pragma unroll
                for (int nt = 0; nt < 4; nt++) {
                    mma_bf16(acc[mt][nt], ahi[mt], bhi[nt]);
                    mma_bf16(acc[mt][nt], ahi[mt], blo[nt]);
                    mma_bf16(acc[mt][nt], alo[mt], bhi[nt]);
                }
        }
        __syncthreads();
        st ^= 1;
    }

#pragma unroll
    for (int mt = 0; mt < 4; mt++) {
        int row = bm + wm * 64 + mt * 16 + g;
#pragma unroll
        for (int nt = 0; nt < 4; nt++) {
            int col = bn + wn * 32 + nt * 8 + tg * 2;
            if (col < N) {
                float* a = acc[mt][nt];
                size_t i0 = (size_t)row * N + col;
                size_t i1 = (size_t)(row + 8) * N + col;
                if (addRes) {
                    a[0] += resid[i0]; a[1] += resid[i0 + 1];
                    a[2] += resid[i1]; a[3] += resid[i1 + 1];
                }
                C[i0] = a[0]; C[i0 + 1] = a[1];
                C[i1] = a[2]; C[i1 + 1] = a[3];
            }
        }
    }
}

// ---------------- K3: depthwise causal conv (width 4) + bias + silu ----------
__global__ void conv_silu_kernel(const float* __restrict__ conv_w,
                                 const float* __restrict__ conv_b) {
    int idx = blockIdx.x * blockDim.x + threadIdx.x;  // ROWS*CONVD
    int c = idx % CONVD;
    int row = idx / CONVD;
    int l = row & (L_ - 1);
    const float* w = conv_w + c * 4;
    float acc = conv_b[c];
#pragma unroll
    for (int j = 0; j < 4; j++) {
        int ls = l - 3 + j;
        if (ls >= 0)
            acc += w[j] * g_zx[(size_t)(row - 3 + j) * DPROJ + DI + c];
    }
    float s = acc / (1.f + __expf(-acc));
    g_xbc[(size_t)row * CONVD + c] = s;
}

// ---------------- K4: dt = softplus(dt_raw + dt_bias) ----------
__global__ void dt_kernel(const float* __restrict__ dt_bias) {
    int idx = blockIdx.x * blockDim.x + threadIdx.x;  // ROWS*NH
    int h = idx & (NH - 1);
    int row = idx >> 5;
    float v = g_zx[(size_t)row * DPROJ + (DI + CONVD) + h] + dt_bias[h];
    float sp = (v > 20.f) ? v : log1pf(__expf(v));
    g_dt[row * NH + h] = sp;
}

// ---------------- K5: per-chunk cumsum of a = dt * A ----------
__global__ void acs_kernel(const float* __restrict__ A_log) {
    int bid = blockIdx.x;  // (b*NH + h)*NCH + c
    int b = bid >> 8, h = (bid >> 3) & 31, c = bid & 7;
    int l = threadIdx.x;
    int row = b * L_ + c * CH + l;
    float A = -__expf(A_log[h]);
    __shared__ float s[CH];
    s[l] = g_dt[row * NH + h] * A;
    __syncthreads();
#pragma unroll
    for (int off = 1; off < CH; off <<= 1) {
        float v = (l >= off) ? s[l - off] : 0.f;
        __syncthreads();
        s[l] += v;
        __syncthreads();
    }
    g_acs[bid * CH + l] = s[l];
}

// ---------------- K6: per-chunk states[p,n] = sum_l decay*xd[l,p]*B[l,n] -----
__global__ __launch_bounds__(256) void states_kernel() {
    int bid = blockIdx.x;  // (b*NCH + c)*NH + h
    int b = bid >> 8, c = (bid >> 5) & 7, h = bid & 31;
    int tid = threadIdx.x;
    int tx = tid & 15, ty = tid >> 4;
    __shared__ float xdw[16][64];
    __shared__ float bs[16][128];
    __shared__ float coef[16];
    int base = ((b * NH + h) * NCH + c) * CH;
    float acs_last = g_acs[base + CH - 1];
    int rowbase = b * L_ + c * CH;

    float acc[4][8];
#pragma unroll
    for (int i = 0; i < 4; i++)
#pragma unroll
        for (int j = 0; j < 8; j++) acc[i][j] = 0.f;

    for (int l0 = 0; l0 < CH; l0 += 16) {
        __syncthreads();
        if (tid < 16) {
            int row = rowbase + l0 + tid;
            coef[tid] = g_dt[row * NH + h] * __expf(acs_last - g_acs[base + l0 + tid]);
        }
        __syncthreads();
#pragma unroll
        for (int e = tid; e < 16 * 64; e += 256) {
            int ll = e >> 6, p = e & 63;
            int row = rowbase + l0 + ll;
            xdw[ll][p] = g_xbc[(size_t)row * CONVD + h * HD + p] * coef[ll];
        }
#pragma unroll
        for (int e = tid; e < 16 * 128; e += 256) {
            int ll = e >> 7, n = e & 127;
            int row = rowbase + l0 + ll;
            bs[ll][n] = g_xbc[(size_t)row * CONVD + DI + n];
        }
        __syncthreads();
#pragma unroll
        for (int ll = 0; ll < 16; ll++) {
            float4 a4 = *(const float4*)&xdw[ll][ty * 4];
            float4 b0 = *(const float4*)&bs[ll][tx * 8];
            float4 b1 = *(const float4*)&bs[ll][tx * 8 + 4];
            float a[4] = {a4.x, a4.y, a4.z, a4.w};
            float bb[8] = {b0.x, b0.y, b0.z, b0.w, b1.x, b1.y, b1.z, b1.w};
#pragma unroll
            for (int i = 0; i < 4; i++)
#pragma unroll
                for (int j = 0; j < 8; j++) acc[i][j] += a[i] * bb[j];
        }
    }
    size_t out = (size_t)bid * HD * DS;
#pragma unroll
    for (int i = 0; i < 4; i++)
#pragma unroll
        for (int j = 0; j < 8; j++)
            g_states[out + (size_t)(ty * 4 + i) * DS + tx * 8 + j] = acc[i][j];
}

// ---------------- K7: chunk recurrence (serial over 8 chunks) ----------
__global__ void recur_kernel() {
    int idx = blockIdx.x * blockDim.x + threadIdx.x;  // B_*NH*HD*DS
    int n = idx & 127;
    int p = (idx >> 7) & 63;
    int h = (idx >> 13) & 31;
    int b = idx >> 18;
    float run = 0.f;
#pragma unroll
    for (int c = 0; c < NCH; c++) {
        size_t sidx = ((size_t)((b * NCH + c) * NH + h) * HD + p) * DS + n;
        g_init[sidx] = run;
        float cs = g_acs[((b * NH + h) * NCH + c) * CH + CH - 1];
        run = run * __expf(cs) + g_states[sidx];
    }
}

// ---------------- K8: CB[l,s] = Cm[l]·Bm[s] per (b,c) ----------
__global__ __launch_bounds__(256) void cb_kernel() {
    int z = blockIdx.z;  // b*NCH + c
    int b = z >> 3, c = z & 7;
    int l0 = blockIdx.y * 64, s0 = blockIdx.x * 64;
    int tid = threadIdx.x;
    int tx = tid & 15, ty = tid >> 4;
    __shared__ float ct[16][64];
    __shared__ float bt[16][64];
    int rowbase = b * L_ + c * CH;
    float acc[4][4];
#pragma unroll
    for (int i = 0; i < 4; i++)
#pragma unroll
        for (int j = 0; j < 4; j++) acc[i][j] = 0.f;

    for (int k0 = 0; k0 < DS; k0 += 16) {
        __syncthreads();
#pragma unroll
        for (int e = tid; e < 1024; e += 256) {
            int kk = e & 15, i = e >> 4;
            ct[kk][i] = g_xbc[(size_t)(rowbase + l0 + i) * CONVD + DI + DS + k0 + kk];
            bt[kk][i] = g_xbc[(size_t)(rowbase + s0 + i) * CONVD + DI + k0 + kk];
        }
        __syncthreads();
#pragma unroll
        for (int kk = 0; kk < 16; kk++) {
            float4 a4 = *(const float4*)&ct[kk][ty * 4];
            float4 b4 = *(const float4*)&bt[kk][tx * 4];
            float a[4] = {a4.x, a4.y, a4.z, a4.w};
            float bb[4] = {b4.x, b4.y, b4.z, b4.w};
#pragma unroll
            for (int i = 0; i < 4; i++)
#pragma unroll
                for (int j = 0; j < 4; j++) acc[i][j] += a[i] * bb[j];
        }
    }
#pragma unroll
    for (int i = 0; i < 4; i++)
#pragma unroll
        for (int j = 0; j < 4; j++)
            g_cb[((size_t)z * CH + l0 + ty * 4 + i) * CH + s0 + tx * 4 + j] = acc[i][j];
}

// ---------------- K9: Y = Y_off + Y_diag + D*xh per (b,c,h) ----------
__global__ __launch_bounds__(256) void y_kernel(const float* __restrict__ Dvec) {
    int bid = blockIdx.x;  // (b*NCH + c)*NH + h
    int b = bid >> 8, c = (bid >> 5) & 7, h = bid & 31;
    int tid = threadIdx.x;
    int tx = tid & 7, ty = tid >> 3;  // tx: 8 p-groups, ty: 32 l-groups
    __shared__ float acs_s[CH];
    __shared__ float mt[CH][17];
    __shared__ float xt[16][68];
    int base = ((b * NH + h) * NCH + c) * CH;
    acs_s[tid] = g_acs[base + tid];
    int rowbase = b * L_ + c * CH;
    float Dh = Dvec[h];
    size_t initbase = (size_t)bid * HD * DS;

    float acc[8][8];
#pragma unroll
    for (int i = 0; i < 8; i++)
#pragma unroll
        for (int j = 0; j < 8; j++) acc[i][j] = 0.f;

    // Phase 1: Y_off = Cm @ init_state^T  (scaled by exp(acs[l]) afterwards)
    for (int n0 = 0; n0 < DS; n0 += 16) {
        __syncthreads();
        {
            int l = tid;
            const float* cm = &g_xbc[(size_t)(rowbase + l) * CONVD + DI + DS + n0];
#pragma unroll
            for (int nn = 0; nn < 16; nn++) mt[l][nn] = cm[nn];
        }
#pragma unroll
        for (int e = tid; e < 1024; e += 256) {
            int p = e >> 4, nn = e & 15;
            xt[nn][p] = g_init[initbase + (size_t)p * DS + n0 + nn];
        }
        __syncthreads();
#pragma unroll
        for (int nn = 0; nn < 16; nn++) {
            float4 x0 = *(const float4*)&xt[nn][tx * 8];
            float4 x1 = *(const float4*)&xt[nn][tx * 8 + 4];
            float xv[8] = {x0.x, x0.y, x0.z, x0.w, x1.x, x1.y, x1.z, x1.w};
            float mv[8];
#pragma unroll
            for (int i = 0; i < 8; i++) mv[i] = mt[ty * 8 + i][nn];
#pragma unroll
            for (int i = 0; i < 8; i++)
#pragma unroll
                for (int j = 0; j < 8; j++) acc[i][j] += mv[i] * xv[j];
        }
    }
#pragma unroll
    for (int i = 0; i < 8; i++) {
        float el = __expf(acs_s[ty * 8 + i]);
#pragma unroll
        for (int j = 0; j < 8; j++) acc[i][j] *= el;
    }

    // Phase 2: Y_diag = (CB ∘ L) @ xd
    for (int s0 = 0; s0 < CH; s0 += 16) {
        __syncthreads();
        {
            int l = tid;
            float al = acs_s[l];
            const float* cbr = &g_cb[((size_t)(b * NCH + c) * CH + l) * CH + s0];
#pragma unroll
            for (int ss = 0; ss < 16; ss++) {
                int s = s0 + ss;
                mt[l][ss] = (s <= l) ? cbr[ss] * __expf(al - acs_s[s]) : 0.f;
            }
        }
#pragma unroll
        for (int e = tid; e < 1024; e += 256) {
            int ss = e >> 6, p = e & 63;
            int row = rowbase + s0 + ss;
            xt[ss][p] = g_xbc[(size_t)row * CONVD + h * HD + p] * g_dt[row * NH + h];
        }
        __syncthreads();
        if (s0 <= ty * 8 + 7) {
#pragma unroll
            for (int ss = 0; ss < 16; ss++) {
                float4 x0 = *(const float4*)&xt[ss][tx * 8];
                float4 x1 = *(const float4*)&xt[ss][tx * 8 + 4];
                float xv[8] = {x0.x, x0.y, x0.z, x0.w, x1.x, x1.y, x1.z, x1.w};
                float mv[8];
#pragma unroll
                for (int i = 0; i < 8; i++) mv[i] = mt[ty * 8 + i][ss];
#pragma unroll
                for (int i = 0; i < 8; i++)
#pragma unroll
                    for (int j = 0; j < 8; j++) acc[i][j] += mv[i] * xv[j];
            }
        }
    }

    // epilogue: + D*xh, write y
#pragma unroll
    for (int i = 0; i < 8; i++) {
        int row = rowbase + ty * 8 + i;
#pragma unroll
        for (int j = 0; j < 8; j++) {
            int p = tx * 8 + j;
            float xh = g_xbc[(size_t)row * CONVD + h * HD + p];
            g_y[(size_t)row * DI + h * HD + p] = acc[i][j] + Dh * xh;
        }
    }
}

// -------- K10: gated rmsnorm: y = rmsnorm(y*silu(z))*gw -> bf16 hi/lo --------
__global__ void gated_norm_kernel(const float* __restrict__ gw) {
    int row = blockIdx.x, tid = threadIdx.x;
    int d0 = tid * 8;
    const float* zr = &g_zx[(size_t)row * DPROJ + d0];
    const float* yr = &g_y[(size_t)row * DI + d0];
    float v[8];
    float local = 0.f;
#pragma unroll
    for (int q = 0; q < 2; q++) {
        float4 z4 = *(const float4*)(zr + q * 4);
        float4 y4 = *(const float4*)(yr + q * 4);
        float zz[4] = {z4.x, z4.y, z4.z, z4.w};
        float yy[4] = {y4.x, y4.y, y4.z, y4.w};
#pragma unroll
        for (int j = 0; j < 4; j++) {
            float t = yy[j] * (zz[j] / (1.f + __expf(-zz[j])));
            v[q * 4 + j] = t;
            local += t * t;
        }
    }
    float tot = blockReduceSum256(local);
    float r = rsqrtf(tot / (float)DI + 1e-5f);
    int o = row * (DI / 2) + tid * 4;
#pragma unroll
    for (int j = 0; j < 4; j++) {
        float a = v[2 * j] * r * gw[d0 + 2 * j];
        float b = v[2 * j + 1] * r * gw[d0 + 2 * j + 1];
        g_yh[o + j] = pack_bf16(a, b);
        g_yl[o + j] = pack_bf16(a - bf16r(a), b - bf16r(b));
    }
}

// ---------------- launch ----------------
extern "C" void kernel_launch(void* const* d_in, const int* in_sizes, int n_in,
                              void* d_out, int out_size) {
    const float* x         = (const float*)d_in[0];
    const float* norm_w    = (const float*)d_in[1];
    const float* in_proj_w = (const float*)d_in[2];
    const float* conv_w    = (const float*)d_in[3];
    const float* conv_b    = (const float*)d_in[4];
    const float* dt_bias   = (const float*)d_in[5];
    const float* A_log     = (const float*)d_in[6];
    const float* Dv        = (const float*)d_in[7];
    const float* gnorm_w   = (const float*)d_in[8];
    const float* out_proj_w= (const float*)d_in[9];
    float* out = (float*)d_out;

    float *pzx;
    uint32_t *puh, *pul, *pyh, *pyl, *pwih, *pwil, *pwoh, *pwol;
    cudaGetSymbolAddress((void**)&pzx, g_zx);
    cudaGetSymbolAddress((void**)&puh, g_uh);
    cudaGetSymbolAddress((void**)&pul, g_ul);
    cudaGetSymbolAddress((void**)&pyh, g_yh);
    cudaGetSymbolAddress((void**)&pyl, g_yl);
    cudaGetSymbolAddress((void**)&pwih, g_wih);
    cudaGetSymbolAddress((void**)&pwil, g_wil);
    cudaGetSymbolAddress((void**)&pwoh, g_woh);
    cudaGetSymbolAddress((void**)&pwol, g_wol);

    cudaFuncSetAttribute(mma_nt_pre, cudaFuncAttributeMaxDynamicSharedMemorySize, GSMEM);

    // weight conversions (each launch; cheap, memory-bound)
    cvt_pairs_kernel<<<(DPROJ * DM / 2 + 255) / 256, 256>>>(in_proj_w, pwih, pwil,
                                                            DPROJ * DM / 2);
    cvt_pairs_kernel<<<(DM * DI / 2 + 255) / 256, 256>>>(out_proj_w, pwoh, pwol,
                                                         DM * DI / 2);

    rmsnorm_x_kernel<<<ROWS, 256>>>(x, norm_w);
    mma_nt_pre<<<dim3((DPROJ + 127) / 128, ROWS / 128), 256, GSMEM>>>(
        puh, pul, pwih, pwil, pzx, nullptr, ROWS, DPROJ, DM, 0);
    conv_silu_kernel<<<(ROWS * CONVD) / 256, 256>>>(conv_w, conv_b);
    dt_kernel<<<(ROWS * NH) / 256, 256>>>(dt_bias);
    acs_kernel<<<B_ * NH * NCH, 256>>>(A_log);
    states_kernel<<<B_ * NCH * NH, 256>>>();
    recur_kernel<<<(B_ * NH * HD * DS) / 256, 256>>>();
    cb_kernel<<<dim3(4, 4, B_ * NCH), 256>>>();
    y_kernel<<<B_ * NCH * NH, 256>>>(Dv);
    gated_norm_kernel<<<ROWS, 256>>>(gnorm_w);
    mma_nt_pre<<<dim3(DM / 128, ROWS / 128), 256, GSMEM>>>(
        pyh, pyl, pwoh, pwol, out, x, ROWS, DM, DI, 1);
}

// round 6
// speedup vs baseline: 1.9469x; 1.0346x over previous
#include <cuda_runtime.h>
#include <cuda_bf16.h>
#include <math.h>
#include <stdint.h>

// ---------------- problem constants ----------------
#define B_    2
#define L_    2048
#define DM    1024          // d_model
#define DI    2048          // d_inner
#define NH    32            // nheads
#define HD    64            // headdim
#define DS    128           // d_state
#define CONVD 2304          // conv dim = DI + 2*DS
#define DPROJ 4384          // 2*DI + 2*DS + NH
#define NCH   8             // chunks per batch
#define CH    256           // chunk length
#define ROWS  4096          // B_*L_

// ---------------- scratch (device globals; no allocation allowed) ----------------
__device__ float g_zx[(size_t)ROWS * DPROJ];        // in_proj output
__device__ float g_xbc[(size_t)ROWS * CONVD];       // conv+silu output
__device__ float g_dt[ROWS * NH];                   // softplus(dt)
__device__ float g_acs[B_ * NH * NCH * CH];         // cumsum(dt*A) per chunk
__device__ float g_states[(size_t)B_ * NCH * NH * HD * DS];
__device__ float g_init[(size_t)B_ * NCH * NH * HD * DS];
__device__ float g_cb[(size_t)B_ * NCH * CH * CH];  // Cm @ Bm^T per chunk
__device__ float g_y[(size_t)ROWS * DI];            // y (pre gated-norm)

// packed bf16x2 hi/lo operand arrays
__device__ uint32_t g_uh[ROWS * DM / 2];            // rmsnorm(x) hi
__device__ uint32_t g_ul[ROWS * DM / 2];            // rmsnorm(x) lo
__device__ uint32_t g_yh[(size_t)ROWS * DI / 2];    // gated-norm(y) hi
__device__ uint32_t g_yl[(size_t)ROWS * DI / 2];    // gated-norm(y) lo
__device__ uint32_t g_wih[(size_t)DPROJ * DM / 2];  // in_proj_w hi
__device__ uint32_t g_wil[(size_t)DPROJ * DM / 2];  // in_proj_w lo
__device__ uint32_t g_woh[(size_t)DM * DI / 2];     // out_proj_w hi
__device__ uint32_t g_wol[(size_t)DM * DI / 2];     // out_proj_w lo

// ---------------- helpers ----------------
__device__ __forceinline__ float blockReduceSum256(float v) {
    __shared__ float ws[8];
    __shared__ float tot;
    int lane = threadIdx.x & 31, wid = threadIdx.x >> 5;
#pragma unroll
    for (int o = 16; o; o >>= 1) v += __shfl_xor_sync(0xffffffffu, v, o);
    if (lane == 0) ws[wid] = v;
    __syncthreads();
    if (threadIdx.x == 0) {
        float s = 0.f;
#pragma unroll
        for (int i = 0; i < 8; i++) s += ws[i];
        tot = s;
    }
    __syncthreads();
    return tot;
}

__device__ __forceinline__ uint32_t pack_bf16(float a, float b) {
    __nv_bfloat162 h = __floats2bfloat162_rn(a, b);
    return *(uint32_t*)&h;
}

__device__ __forceinline__ float bf16r(float v) {
    return __bfloat162float(__float2bfloat16(v));
}

__device__ __forceinline__ uint32_t smem_u32(const void* p) {
    uint32_t a;
    asm("{ .reg .u64 t; cvta.to.shared.u64 t, %1; cvt.u32.u64 %0, t; }"
        : "=r"(a) : "l"(p));
    return a;
}

// m16n8k16 row.col bf16 MMA, fp32 accumulate
__device__ __forceinline__ void mma_bf16(float* d, const uint32_t* a, const uint32_t* b) {
    asm volatile(
        "mma.sync.aligned.m16n8k16.row.col.f32.bf16.bf16.f32 "
        "{%0,%1,%2,%3}, {%4,%5,%6,%7}, {%8,%9}, {%0,%1,%2,%3};"
        : "+f"(d[0]), "+f"(d[1]), "+f"(d[2]), "+f"(d[3])
        : "r"(a[0]), "r"(a[1]), "r"(a[2]), "r"(a[3]), "r"(b[0]), "r"(b[1]));
}

__device__ __forceinline__ void ldsm4(uint32_t* r, uint32_t addr) {
    asm volatile("ldmatrix.sync.aligned.m8n8.x4.shared.b16 {%0,%1,%2,%3}, [%4];"
                 : "=r"(r[0]), "=r"(r[1]), "=r"(r[2]), "=r"(r[3]) : "r"(addr));
}

__device__ __forceinline__ void cp16(uint32_t dst, const void* src, bool ok) {
    if (ok)
        asm volatile("cp.async.cg.shared.global [%0], [%1], 16;"
                     :: "r"(dst), "l"(src) : "memory");
    else
        asm volatile("cp.async.cg.shared.global [%0], [%1], 16, 0;"
                     :: "r"(dst), "l"(src) : "memory");
}

// ---------------- K0: split fp32 pairs -> bf16 hi/lo packed ----------
__global__ void cvt_pairs_kernel(const float* __restrict__ W,
                                 uint32_t* __restrict__ Wh,
                                 uint32_t* __restrict__ Wl, int npairs) {
    int i = blockIdx.x * blockDim.x + threadIdx.x;
    if (i < npairs) {
        float2 v = ((const float2*)W)[i];
        Wh[i] = pack_bf16(v.x, v.y);
        Wl[i] = pack_bf16(v.x - bf16r(v.x), v.y - bf16r(v.y));
    }
}

// ---------------- K1: rmsnorm(x) -> bf16 hi/lo ----------------
__global__ void rmsnorm_x_kernel(const float* __restrict__ x,
                                 const float* __restrict__ w) {
    int row = blockIdx.x, tid = threadIdx.x;
    const float4 v = ((const float4*)(x + (size_t)row * DM))[tid];
    const float4 wv = ((const float4*)w)[tid];
    float local = v.x * v.x + v.y * v.y + v.z * v.z + v.w * v.w;
    float tot = blockReduceSum256(local);
    float r = rsqrtf(tot / (float)DM + 1e-5f);
    float u0 = v.x * r * wv.x, u1 = v.y * r * wv.y;
    float u2 = v.z * r * wv.z, u3 = v.w * r * wv.w;
    int o = row * (DM / 2) + tid * 2;
    g_uh[o] = pack_bf16(u0, u1);
    g_uh[o + 1] = pack_bf16(u2, u3);
    g_ul[o] = pack_bf16(u0 - bf16r(u0), u1 - bf16r(u1));
    g_ul[o + 1] = pack_bf16(u2 - bf16r(u2), u3 - bf16r(u3));
}

// ------- tensor-core NT GEMM, preconverted bf16 hi/lo, cp.async 2-stage -------
// C[M,N] = A[M,K]*B[N,K]^T (+resid). 128x128 tile, K-slab 32, 256 thr, 8 warps.
// Fragments loaded via ldmatrix.x4 (12 LDSM per k16-step instead of 48 LDS).
// smem per stage: 4 arrays x 128 rows x 20 u32 (16 data + 4 pad).
#define UPS   (4 * 128 * 20)          // u32 per stage
#define GSMEM (2 * UPS * 4)           // bytes
__global__ __launch_bounds__(256) void mma_nt_pre(const uint32_t* __restrict__ Ahg,
                                                  const uint32_t* __restrict__ Alg,
                                                  const uint32_t* __restrict__ Bhg,
                                                  const uint32_t* __restrict__ Blg,
                                                  float* __restrict__ C,
                                                  const float* __restrict__ resid,
                                                  int M, int N, int K, int addRes) {
    extern __shared__ __align__(16) uint32_t S[];
    uint32_t sbase = smem_u32(S);
    int tid = threadIdx.x;
    int warp = tid >> 5, lane = tid & 31;
    int wm = warp & 1, wn = warp >> 1;  // 2 x 4
    int bm = blockIdx.y * 128, bn = blockIdx.x * 128;
    int g = lane >> 2, tg = lane & 3;
    int K2 = K >> 1;

    int lrow = tid >> 1, lhalf = tid & 1;     // row 0..127, 8-u32 half
    const uint32_t* pA[2] = {Ahg + (size_t)(bm + lrow) * K2 + lhalf * 8,
                             Alg + (size_t)(bm + lrow) * K2 + lhalf * 8};
    bool okB = (bn + lrow) < N;
    int brow = okB ? (bn + lrow) : 0;
    const uint32_t* pB[2] = {Bhg + (size_t)brow * K2 + lhalf * 8,
                             Blg + (size_t)brow * K2 + lhalf * 8};
    uint32_t dto = (uint32_t)(lrow * 20 + lhalf * 8) * 4;

    // ldmatrix per-thread base addresses (stage 0, kk = 0)
    int mat = lane >> 3, mrow = lane & 7;
    uint32_t a_ad[4], b_ad[2];
#pragma unroll
    for (int mt = 0; mt < 4; mt++) {
        int r = wm * 64 + mt * 16 + (mat & 1) * 8 + mrow;
        a_ad[mt] = sbase + (uint32_t)(r * 20 + (mat >> 1) * 4) * 4;
    }
#pragma unroll
    for (int p = 0; p < 2; p++) {
        int n = wn * 32 + p * 16 + (mat >> 1) * 8 + mrow;
        b_ad[p] = sbase + (uint32_t)(n * 20 + (mat & 1) * 4) * 4;
    }

    float acc[4][4][4];
#pragma unroll
    for (int mt = 0; mt < 4; mt++)
#pragma unroll
        for (int nt = 0; nt < 4; nt++)
#pragma unroll
            for (int q = 0; q < 4; q++) acc[mt][nt][q] = 0.f;

    int nslab = K >> 5;

    auto issue = [&](int st, int sl) {
        int ko = sl * 16;  // u32 offset within row
        uint32_t db = sbase + (uint32_t)(st * UPS) * 4 + dto;
#pragma unroll
        for (int t = 0; t < 2; t++) {
            cp16(db + (uint32_t)(t * 2560 * 4), pA[t] + ko, true);
            cp16(db + (uint32_t)(t * 2560 * 4) + 16, pA[t] + ko + 4, true);
            cp16(db + (uint32_t)((2 + t) * 2560 * 4), pB[t] + ko, okB);
            cp16(db + (uint32_t)((2 + t) * 2560 * 4) + 16, pB[t] + ko + 4, okB);
        }
        asm volatile("cp.async.commit_group;" ::: "memory");
    };

    issue(0, 0);
    int st = 0;
    for (int i = 0; i < nslab; i++) {
        if (i + 1 < nslab) {
            issue(st ^ 1, i + 1);
            asm volatile("cp.async.wait_group 1;" ::: "memory");
        } else {
            asm volatile("cp.async.wait_group 0;" ::: "memory");
        }
        __syncthreads();
        uint32_t so = (uint32_t)(st * UPS) * 4;
#pragma unroll
        for (int kk = 0; kk < 2; kk++) {
            uint32_t kb = so + kk * 32;  // 8 u32 per k16 step
            uint32_t ahi[4][4], alo[4][4];
#pragma unroll
            for (int mt = 0; mt < 4; mt++) {
                ldsm4(ahi[mt], a_ad[mt] + kb);
                ldsm4(alo[mt], a_ad[mt] + kb + 2560 * 4);
            }
            uint32_t bhi[4][2], blo[4][2];
#pragma unroll
            for (int p = 0; p < 2; p++) {
                uint32_t t4[4];
                ldsm4(t4, b_ad[p] + kb + 2 * 2560 * 4);
                bhi[p * 2][0] = t4[0]; bhi[p * 2][1] = t4[1];
                bhi[p * 2 + 1][0] = t4[2]; bhi[p * 2 + 1][1] = t4[3];
                ldsm4(t4, b_ad[p] + kb + 3 * 2560 * 4);
                blo[p * 2][0] = t4[0]; blo[p * 2][1] = t4[1];
                blo[p * 2 + 1][0] = t4[2]; blo[p * 2 + 1][1] = t4[3];
            }
#pragma unroll
            for (int mt = 0; mt < 4; mt++)
#pragma unroll
                for (int nt = 0; nt < 4; nt++) {
                    mma_bf16(acc[mt][nt], ahi[mt], bhi[nt]);
                    mma_bf16(acc[mt][nt], ahi[mt], blo[nt]);
                    mma_bf16(acc[mt][nt], alo[mt], bhi[nt]);
                }
        }
        __syncthreads();
        st ^= 1;
    }

#pragma unroll
    for (int mt = 0; mt < 4; mt++) {
        int row = bm + wm * 64 + mt * 16 + g;
#pragma unroll
        for (int nt = 0; nt < 4; nt++) {
            int col = bn + wn * 32 + nt * 8 + tg * 2;
            if (col < N) {
                float* a = acc[mt][nt];
                size_t i0 = (size_t)row * N + col;
                size_t i1 = (size_t)(row + 8) * N + col;
                if (addRes) {
                    a[0] += resid[i0]; a[1] += resid[i0 + 1];
                    a[2] += resid[i1]; a[3] += resid[i1 + 1];
                }
                C[i0] = a[0]; C[i0 + 1] = a[1];
                C[i1] = a[2]; C[i1 + 1] = a[3];
            }
        }
    }
}

// ---------------- K3: depthwise causal conv (width 4) + bias + silu ----------
__global__ void conv_silu_kernel(const float* __restrict__ conv_w,
                                 const float* __restrict__ conv_b) {
    int idx = blockIdx.x * blockDim.x + threadIdx.x;  // ROWS*CONVD
    int c = idx % CONVD;
    int row = idx / CONVD;
    int l = row & (L_ - 1);
    const float* w = conv_w + c * 4;
    float acc = conv_b[c];
#pragma unroll
    for (int j = 0; j < 4; j++) {
        int ls = l - 3 + j;
        if (ls >= 0)
            acc += w[j] * g_zx[(size_t)(row - 3 + j) * DPROJ + DI + c];
    }
    float s = acc / (1.f + __expf(-acc));
    g_xbc[(size_t)row * CONVD + c] = s;
}

// ---------------- K4: dt = softplus(dt_raw + dt_bias) ----------
__global__ void dt_kernel(const float* __restrict__ dt_bias) {
    int idx = blockIdx.x * blockDim.x + threadIdx.x;  // ROWS*NH
    int h = idx & (NH - 1);
    int row = idx >> 5;
    float v = g_zx[(size_t)row * DPROJ + (DI + CONVD) + h] + dt_bias[h];
    float sp = (v > 20.f) ? v : log1pf(__expf(v));
    g_dt[row * NH + h] = sp;
}

// ---------------- K5: per-chunk cumsum of a = dt * A ----------
__global__ void acs_kernel(const float* __restrict__ A_log) {
    int bid = blockIdx.x;  // (b*NH + h)*NCH + c
    int b = bid >> 8, h = (bid >> 3) & 31, c = bid & 7;
    int l = threadIdx.x;
    int row = b * L_ + c * CH + l;
    float A = -__expf(A_log[h]);
    __shared__ float s[CH];
    s[l] = g_dt[row * NH + h] * A;
    __syncthreads();
#pragma unroll
    for (int off = 1; off < CH; off <<= 1) {
        float v = (l >= off) ? s[l - off] : 0.f;
        __syncthreads();
        s[l] += v;
        __syncthreads();
    }
    g_acs[bid * CH + l] = s[l];
}

// ---------------- K6: per-chunk states[p,n] = sum_l decay*xd[l,p]*B[l,n] -----
__global__ __launch_bounds__(256) void states_kernel() {
    int bid = blockIdx.x;  // (b*NCH + c)*NH + h
    int b = bid >> 8, c = (bid >> 5) & 7, h = bid & 31;
    int tid = threadIdx.x;
    int tx = tid & 15, ty = tid >> 4;
    __shared__ float xdw[16][64];
    __shared__ float bs[16][128];
    __shared__ float coef[16];
    int base = ((b * NH + h) * NCH + c) * CH;
    float acs_last = g_acs[base + CH - 1];
    int rowbase = b * L_ + c * CH;

    float acc[4][8];
#pragma unroll
    for (int i = 0; i < 4; i++)
#pragma unroll
        for (int j = 0; j < 8; j++) acc[i][j] = 0.f;

    for (int l0 = 0; l0 < CH; l0 += 16) {
        __syncthreads();
        if (tid < 16) {
            int row = rowbase + l0 + tid;
            coef[tid] = g_dt[row * NH + h] * __expf(acs_last - g_acs[base + l0 + tid]);
        }
        __syncthreads();
#pragma unroll
        for (int e = tid; e < 16 * 64; e += 256) {
            int ll = e >> 6, p = e & 63;
            int row = rowbase + l0 + ll;
            xdw[ll][p] = g_xbc[(size_t)row * CONVD + h * HD + p] * coef[ll];
        }
#pragma unroll
        for (int e = tid; e < 16 * 128; e += 256) {
            int ll = e >> 7, n = e & 127;
            int row = rowbase + l0 + ll;
            bs[ll][n] = g_xbc[(size_t)row * CONVD + DI + n];
        }
        __syncthreads();
#pragma unroll
        for (int ll = 0; ll < 16; ll++) {
            float4 a4 = *(const float4*)&xdw[ll][ty * 4];
            float4 b0 = *(const float4*)&bs[ll][tx * 8];
            float4 b1 = *(const float4*)&bs[ll][tx * 8 + 4];
            float a[4] = {a4.x, a4.y, a4.z, a4.w};
            float bb[8] = {b0.x, b0.y, b0.z, b0.w, b1.x, b1.y, b1.z, b1.w};
#pragma unroll
            for (int i = 0; i < 4; i++)
#pragma unroll
                for (int j = 0; j < 8; j++) acc[i][j] += a[i] * bb[j];
        }
    }
    size_t out = (size_t)bid * HD * DS;
#pragma unroll
    for (int i = 0; i < 4; i++)
#pragma unroll
        for (int j = 0; j < 8; j++)
            g_states[out + (size_t)(ty * 4 + i) * DS + tx * 8 + j] = acc[i][j];
}

// ---------------- K7: chunk recurrence (serial over 8 chunks) ----------
__global__ void recur_kernel() {
    int idx = blockIdx.x * blockDim.x + threadIdx.x;  // B_*NH*HD*DS
    int n = idx & 127;
    int p = (idx >> 7) & 63;
    int h = (idx >> 13) & 31;
    int b = idx >> 18;
    float run = 0.f;
#pragma unroll
    for (int c = 0; c < NCH; c++) {
        size_t sidx = ((size_t)((b * NCH + c) * NH + h) * HD + p) * DS + n;
        g_init[sidx] = run;
        float cs = g_acs[((b * NH + h) * NCH + c) * CH + CH - 1];
        run = run * __expf(cs) + g_states[sidx];
    }
}

// ---------------- K8: CB[l,s] = Cm[l]·Bm[s] per (b,c) ----------
__global__ __launch_bounds__(256) void cb_kernel() {
    int z = blockIdx.z;  // b*NCH + c
    int b = z >> 3, c = z & 7;
    int l0 = blockIdx.y * 64, s0 = blockIdx.x * 64;
    int tid = threadIdx.x;
    int tx = tid & 15, ty = tid >> 4;
    __shared__ float ct[16][64];
    __shared__ float bt[16][64];
    int rowbase = b * L_ + c * CH;
    float acc[4][4];
#pragma unroll
    for (int i = 0; i < 4; i++)
#pragma unroll
        for (int j = 0; j < 4; j++) acc[i][j] = 0.f;

    for (int k0 = 0; k0 < DS; k0 += 16) {
        __syncthreads();
#pragma unroll
        for (int e = tid; e < 1024; e += 256) {
            int kk = e & 15, i = e >> 4;
            ct[kk][i] = g_xbc[(size_t)(rowbase + l0 + i) * CONVD + DI + DS + k0 + kk];
            bt[kk][i] = g_xbc[(size_t)(rowbase + s0 + i) * CONVD + DI + k0 + kk];
        }
        __syncthreads();
#pragma unroll
        for (int kk = 0; kk < 16; kk++) {
            float4 a4 = *(const float4*)&ct[kk][ty * 4];
            float4 b4 = *(const float4*)&bt[kk][tx * 4];
            float a[4] = {a4.x, a4.y, a4.z, a4.w};
            float bb[4] = {b4.x, b4.y, b4.z, b4.w};
#pragma unroll
            for (int i = 0; i < 4; i++)
#pragma unroll
                for (int j = 0; j < 4; j++) acc[i][j] += a[i] * bb[j];
        }
    }
#pragma unroll
    for (int i = 0; i < 4; i++)
#pragma unroll
        for (int j = 0; j < 4; j++)
            g_cb[((size_t)z * CH + l0 + ty * 4 + i) * CH + s0 + tx * 4 + j] = acc[i][j];
}

// ---------------- K9: Y = Y_off + Y_diag + D*xh per (b,c,h) ----------
__global__ __launch_bounds__(256) void y_kernel(const float* __restrict__ Dvec) {
    int bid = blockIdx.x;  // (b*NCH + c)*NH + h
    int b = bid >> 8, c = (bid >> 5) & 7, h = bid & 31;
    int tid = threadIdx.x;
    int tx = tid & 7, ty = tid >> 3;  // tx: 8 p-groups, ty: 32 l-groups
    __shared__ float acs_s[CH];
    __shared__ float mt[CH][17];
    __shared__ float xt[16][68];
    int base = ((b * NH + h) * NCH + c) * CH;
    acs_s[tid] = g_acs[base + tid];
    int rowbase = b * L_ + c * CH;
    float Dh = Dvec[h];
    size_t initbase = (size_t)bid * HD * DS;

    float acc[8][8];
#pragma unroll
    for (int i = 0; i < 8; i++)
#pragma unroll
        for (int j = 0; j < 8; j++) acc[i][j] = 0.f;

    // Phase 1: Y_off = Cm @ init_state^T  (scaled by exp(acs[l]) afterwards)
    for (int n0 = 0; n0 < DS; n0 += 16) {
        __syncthreads();
        {
            int l = tid;
            const float* cm = &g_xbc[(size_t)(rowbase + l) * CONVD + DI + DS + n0];
#pragma unroll
            for (int nn = 0; nn < 16; nn++) mt[l][nn] = cm[nn];
        }
#pragma unroll
        for (int e = tid; e < 1024; e += 256) {
            int p = e >> 4, nn = e & 15;
            xt[nn][p] = g_init[initbase + (size_t)p * DS + n0 + nn];
        }
        __syncthreads();
#pragma unroll
        for (int nn = 0; nn < 16; nn++) {
            float4 x0 = *(const float4*)&xt[nn][tx * 8];
            float4 x1 = *(const float4*)&xt[nn][tx * 8 + 4];
            float xv[8] = {x0.x, x0.y, x0.z, x0.w, x1.x, x1.y, x1.z, x1.w};
            float mv[8];
#pragma unroll
            for (int i = 0; i < 8; i++) mv[i] = mt[ty * 8 + i][nn];
#pragma unroll
            for (int i = 0; i < 8; i++)
#pragma unroll
                for (int j = 0; j < 8; j++) acc[i][j] += mv[i] * xv[j];
        }
    }
#pragma unroll
    for (int i = 0; i < 8; i++) {
        float el = __expf(acs_s[ty * 8 + i]);
#pragma unroll
        for (int j = 0; j < 8; j++) acc[i][j] *= el;
    }

    // Phase 2: Y_diag = (CB ∘ L) @ xd
    for (int s0 = 0; s0 < CH; s0 += 16) {
        __syncthreads();
        {
            int l = tid;
            float al = acs_s[l];
            const float* cbr = &g_cb[((size_t)(b * NCH + c) * CH + l) * CH + s0];
#pragma unroll
            for (int ss = 0; ss < 16; ss++) {
                int s = s0 + ss;
                mt[l][ss] = (s <= l) ? cbr[ss] * __expf(al - acs_s[s]) : 0.f;
            }
        }
#pragma unroll
        for (int e = tid; e < 1024; e += 256) {
            int ss = e >> 6, p = e & 63;
            int row = rowbase + s0 + ss;
            xt[ss][p] = g_xbc[(size_t)row * CONVD + h * HD + p] * g_dt[row * NH + h];
        }
        __syncthreads();
        if (s0 <= ty * 8 + 7) {
#pragma unroll
            for (int ss = 0; ss < 16; ss++) {
                float4 x0 = *(const float4*)&xt[ss][tx * 8];
                float4 x1 = *(const float4*)&xt[ss][tx * 8 + 4];
                float xv[8] = {x0.x, x0.y, x0.z, x0.w, x1.x, x1.y, x1.z, x1.w};
                float mv[8];
#pragma unroll
                for (int i = 0; i < 8; i++) mv[i] = mt[ty * 8 + i][ss];
#pragma unroll
                for (int i = 0; i < 8; i++)
#pragma unroll
                    for (int j = 0; j < 8; j++) acc[i][j] += mv[i] * xv[j];
            }
        }
    }

    // epilogue: + D*xh, write y
#pragma unroll
    for (int i = 0; i < 8; i++) {
        int row = rowbase + ty * 8 + i;
#pragma unroll
        for (int j = 0; j < 8; j++) {
            int p = tx * 8 + j;
            float xh = g_xbc[(size_t)row * CONVD + h * HD + p];
            g_y[(size_t)row * DI + h * HD + p] = acc[i][j] + Dh * xh;
        }
    }
}

// -------- K10: gated rmsnorm: y = rmsnorm(y*silu(z))*gw -> bf16 hi/lo --------
__global__ void gated_norm_kernel(const float* __restrict__ gw) {
    int row = blockIdx.x, tid = threadIdx.x;
    int d0 = tid * 8;
    const float* zr = &g_zx[(size_t)row * DPROJ + d0];
    const float* yr = &g_y[(size_t)row * DI + d0];
    float v[8];
    float local = 0.f;
#pragma unroll
    for (int q = 0; q < 2; q++) {
        float4 z4 = *(const float4*)(zr + q * 4);
        float4 y4 = *(const float4*)(yr + q * 4);
        float zz[4] = {z4.x, z4.y, z4.z, z4.w};
        float yy[4] = {y4.x, y4.y, y4.z, y4.w};
#pragma unroll
        for (int j = 0; j < 4; j++) {
            float t = yy[j] * (zz[j] / (1.f + __expf(-zz[j])));
            v[q * 4 + j] = t;
            local += t * t;
        }
    }
    float tot = blockReduceSum256(local);
    float r = rsqrtf(tot / (float)DI + 1e-5f);
    int o = row * (DI / 2) + tid * 4;
#pragma unroll
    for (int j = 0; j < 4; j++) {
        float a = v[2 * j] * r * gw[d0 + 2 * j];
        float b = v[2 * j + 1] * r * gw[d0 + 2 * j + 1];
        g_yh[o + j] = pack_bf16(a, b);
        g_yl[o + j] = pack_bf16(a - bf16r(a), b - bf16r(b));
    }
}

// ---------------- launch ----------------
extern "C" void kernel_launch(void* const* d_in, const int* in_sizes, int n_in,
                              void* d_out, int out_size) {
    const float* x         = (const float*)d_in[0];
    const float* norm_w    = (const float*)d_in[1];
    const float* in_proj_w = (const float*)d_in[2];
    const float* conv_w    = (const float*)d_in[3];
    const float* conv_b    = (const float*)d_in[4];
    const float* dt_bias   = (const float*)d_in[5];
    const float* A_log     = (const float*)d_in[6];
    const float* Dv        = (const float*)d_in[7];
    const float* gnorm_w   = (const float*)d_in[8];
    const float* out_proj_w= (const float*)d_in[9];
    float* out = (float*)d_out;

    float *pzx;
    uint32_t *puh, *pul, *pyh, *pyl, *pwih, *pwil, *pwoh, *pwol;
    cudaGetSymbolAddress((void**)&pzx, g_zx);
    cudaGetSymbolAddress((void**)&puh, g_uh);
    cudaGetSymbolAddress((void**)&pul, g_ul);
    cudaGetSymbolAddress((void**)&pyh, g_yh);
    cudaGetSymbolAddress((void**)&pyl, g_yl);
    cudaGetSymbolAddress((void**)&pwih, g_wih);
    cudaGetSymbolAddress((void**)&pwil, g_wil);
    cudaGetSymbolAddress((void**)&pwoh, g_woh);
    cudaGetSymbolAddress((void**)&pwol, g_wol);

    cudaFuncSetAttribute(mma_nt_pre, cudaFuncAttributeMaxDynamicSharedMemorySize, GSMEM);

    cvt_pairs_kernel<<<(DPROJ * DM / 2 + 255) / 256, 256>>>(in_proj_w, pwih, pwil,
                                                            DPROJ * DM / 2);
    cvt_pairs_kernel<<<(DM * DI / 2 + 255) / 256, 256>>>(out_proj_w, pwoh, pwol,
                                                         DM * DI / 2);

    rmsnorm_x_kernel<<<ROWS, 256>>>(x, norm_w);
    mma_nt_pre<<<dim3((DPROJ + 127) / 128, ROWS / 128), 256, GSMEM>>>(
        puh, pul, pwih, pwil, pzx, nullptr, ROWS, DPROJ, DM, 0);
    conv_silu_kernel<<<(ROWS * CONVD) / 256, 256>>>(conv_w, conv_b);
    dt_kernel<<<(ROWS * NH) / 256, 256>>>(dt_bias);
    acs_kernel<<<B_ * NH * NCH, 256>>>(A_log);
    states_kernel<<<B_ * NCH * NH, 256>>>();
    recur_kernel<<<(B_ * NH * HD * DS) / 256, 256>>>();
    cb_kernel<<<dim3(4, 4, B_ * NCH), 256>>>();
    y_kernel<<<B_ * NCH * NH, 256>>>(Dv);
    gated_norm_kernel<<<ROWS, 256>>>(gnorm_w);
    mma_nt_pre<<<dim3(DM / 128, ROWS / 128), 256, GSMEM>>>(
        pyh, pyl, pwoh, pwol, out, x, ROWS, DM, DI, 1);
}

// round 7
// speedup vs baseline: 2.1140x; 1.0858x over previous
#include <cuda_runtime.h>
#include <cuda_bf16.h>
#include <math.h>
#include <stdint.h>

// ---------------- problem constants ----------------
#define B_    2
#define L_    2048
#define DM    1024          // d_model
#define DI    2048          // d_inner
#define NH    32            // nheads
#define HD    64            // headdim
#define DS    128           // d_state
#define CONVD 2304          // conv dim = DI + 2*DS
#define DPROJ 4384          // 2*DI + 2*DS + NH
#define NCH   8             // chunks per batch
#define CH    256           // chunk length
#define ROWS  4096          // B_*L_

// ---------------- scratch (device globals; no allocation allowed) ----------------
__device__ float g_zx[(size_t)ROWS * DPROJ];        // in_proj output
__device__ float g_xbc[(size_t)ROWS * CONVD];       // conv+silu output
__device__ float g_dt[ROWS * NH];                   // softplus(dt)
__device__ float g_acs[B_ * NH * NCH * CH];         // cumsum(dt*A) per chunk
__device__ float g_states[(size_t)B_ * NCH * NH * HD * DS];
__device__ float g_init[(size_t)B_ * NCH * NH * HD * DS];
__device__ float g_cb[(size_t)B_ * NCH * CH * CH];  // Cm @ Bm^T per chunk
__device__ float g_y[(size_t)ROWS * DI];            // y (pre gated-norm)

// packed bf16x2 hi/lo operand arrays
__device__ uint32_t g_uh[ROWS * DM / 2];            // rmsnorm(x) hi
__device__ uint32_t g_ul[ROWS * DM / 2];            // rmsnorm(x) lo
__device__ uint32_t g_yh[(size_t)ROWS * DI / 2];    // gated-norm(y) hi
__device__ uint32_t g_yl[(size_t)ROWS * DI / 2];    // gated-norm(y) lo
__device__ uint32_t g_wih[(size_t)DPROJ * DM / 2];  // in_proj_w hi
__device__ uint32_t g_wil[(size_t)DPROJ * DM / 2];  // in_proj_w lo
__device__ uint32_t g_woh[(size_t)DM * DI / 2];     // out_proj_w hi
__device__ uint32_t g_wol[(size_t)DM * DI / 2];     // out_proj_w lo

// ---------------- helpers ----------------
__device__ __forceinline__ float blockReduceSum256(float v) {
    __shared__ float ws[8];
    __shared__ float tot;
    int lane = threadIdx.x & 31, wid = threadIdx.x >> 5;
#pragma unroll
    for (int o = 16; o; o >>= 1) v += __shfl_xor_sync(0xffffffffu, v, o);
    if (lane == 0) ws[wid] = v;
    __syncthreads();
    if (threadIdx.x == 0) {
        float s = 0.f;
#pragma unroll
        for (int i = 0; i < 8; i++) s += ws[i];
        tot = s;
    }
    __syncthreads();
    return tot;
}

__device__ __forceinline__ uint32_t pack_bf16(float a, float b) {
    __nv_bfloat162 h = __floats2bfloat162_rn(a, b);
    return *(uint32_t*)&h;
}

__device__ __forceinline__ float bf16r(float v) {
    return __bfloat162float(__float2bfloat16(v));
}

__device__ __forceinline__ uint32_t smem_u32(const void* p) {
    uint32_t a;
    asm("{ .reg .u64 t; cvta.to.shared.u64 t, %1; cvt.u32.u64 %0, t; }"
        : "=r"(a) : "l"(p));
    return a;
}

// m16n8k16 row.col bf16 MMA, fp32 accumulate
__device__ __forceinline__ void mma_bf16(float* d, const uint32_t* a, const uint32_t* b) {
    asm volatile(
        "mma.sync.aligned.m16n8k16.row.col.f32.bf16.bf16.f32 "
        "{%0,%1,%2,%3}, {%4,%5,%6,%7}, {%8,%9}, {%0,%1,%2,%3};"
        : "+f"(d[0]), "+f"(d[1]), "+f"(d[2]), "+f"(d[3])
        : "r"(a[0]), "r"(a[1]), "r"(a[2]), "r"(a[3]), "r"(b[0]), "r"(b[1]));
}

__device__ __forceinline__ void ldsm4(uint32_t* r, uint32_t addr) {
    asm volatile("ldmatrix.sync.aligned.m8n8.x4.shared.b16 {%0,%1,%2,%3}, [%4];"
                 : "=r"(r[0]), "=r"(r[1]), "=r"(r[2]), "=r"(r[3]) : "r"(addr));
}

__device__ __forceinline__ void cp16(uint32_t dst, const void* src, bool ok) {
    if (ok)
        asm volatile("cp.async.cg.shared.global [%0], [%1], 16;"
                     :: "r"(dst), "l"(src) : "memory");
    else
        asm volatile("cp.async.cg.shared.global [%0], [%1], 16, 0;"
                     :: "r"(dst), "l"(src) : "memory");
}

// ---------------- K0: split fp32 pairs -> bf16 hi/lo packed ----------
__global__ void cvt_pairs_kernel(const float* __restrict__ W,
                                 uint32_t* __restrict__ Wh,
                                 uint32_t* __restrict__ Wl, int npairs) {
    int i = blockIdx.x * blockDim.x + threadIdx.x;
    if (i < npairs) {
        float2 v = ((const float2*)W)[i];
        Wh[i] = pack_bf16(v.x, v.y);
        Wl[i] = pack_bf16(v.x - bf16r(v.x), v.y - bf16r(v.y));
    }
}

// ---------------- K1: rmsnorm(x) -> bf16 hi/lo ----------------
__global__ void rmsnorm_x_kernel(const float* __restrict__ x,
                                 const float* __restrict__ w) {
    int row = blockIdx.x, tid = threadIdx.x;
    const float4 v = ((const float4*)(x + (size_t)row * DM))[tid];
    const float4 wv = ((const float4*)w)[tid];
    float local = v.x * v.x + v.y * v.y + v.z * v.z + v.w * v.w;
    float tot = blockReduceSum256(local);
    float r = rsqrtf(tot / (float)DM + 1e-5f);
    float u0 = v.x * r * wv.x, u1 = v.y * r * wv.y;
    float u2 = v.z * r * wv.z, u3 = v.w * r * wv.w;
    int o = row * (DM / 2) + tid * 2;
    g_uh[o] = pack_bf16(u0, u1);
    g_uh[o + 1] = pack_bf16(u2, u3);
    g_ul[o] = pack_bf16(u0 - bf16r(u0), u1 - bf16r(u1));
    g_ul[o + 1] = pack_bf16(u2 - bf16r(u2), u3 - bf16r(u3));
}

// ------- tensor-core NT GEMM, preconverted bf16 hi/lo, cp.async 2-stage -------
#define UPS   (4 * 128 * 20)          // u32 per stage
#define GSMEM (2 * UPS * 4)           // bytes
__global__ __launch_bounds__(256) void mma_nt_pre(const uint32_t* __restrict__ Ahg,
                                                  const uint32_t* __restrict__ Alg,
                                                  const uint32_t* __restrict__ Bhg,
                                                  const uint32_t* __restrict__ Blg,
                                                  float* __restrict__ C,
                                                  const float* __restrict__ resid,
                                                  int M, int N, int K, int addRes) {
    extern __shared__ __align__(16) uint32_t S[];
    uint32_t sbase = smem_u32(S);
    int tid = threadIdx.x;
    int warp = tid >> 5, lane = tid & 31;
    int wm = warp & 1, wn = warp >> 1;  // 2 x 4
    int bm = blockIdx.y * 128, bn = blockIdx.x * 128;
    int g = lane >> 2, tg = lane & 3;
    int K2 = K >> 1;

    int lrow = tid >> 1, lhalf = tid & 1;
    const uint32_t* pA[2] = {Ahg + (size_t)(bm + lrow) * K2 + lhalf * 8,
                             Alg + (size_t)(bm + lrow) * K2 + lhalf * 8};
    bool okB = (bn + lrow) < N;
    int brow = okB ? (bn + lrow) : 0;
    const uint32_t* pB[2] = {Bhg + (size_t)brow * K2 + lhalf * 8,
                             Blg + (size_t)brow * K2 + lhalf * 8};
    uint32_t dto = (uint32_t)(lrow * 20 + lhalf * 8) * 4;

    int mat = lane >> 3, mrow = lane & 7;
    uint32_t a_ad[4], b_ad[2];
#pragma unroll
    for (int mt = 0; mt < 4; mt++) {
        int r = wm * 64 + mt * 16 + (mat & 1) * 8 + mrow;
        a_ad[mt] = sbase + (uint32_t)(r * 20 + (mat >> 1) * 4) * 4;
    }
#pragma unroll
    for (int p = 0; p < 2; p++) {
        int n = wn * 32 + p * 16 + (mat >> 1) * 8 + mrow;
        b_ad[p] = sbase + (uint32_t)(n * 20 + (mat & 1) * 4) * 4;
    }

    float acc[4][4][4];
#pragma unroll
    for (int mt = 0; mt < 4; mt++)
#pragma unroll
        for (int nt = 0; nt < 4; nt++)
#pragma unroll
            for (int q = 0; q < 4; q++) acc[mt][nt][q] = 0.f;

    int nslab = K >> 5;

    auto issue = [&](int st, int sl) {
        int ko = sl * 16;
        uint32_t db = sbase + (uint32_t)(st * UPS) * 4 + dto;
#pragma unroll
        for (int t = 0; t < 2; t++) {
            cp16(db + (uint32_t)(t * 2560 * 4), pA[t] + ko, true);
            cp16(db + (uint32_t)(t * 2560 * 4) + 16, pA[t] + ko + 4, true);
            cp16(db + (uint32_t)((2 + t) * 2560 * 4), pB[t] + ko, okB);
            cp16(db + (uint32_t)((2 + t) * 2560 * 4) + 16, pB[t] + ko + 4, okB);
        }
        asm volatile("cp.async.commit_group;" ::: "memory");
    };

    issue(0, 0);
    int st = 0;
    for (int i = 0; i < nslab; i++) {
        if (i + 1 < nslab) {
            issue(st ^ 1, i + 1);
            asm volatile("cp.async.wait_group 1;" ::: "memory");
        } else {
            asm volatile("cp.async.wait_group 0;" ::: "memory");
        }
        __syncthreads();
        uint32_t so = (uint32_t)(st * UPS) * 4;
#pragma unroll
        for (int kk = 0; kk < 2; kk++) {
            uint32_t kb = so + kk * 32;
            uint32_t ahi[4][4], alo[4][4];
#pragma unroll
            for (int mt = 0; mt < 4; mt++) {
                ldsm4(ahi[mt], a_ad[mt] + kb);
                ldsm4(alo[mt], a_ad[mt] + kb + 2560 * 4);
            }
            uint32_t bhi[4][2], blo[4][2];
#pragma unroll
            for (int p = 0; p < 2; p++) {
                uint32_t t4[4];
                ldsm4(t4, b_ad[p] + kb + 2 * 2560 * 4);
                bhi[p * 2][0] = t4[0]; bhi[p * 2][1] = t4[1];
                bhi[p * 2 + 1][0] = t4[2]; bhi[p * 2 + 1][1] = t4[3];
                ldsm4(t4, b_ad[p] + kb + 3 * 2560 * 4);
                blo[p * 2][0] = t4[0]; blo[p * 2][1] = t4[1];
                blo[p * 2 + 1][0] = t4[2]; blo[p * 2 + 1][1] = t4[3];
            }
#pragma unroll
            for (int mt = 0; mt < 4; mt++)
#pragma unroll
                for (int nt = 0; nt < 4; nt++) {
                    mma_bf16(acc[mt][nt], ahi[mt], bhi[nt]);
                    mma_bf16(acc[mt][nt], ahi[mt], blo[nt]);
                    mma_bf16(acc[mt][nt], alo[mt], bhi[nt]);
                }
        }
        __syncthreads();
        st ^= 1;
    }

#pragma unroll
    for (int mt = 0; mt < 4; mt++) {
        int row = bm + wm * 64 + mt * 16 + g;
#pragma unroll
        for (int nt = 0; nt < 4; nt++) {
            int col = bn + wn * 32 + nt * 8 + tg * 2;
            if (col < N) {
                float* a = acc[mt][nt];
                size_t i0 = (size_t)row * N + col;
                size_t i1 = (size_t)(row + 8) * N + col;
                if (addRes) {
                    a[0] += resid[i0]; a[1] += resid[i0 + 1];
                    a[2] += resid[i1]; a[3] += resid[i1 + 1];
                }
                C[i0] = a[0]; C[i0 + 1] = a[1];
                C[i1] = a[2]; C[i1 + 1] = a[3];
            }
        }
    }
}

// ---------------- K3: depthwise causal conv (width 4) + bias + silu ----------
__global__ void conv_silu_kernel(const float* __restrict__ conv_w,
                                 const float* __restrict__ conv_b) {
    int idx = blockIdx.x * blockDim.x + threadIdx.x;
    int c = idx % CONVD;
    int row = idx / CONVD;
    int l = row & (L_ - 1);
    const float* w = conv_w + c * 4;
    float acc = conv_b[c];
#pragma unroll
    for (int j = 0; j < 4; j++) {
        int ls = l - 3 + j;
        if (ls >= 0)
            acc += w[j] * g_zx[(size_t)(row - 3 + j) * DPROJ + DI + c];
    }
    float s = acc / (1.f + __expf(-acc));
    g_xbc[(size_t)row * CONVD + c] = s;
}

// ---------------- K4: dt = softplus(dt_raw + dt_bias) ----------
__global__ void dt_kernel(const float* __restrict__ dt_bias) {
    int idx = blockIdx.x * blockDim.x + threadIdx.x;
    int h = idx & (NH - 1);
    int row = idx >> 5;
    float v = g_zx[(size_t)row * DPROJ + (DI + CONVD) + h] + dt_bias[h];
    float sp = (v > 20.f) ? v : log1pf(__expf(v));
    g_dt[row * NH + h] = sp;
}

// ---------------- K5: per-chunk cumsum of a = dt * A ----------
__global__ void acs_kernel(const float* __restrict__ A_log) {
    int bid = blockIdx.x;
    int b = bid >> 8, h = (bid >> 3) & 31, c = bid & 7;
    int l = threadIdx.x;
    int row = b * L_ + c * CH + l;
    float A = -__expf(A_log[h]);
    __shared__ float s[CH];
    s[l] = g_dt[row * NH + h] * A;
    __syncthreads();
#pragma unroll
    for (int off = 1; off < CH; off <<= 1) {
        float v = (l >= off) ? s[l - off] : 0.f;
        __syncthreads();
        s[l] += v;
        __syncthreads();
    }
    g_acs[bid * CH + l] = s[l];
}

// ---------------- K6: per-chunk states[p,n] = sum_l decay*xd[l,p]*B[l,n] -----
__global__ __launch_bounds__(256) void states_kernel() {
    int bid = blockIdx.x;
    int b = bid >> 8, c = (bid >> 5) & 7, h = bid & 31;
    int tid = threadIdx.x;
    int tx = tid & 15, ty = tid >> 4;
    __shared__ float xdw[16][64];
    __shared__ float bs[16][128];
    __shared__ float coef[16];
    int base = ((b * NH + h) * NCH + c) * CH;
    float acs_last = g_acs[base + CH - 1];
    int rowbase = b * L_ + c * CH;

    float acc[4][8];
#pragma unroll
    for (int i = 0; i < 4; i++)
#pragma unroll
        for (int j = 0; j < 8; j++) acc[i][j] = 0.f;

    for (int l0 = 0; l0 < CH; l0 += 16) {
        __syncthreads();
        if (tid < 16) {
            int row = rowbase + l0 + tid;
            coef[tid] = g_dt[row * NH + h] * __expf(acs_last - g_acs[base + l0 + tid]);
        }
        __syncthreads();
#pragma unroll
        for (int e = tid; e < 16 * 64; e += 256) {
            int ll = e >> 6, p = e & 63;
            int row = rowbase + l0 + ll;
            xdw[ll][p] = g_xbc[(size_t)row * CONVD + h * HD + p] * coef[ll];
        }
#pragma unroll
        for (int e = tid; e < 16 * 128; e += 256) {
            int ll = e >> 7, n = e & 127;
            int row = rowbase + l0 + ll;
            bs[ll][n] = g_xbc[(size_t)row * CONVD + DI + n];
        }
        __syncthreads();
#pragma unroll
        for (int ll = 0; ll < 16; ll++) {
            float4 a4 = *(const float4*)&xdw[ll][ty * 4];
            float4 b0 = *(const float4*)&bs[ll][tx * 8];
            float4 b1 = *(const float4*)&bs[ll][tx * 8 + 4];
            float a[4] = {a4.x, a4.y, a4.z, a4.w};
            float bb[8] = {b0.x, b0.y, b0.z, b0.w, b1.x, b1.y, b1.z, b1.w};
#pragma unroll
            for (int i = 0; i < 4; i++)
#pragma unroll
                for (int j = 0; j < 8; j++) acc[i][j] += a[i] * bb[j];
        }
    }
    size_t out = (size_t)bid * HD * DS;
#pragma unroll
    for (int i = 0; i < 4; i++)
#pragma unroll
        for (int j = 0; j < 8; j++)
            g_states[out + (size_t)(ty * 4 + i) * DS + tx * 8 + j] = acc[i][j];
}

// ---------------- K7: chunk recurrence (serial over 8 chunks) ----------
__global__ void recur_kernel() {
    int idx = blockIdx.x * blockDim.x + threadIdx.x;
    int n = idx & 127;
    int p = (idx >> 7) & 63;
    int h = (idx >> 13) & 31;
    int b = idx >> 18;
    float run = 0.f;
#pragma unroll
    for (int c = 0; c < NCH; c++) {
        size_t sidx = ((size_t)((b * NCH + c) * NH + h) * HD + p) * DS + n;
        g_init[sidx] = run;
        float cs = g_acs[((b * NH + h) * NCH + c) * CH + CH - 1];
        run = run * __expf(cs) + g_states[sidx];
    }
}

// ---------------- K8: CB[l,s] = Cm[l]·Bm[s] per (b,c) ----------
__global__ __launch_bounds__(256) void cb_kernel() {
    int z = blockIdx.z;
    int b = z >> 3, c = z & 7;
    int l0 = blockIdx.y * 64, s0 = blockIdx.x * 64;
    int tid = threadIdx.x;
    int tx = tid & 15, ty = tid >> 4;
    __shared__ float ct[16][64];
    __shared__ float bt[16][64];
    int rowbase = b * L_ + c * CH;
    float acc[4][4];
#pragma unroll
    for (int i = 0; i < 4; i++)
#pragma unroll
        for (int j = 0; j < 4; j++) acc[i][j] = 0.f;

    for (int k0 = 0; k0 < DS; k0 += 16) {
        __syncthreads();
#pragma unroll
        for (int e = tid; e < 1024; e += 256) {
            int kk = e & 15, i = e >> 4;
            ct[kk][i] = g_xbc[(size_t)(rowbase + l0 + i) * CONVD + DI + DS + k0 + kk];
            bt[kk][i] = g_xbc[(size_t)(rowbase + s0 + i) * CONVD + DI + k0 + kk];
        }
        __syncthreads();
#pragma unroll
        for (int kk = 0; kk < 16; kk++) {
            float4 a4 = *(const float4*)&ct[kk][ty * 4];
            float4 b4 = *(const float4*)&bt[kk][tx * 4];
            float a[4] = {a4.x, a4.y, a4.z, a4.w};
            float bb[4] = {b4.x, b4.y, b4.z, b4.w};
#pragma unroll
            for (int i = 0; i < 4; i++)
#pragma unroll
                for (int j = 0; j < 4; j++) acc[i][j] += a[i] * bb[j];
        }
    }
#pragma unroll
    for (int i = 0; i < 4; i++)
#pragma unroll
        for (int j = 0; j < 4; j++)
            g_cb[((size_t)z * CH + l0 + ty * 4 + i) * CH + s0 + tx * 4 + j] = acc[i][j];
}

// ------ K9 (tensorized): Y[256,64] = exp(acs)*(Cm@init^T) + (CB·L)@xd + D*xh --
// per (b,c,h) block, 256 threads = 8 warps (4 M x 2 N), warp tile 64x32.
// smem rows stride 20 u32; A: 256 rows, B: 64 rows; bf16 hi/lo, 3-term mma.
#define YW 20
#define YA_H 0
#define YA_L (256 * YW)
#define YB_H (2 * 256 * YW)
#define YB_L (2 * 256 * YW + 64 * YW)
#define YACS (2 * 256 * YW + 2 * 64 * YW)
#define YSMEM ((YACS + 256) * 4)
__global__ __launch_bounds__(256) void y_tc_kernel(const float* __restrict__ Dvec) {
    extern __shared__ __align__(16) uint32_t S[];
    uint32_t* Ah = S + YA_H;
    uint32_t* Al = S + YA_L;
    uint32_t* Bh = S + YB_H;
    uint32_t* Bl = S + YB_L;
    float* acs_s = (float*)(S + YACS);
    uint32_t sb = smem_u32(S);

    int bid = blockIdx.x;  // (b*NCH + c)*NH + h
    int b = bid >> 8, c = (bid >> 5) & 7, h = bid & 31;
    int z = b * NCH + c;
    int tid = threadIdx.x, warp = tid >> 5, lane = tid & 31;
    int wm = warp & 3, wn = warp >> 2;  // 4 M-warps x 2 N-warps
    int g = lane >> 2, tg = lane & 3;
    int base = ((b * NH + h) * NCH + c) * CH;
    acs_s[tid] = g_acs[base + tid];
    int rowbase = b * L_ + c * CH;
    size_t initbase = (size_t)bid * HD * DS;

    // ldmatrix addresses
    int mat = lane >> 3, mrow = lane & 7;
    uint32_t a_adh[4], a_adl[4], b_adh[2], b_adl[2];
#pragma unroll
    for (int mt = 0; mt < 4; mt++) {
        int r = wm * 64 + mt * 16 + (mat & 1) * 8 + mrow;
        uint32_t off = (uint32_t)(r * YW + (mat >> 1) * 4) * 4;
        a_adh[mt] = sb + YA_H * 4 + off;
        a_adl[mt] = sb + YA_L * 4 + off;
    }
#pragma unroll
    for (int p = 0; p < 2; p++) {
        int n = wn * 32 + p * 16 + (mat >> 1) * 8 + mrow;
        uint32_t off = (uint32_t)(n * YW + (mat & 1) * 4) * 4;
        b_adh[p] = sb + YB_H * 4 + off;
        b_adl[p] = sb + YB_L * 4 + off;
    }

    float acc[4][4][4];
#pragma unroll
    for (int mt = 0; mt < 4; mt++)
#pragma unroll
        for (int nt = 0; nt < 4; nt++)
#pragma unroll
            for (int q = 0; q < 4; q++) acc[mt][nt][q] = 0.f;

    auto do_mma = [&](void) {
#pragma unroll
        for (int kk = 0; kk < 2; kk++) {
            uint32_t kb = kk * 32;
            uint32_t ahi[4][4], alo[4][4];
#pragma unroll
            for (int mt = 0; mt < 4; mt++) {
                ldsm4(ahi[mt], a_adh[mt] + kb);
                ldsm4(alo[mt], a_adl[mt] + kb);
            }
            uint32_t bhi[4][2], blo[4][2];
#pragma unroll
            for (int p = 0; p < 2; p++) {
                uint32_t t4[4];
                ldsm4(t4, b_adh[p] + kb);
                bhi[p * 2][0] = t4[0]; bhi[p * 2][1] = t4[1];
                bhi[p * 2 + 1][0] = t4[2]; bhi[p * 2 + 1][1] = t4[3];
                ldsm4(t4, b_adl[p] + kb);
                blo[p * 2][0] = t4[0]; blo[p * 2][1] = t4[1];
                blo[p * 2 + 1][0] = t4[2]; blo[p * 2 + 1][1] = t4[3];
            }
#pragma unroll
            for (int mt = 0; mt < 4; mt++)
#pragma unroll
                for (int nt = 0; nt < 4; nt++) {
                    mma_bf16(acc[mt][nt], ahi[mt], bhi[nt]);
                    mma_bf16(acc[mt][nt], ahi[mt], blo[nt]);
                    mma_bf16(acc[mt][nt], alo[mt], bhi[nt]);
                }
        }
    };

    // ---------------- Phase 1: Cm @ init^T, K = DS = 128 (4 slabs) ----------
    for (int ks = 0; ks < 4; ks++) {
        __syncthreads();
        {   // A: row l = tid, 32 floats of Cm
            const float* cm = &g_xbc[(size_t)(rowbase + tid) * CONVD + DI + DS + ks * 32];
            uint32_t* dah = &Ah[tid * YW];
            uint32_t* dal = &Al[tid * YW];
#pragma unroll
            for (int j2 = 0; j2 < 16; j2++) {
                float2 v = ((const float2*)cm)[j2];
                dah[j2] = pack_bf16(v.x, v.y);
                dal[j2] = pack_bf16(v.x - bf16r(v.x), v.y - bf16r(v.y));
            }
        }
        {   // B: row p = tid>>2, 4 u32 at (tid&3)*4
            int p = tid >> 2, q0 = tid & 3;
            const float* ir = &g_init[initbase + (size_t)p * DS + ks * 32 + q0 * 8];
            uint32_t* dbh = &Bh[p * YW + q0 * 4];
            uint32_t* dbl = &Bl[p * YW + q0 * 4];
#pragma unroll
            for (int q = 0; q < 4; q++) {
                float2 v = ((const float2*)ir)[q];
                dbh[q] = pack_bf16(v.x, v.y);
                dbl[q] = pack_bf16(v.x - bf16r(v.x), v.y - bf16r(v.y));
            }
        }
        __syncthreads();
        do_mma();
    }

    // scale by exp(acs[l])
#pragma unroll
    for (int mt = 0; mt < 4; mt++) {
        int r0 = wm * 64 + mt * 16 + g;
        float e0 = __expf(acs_s[r0]);
        float e1 = __expf(acs_s[r0 + 8]);
#pragma unroll
        for (int nt = 0; nt < 4; nt++) {
            acc[mt][nt][0] *= e0; acc[mt][nt][1] *= e0;
            acc[mt][nt][2] *= e1; acc[mt][nt][3] *= e1;
        }
    }

    // ---------------- Phase 2: (CB ∘ L) @ xd^T, K = CH = 256 (8 slabs) -------
    int wlast = wm * 64 + 63;  // last row this warp owns
    for (int ss = 0; ss < 8; ss++) {
        int s0 = ss * 32;
        __syncthreads();
        {   // A: row l = tid, masked decayed CB
            int l = tid;
            float al = acs_s[l];
            const float* cbr = &g_cb[((size_t)z * CH + l) * CH + s0];
            uint32_t* dah = &Ah[l * YW];
            uint32_t* dal = &Al[l * YW];
#pragma unroll
            for (int j2 = 0; j2 < 16; j2++) {
                int s = s0 + 2 * j2;
                float va = (s <= l) ? cbr[2 * j2] * __expf(al - acs_s[s]) : 0.f;
                float vb = (s + 1 <= l) ? cbr[2 * j2 + 1] * __expf(al - acs_s[s + 1]) : 0.f;
                dah[j2] = pack_bf16(va, vb);
                dal[j2] = pack_bf16(va - bf16r(va), vb - bf16r(vb));
            }
        }
        {   // B transpose: warp w handles p-group w (8 p), lane = s offset
            int s = s0 + lane;
            int row = rowbase + s;
            float dtv = g_dt[row * NH + h];
            const float* xr = &g_xbc[(size_t)row * CONVD + h * HD + warp * 8];
            __nv_bfloat16* BhH = (__nv_bfloat16*)Bh;
            __nv_bfloat16* BlH = (__nv_bfloat16*)Bl;
#pragma unroll
            for (int q = 0; q < 8; q++) {
                int p = warp * 8 + q;
                float v = xr[q] * dtv;
                float hv = bf16r(v);
                BhH[p * (2 * YW) + lane] = __float2bfloat16(v);
                BlH[p * (2 * YW) + lane] = __float2bfloat16(v - hv);
            }
        }
        __syncthreads();
        if (s0 <= wlast) do_mma();
    }

    // epilogue: + D*xh, write y (fp32)
    float Dh = Dvec[h];
#pragma unroll
    for (int mt = 0; mt < 4; mt++) {
        int r = wm * 64 + mt * 16 + g;
#pragma unroll
        for (int nt = 0; nt < 4; nt++) {
            int p = wn * 32 + nt * 8 + tg * 2;
            float* a = acc[mt][nt];
#pragma unroll
            for (int q = 0; q < 4; q++) {
                int row = rowbase + r + (q >> 1) * 8;
                int pp = p + (q & 1);
                float xh = g_xbc[(size_t)row * CONVD + h * HD + pp];
                g_y[(size_t)row * DI + h * HD + pp] = a[q] + Dh * xh;
            }
        }
    }
}

// -------- K10: gated rmsnorm: y = rmsnorm(y*silu(z))*gw -> bf16 hi/lo --------
__global__ void gated_norm_kernel(const float* __restrict__ gw) {
    int row = blockIdx.x, tid = threadIdx.x;
    int d0 = tid * 8;
    const float* zr = &g_zx[(size_t)row * DPROJ + d0];
    const float* yr = &g_y[(size_t)row * DI + d0];
    float v[8];
    float local = 0.f;
#pragma unroll
    for (int q = 0; q < 2; q++) {
        float4 z4 = *(const float4*)(zr + q * 4);
        float4 y4 = *(const float4*)(yr + q * 4);
        float zz[4] = {z4.x, z4.y, z4.z, z4.w};
        float yy[4] = {y4.x, y4.y, y4.z, y4.w};
#pragma unroll
        for (int j = 0; j < 4; j++) {
            float t = yy[j] * (zz[j] / (1.f + __expf(-zz[j])));
            v[q * 4 + j] = t;
            local += t * t;
        }
    }
    float tot = blockReduceSum256(local);
    float r = rsqrtf(tot / (float)DI + 1e-5f);
    int o = row * (DI / 2) + tid * 4;
#pragma unroll
    for (int j = 0; j < 4; j++) {
        float a = v[2 * j] * r * gw[d0 + 2 * j];
        float b = v[2 * j + 1] * r * gw[d0 + 2 * j + 1];
        g_yh[o + j] = pack_bf16(a, b);
        g_yl[o + j] = pack_bf16(a - bf16r(a), b - bf16r(b));
    }
}

// ---------------- launch ----------------
extern "C" void kernel_launch(void* const* d_in, const int* in_sizes, int n_in,
                              void* d_out, int out_size) {
    const float* x         = (const float*)d_in[0];
    const float* norm_w    = (const float*)d_in[1];
    const float* in_proj_w = (const float*)d_in[2];
    const float* conv_w    = (const float*)d_in[3];
    const float* conv_b    = (const float*)d_in[4];
    const float* dt_bias   = (const float*)d_in[5];
    const float* A_log     = (const float*)d_in[6];
    const float* Dv        = (const float*)d_in[7];
    const float* gnorm_w   = (const float*)d_in[8];
    const float* out_proj_w= (const float*)d_in[9];
    float* out = (float*)d_out;

    float *pzx;
    uint32_t *puh, *pul, *pyh, *pyl, *pwih, *pwil, *pwoh, *pwol;
    cudaGetSymbolAddress((void**)&pzx, g_zx);
    cudaGetSymbolAddress((void**)&puh, g_uh);
    cudaGetSymbolAddress((void**)&pul, g_ul);
    cudaGetSymbolAddress((void**)&pyh, g_yh);
    cudaGetSymbolAddress((void**)&pyl, g_yl);
    cudaGetSymbolAddress((void**)&pwih, g_wih);
    cudaGetSymbolAddress((void**)&pwil, g_wil);
    cudaGetSymbolAddress((void**)&pwoh, g_woh);
    cudaGetSymbolAddress((void**)&pwol, g_wol);

    cudaFuncSetAttribute(mma_nt_pre, cudaFuncAttributeMaxDynamicSharedMemorySize, GSMEM);
    cudaFuncSetAttribute(y_tc_kernel, cudaFuncAttributeMaxDynamicSharedMemorySize, YSMEM);

    cvt_pairs_kernel<<<(DPROJ * DM / 2 + 255) / 256, 256>>>(in_proj_w, pwih, pwil,
                                                            DPROJ * DM / 2);
    cvt_pairs_kernel<<<(DM * DI / 2 + 255) / 256, 256>>>(out_proj_w, pwoh, pwol,
                                                         DM * DI / 2);

    rmsnorm_x_kernel<<<ROWS, 256>>>(x, norm_w);
    mma_nt_pre<<<dim3((DPROJ + 127) / 128, ROWS / 128), 256, GSMEM>>>(
        puh, pul, pwih, pwil, pzx, nullptr, ROWS, DPROJ, DM, 0);
    conv_silu_kernel<<<(ROWS * CONVD) / 256, 256>>>(conv_w, conv_b);
    dt_kernel<<<(ROWS * NH) / 256, 256>>>(dt_bias);
    acs_kernel<<<B_ * NH * NCH, 256>>>(A_log);
    states_kernel<<<B_ * NCH * NH, 256>>>();
    recur_kernel<<<(B_ * NH * HD * DS) / 256, 256>>>();
    cb_kernel<<<dim3(4, 4, B_ * NCH), 256>>>();
    y_tc_kernel<<<B_ * NCH * NH, 256, YSMEM>>>(Dv);
    gated_norm_kernel<<<ROWS, 256>>>(gnorm_w);
    mma_nt_pre<<<dim3(DM / 128, ROWS / 128), 256, GSMEM>>>(
        pyh, pyl, pwoh, pwol, out, x, ROWS, DM, DI, 1);
}

// round 8
// speedup vs baseline: 2.1322x; 1.0086x over previous
#include <cuda_runtime.h>
#include <cuda_bf16.h>
#include <math.h>
#include <stdint.h>

// ---------------- problem constants ----------------
#define B_    2
#define L_    2048
#define DM    1024          // d_model
#define DI    2048          // d_inner
#define NH    32            // nheads
#define HD    64            // headdim
#define DS    128           // d_state
#define CONVD 2304          // conv dim = DI + 2*DS
#define DPROJ 4384          // 2*DI + 2*DS + NH
#define NCH   8             // chunks per batch
#define CH    256           // chunk length
#define ROWS  4096          // B_*L_

// ---------------- scratch (device globals; no allocation allowed) ----------------
__device__ float g_zx[(size_t)ROWS * DPROJ];        // in_proj output
__device__ float g_xbc[(size_t)ROWS * CONVD];       // conv+silu output
__device__ float g_dt[ROWS * NH];                   // softplus(dt)
__device__ float g_acs[B_ * NH * NCH * CH];         // cumsum(dt*A) per chunk
__device__ float g_states[(size_t)B_ * NCH * NH * HD * DS];
__device__ float g_init[(size_t)B_ * NCH * NH * HD * DS];
__device__ float g_cb[(size_t)B_ * NCH * CH * CH];  // Cm @ Bm^T per chunk
__device__ float g_y[(size_t)ROWS * DI];            // y (pre gated-norm)

// packed bf16x2 hi/lo operand arrays
__device__ uint32_t g_uh[ROWS * DM / 2];            // rmsnorm(x) hi
__device__ uint32_t g_ul[ROWS * DM / 2];            // rmsnorm(x) lo
__device__ uint32_t g_yh[(size_t)ROWS * DI / 2];    // gated-norm(y) hi
__device__ uint32_t g_yl[(size_t)ROWS * DI / 2];    // gated-norm(y) lo
__device__ uint32_t g_wih[(size_t)DPROJ * DM / 2];  // in_proj_w hi
__device__ uint32_t g_wil[(size_t)DPROJ * DM / 2];  // in_proj_w lo
__device__ uint32_t g_woh[(size_t)DM * DI / 2];     // out_proj_w hi
__device__ uint32_t g_wol[(size_t)DM * DI / 2];     // out_proj_w lo

// ---------------- helpers ----------------
__device__ __forceinline__ float blockReduceSum256(float v) {
    __shared__ float ws[8];
    __shared__ float tot;
    int lane = threadIdx.x & 31, wid = threadIdx.x >> 5;
#pragma unroll
    for (int o = 16; o; o >>= 1) v += __shfl_xor_sync(0xffffffffu, v, o);
    if (lane == 0) ws[wid] = v;
    __syncthreads();
    if (threadIdx.x == 0) {
        float s = 0.f;
#pragma unroll
        for (int i = 0; i < 8; i++) s += ws[i];
        tot = s;
    }
    __syncthreads();
    return tot;
}

__device__ __forceinline__ uint32_t pack_bf16(float a, float b) {
    __nv_bfloat162 h = __floats2bfloat162_rn(a, b);
    return *(uint32_t*)&h;
}

__device__ __forceinline__ float bf16r(float v) {
    return __bfloat162float(__float2bfloat16(v));
}

__device__ __forceinline__ uint32_t smem_u32(const void* p) {
    uint32_t a;
    asm("{ .reg .u64 t; cvta.to.shared.u64 t, %1; cvt.u32.u64 %0, t; }"
        : "=r"(a) : "l"(p));
    return a;
}

// m16n8k16 row.col bf16 MMA, fp32 accumulate
__device__ __forceinline__ void mma_bf16(float* d, const uint32_t* a, const uint32_t* b) {
    asm volatile(
        "mma.sync.aligned.m16n8k16.row.col.f32.bf16.bf16.f32 "
        "{%0,%1,%2,%3}, {%4,%5,%6,%7}, {%8,%9}, {%0,%1,%2,%3};"
        : "+f"(d[0]), "+f"(d[1]), "+f"(d[2]), "+f"(d[3])
        : "r"(a[0]), "r"(a[1]), "r"(a[2]), "r"(a[3]), "r"(b[0]), "r"(b[1]));
}

__device__ __forceinline__ void ldsm4(uint32_t* r, uint32_t addr) {
    asm volatile("ldmatrix.sync.aligned.m8n8.x4.shared.b16 {%0,%1,%2,%3}, [%4];"
                 : "=r"(r[0]), "=r"(r[1]), "=r"(r[2]), "=r"(r[3]) : "r"(addr));
}

__device__ __forceinline__ void cp16(uint32_t dst, const void* src, bool ok) {
    if (ok)
        asm volatile("cp.async.cg.shared.global [%0], [%1], 16;"
                     :: "r"(dst), "l"(src) : "memory");
    else
        asm volatile("cp.async.cg.shared.global [%0], [%1], 16, 0;"
                     :: "r"(dst), "l"(src) : "memory");
}

// ---------------- K0: split fp32 pairs -> bf16 hi/lo packed ----------
__global__ void cvt_pairs_kernel(const float* __restrict__ W,
                                 uint32_t* __restrict__ Wh,
                                 uint32_t* __restrict__ Wl, int npairs) {
    int i = blockIdx.x * blockDim.x + threadIdx.x;
    if (i < npairs) {
        float2 v = ((const float2*)W)[i];
        Wh[i] = pack_bf16(v.x, v.y);
        Wl[i] = pack_bf16(v.x - bf16r(v.x), v.y - bf16r(v.y));
    }
}

// ---------------- K1: rmsnorm(x) -> bf16 hi/lo ----------------
__global__ void rmsnorm_x_kernel(const float* __restrict__ x,
                                 const float* __restrict__ w) {
    int row = blockIdx.x, tid = threadIdx.x;
    const float4 v = ((const float4*)(x + (size_t)row * DM))[tid];
    const float4 wv = ((const float4*)w)[tid];
    float local = v.x * v.x + v.y * v.y + v.z * v.z + v.w * v.w;
    float tot = blockReduceSum256(local);
    float r = rsqrtf(tot / (float)DM + 1e-5f);
    float u0 = v.x * r * wv.x, u1 = v.y * r * wv.y;
    float u2 = v.z * r * wv.z, u3 = v.w * r * wv.w;
    int o = row * (DM / 2) + tid * 2;
    g_uh[o] = pack_bf16(u0, u1);
    g_uh[o + 1] = pack_bf16(u2, u3);
    g_ul[o] = pack_bf16(u0 - bf16r(u0), u1 - bf16r(u1));
    g_ul[o + 1] = pack_bf16(u2 - bf16r(u2), u3 - bf16r(u3));
}

// ------- tensor-core NT GEMM, preconverted bf16 hi/lo, cp.async 2-stage -------
#define UPS   (4 * 128 * 20)          // u32 per stage
#define GSMEM (2 * UPS * 4)           // bytes
__global__ __launch_bounds__(256) void mma_nt_pre(const uint32_t* __restrict__ Ahg,
                                                  const uint32_t* __restrict__ Alg,
                                                  const uint32_t* __restrict__ Bhg,
                                                  const uint32_t* __restrict__ Blg,
                                                  float* __restrict__ C,
                                                  const float* __restrict__ resid,
                                                  int M, int N, int K, int addRes) {
    extern __shared__ __align__(16) uint32_t S[];
    uint32_t sbase = smem_u32(S);
    int tid = threadIdx.x;
    int warp = tid >> 5, lane = tid & 31;
    int wm = warp & 1, wn = warp >> 1;  // 2 x 4
    int bm = blockIdx.y * 128, bn = blockIdx.x * 128;
    int g = lane >> 2, tg = lane & 3;
    int K2 = K >> 1;

    int lrow = tid >> 1, lhalf = tid & 1;
    const uint32_t* pA[2] = {Ahg + (size_t)(bm + lrow) * K2 + lhalf * 8,
                             Alg + (size_t)(bm + lrow) * K2 + lhalf * 8};
    bool okB = (bn + lrow) < N;
    int brow = okB ? (bn + lrow) : 0;
    const uint32_t* pB[2] = {Bhg + (size_t)brow * K2 + lhalf * 8,
                             Blg + (size_t)brow * K2 + lhalf * 8};
    uint32_t dto = (uint32_t)(lrow * 20 + lhalf * 8) * 4;

    int mat = lane >> 3, mrow = lane & 7;
    uint32_t a_ad[4], b_ad[2];
#pragma unroll
    for (int mt = 0; mt < 4; mt++) {
        int r = wm * 64 + mt * 16 + (mat & 1) * 8 + mrow;
        a_ad[mt] = sbase + (uint32_t)(r * 20 + (mat >> 1) * 4) * 4;
    }
#pragma unroll
    for (int p = 0; p < 2; p++) {
        int n = wn * 32 + p * 16 + (mat >> 1) * 8 + mrow;
        b_ad[p] = sbase + (uint32_t)(n * 20 + (mat & 1) * 4) * 4;
    }

    float acc[4][4][4];
#pragma unroll
    for (int mt = 0; mt < 4; mt++)
#pragma unroll
        for (int nt = 0; nt < 4; nt++)
#pragma unroll
            for (int q = 0; q < 4; q++) acc[mt][nt][q] = 0.f;

    int nslab = K >> 5;

    auto issue = [&](int st, int sl) {
        int ko = sl * 16;
        uint32_t db = sbase + (uint32_t)(st * UPS) * 4 + dto;
#pragma unroll
        for (int t = 0; t < 2; t++) {
            cp16(db + (uint32_t)(t * 2560 * 4), pA[t] + ko, true);
            cp16(db + (uint32_t)(t * 2560 * 4) + 16, pA[t] + ko + 4, true);
            cp16(db + (uint32_t)((2 + t) * 2560 * 4), pB[t] + ko, okB);
            cp16(db + (uint32_t)((2 + t) * 2560 * 4) + 16, pB[t] + ko + 4, okB);
        }
        asm volatile("cp.async.commit_group;" ::: "memory");
    };

    issue(0, 0);
    int st = 0;
    for (int i = 0; i < nslab; i++) {
        if (i + 1 < nslab) {
            issue(st ^ 1, i + 1);
            asm volatile("cp.async.wait_group 1;" ::: "memory");
        } else {
            asm volatile("cp.async.wait_group 0;" ::: "memory");
        }
        __syncthreads();
        uint32_t so = (uint32_t)(st * UPS) * 4;
#pragma unroll
        for (int kk = 0; kk < 2; kk++) {
            uint32_t kb = so + kk * 32;
            uint32_t ahi[4][4], alo[4][4];
#pragma unroll
            for (int mt = 0; mt < 4; mt++) {
                ldsm4(ahi[mt], a_ad[mt] + kb);
                ldsm4(alo[mt], a_ad[mt] + kb + 2560 * 4);
            }
            uint32_t bhi[4][2], blo[4][2];
#pragma unroll
            for (int p = 0; p < 2; p++) {
                uint32_t t4[4];
                ldsm4(t4, b_ad[p] + kb + 2 * 2560 * 4);
                bhi[p * 2][0] = t4[0]; bhi[p * 2][1] = t4[1];
                bhi[p * 2 + 1][0] = t4[2]; bhi[p * 2 + 1][1] = t4[3];
                ldsm4(t4, b_ad[p] + kb + 3 * 2560 * 4);
                blo[p * 2][0] = t4[0]; blo[p * 2][1] = t4[1];
                blo[p * 2 + 1][0] = t4[2]; blo[p * 2 + 1][1] = t4[3];
            }
#pragma unroll
            for (int mt = 0; mt < 4; mt++)
#pragma unroll
                for (int nt = 0; nt < 4; nt++) {
                    mma_bf16(acc[mt][nt], ahi[mt], bhi[nt]);
                    mma_bf16(acc[mt][nt], ahi[mt], blo[nt]);
                    mma_bf16(acc[mt][nt], alo[mt], bhi[nt]);
                }
        }
        __syncthreads();
        st ^= 1;
    }

#pragma unroll
    for (int mt = 0; mt < 4; mt++) {
        int row = bm + wm * 64 + mt * 16 + g;
#pragma unroll
        for (int nt = 0; nt < 4; nt++) {
            int col = bn + wn * 32 + nt * 8 + tg * 2;
            if (col < N) {
                float* a = acc[mt][nt];
                size_t i0 = (size_t)row * N + col;
                size_t i1 = (size_t)(row + 8) * N + col;
                if (addRes) {
                    a[0] += resid[i0]; a[1] += resid[i0 + 1];
                    a[2] += resid[i1]; a[3] += resid[i1 + 1];
                }
                C[i0] = a[0]; C[i0 + 1] = a[1];
                C[i1] = a[2]; C[i1 + 1] = a[3];
            }
        }
    }
}

// ---------------- K3: depthwise causal conv (width 4) + bias + silu ----------
__global__ void conv_silu_kernel(const float* __restrict__ conv_w,
                                 const float* __restrict__ conv_b) {
    int idx = blockIdx.x * blockDim.x + threadIdx.x;
    int c = idx % CONVD;
    int row = idx / CONVD;
    int l = row & (L_ - 1);
    const float* w = conv_w + c * 4;
    float acc = conv_b[c];
#pragma unroll
    for (int j = 0; j < 4; j++) {
        int ls = l - 3 + j;
        if (ls >= 0)
            acc += w[j] * g_zx[(size_t)(row - 3 + j) * DPROJ + DI + c];
    }
    float s = acc / (1.f + __expf(-acc));
    g_xbc[(size_t)row * CONVD + c] = s;
}

// ---------------- K4: dt = softplus(dt_raw + dt_bias) ----------
__global__ void dt_kernel(const float* __restrict__ dt_bias) {
    int idx = blockIdx.x * blockDim.x + threadIdx.x;
    int h = idx & (NH - 1);
    int row = idx >> 5;
    float v = g_zx[(size_t)row * DPROJ + (DI + CONVD) + h] + dt_bias[h];
    float sp = (v > 20.f) ? v : log1pf(__expf(v));
    g_dt[row * NH + h] = sp;
}

// ---------------- K5: per-chunk cumsum of a = dt * A ----------
__global__ void acs_kernel(const float* __restrict__ A_log) {
    int bid = blockIdx.x;
    int b = bid >> 8, h = (bid >> 3) & 31, c = bid & 7;
    int l = threadIdx.x;
    int row = b * L_ + c * CH + l;
    float A = -__expf(A_log[h]);
    __shared__ float s[CH];
    s[l] = g_dt[row * NH + h] * A;
    __syncthreads();
#pragma unroll
    for (int off = 1; off < CH; off <<= 1) {
        float v = (l >= off) ? s[l - off] : 0.f;
        __syncthreads();
        s[l] += v;
        __syncthreads();
    }
    g_acs[bid * CH + l] = s[l];
}

// ---------------- K6: per-chunk states[p,n] = sum_l decay*xd[l,p]*B[l,n] -----
__global__ __launch_bounds__(256) void states_kernel() {
    int bid = blockIdx.x;
    int b = bid >> 8, c = (bid >> 5) & 7, h = bid & 31;
    int tid = threadIdx.x;
    int tx = tid & 15, ty = tid >> 4;
    __shared__ float xdw[16][64];
    __shared__ float bs[16][128];
    __shared__ float coef[16];
    int base = ((b * NH + h) * NCH + c) * CH;
    float acs_last = g_acs[base + CH - 1];
    int rowbase = b * L_ + c * CH;

    float acc[4][8];
#pragma unroll
    for (int i = 0; i < 4; i++)
#pragma unroll
        for (int j = 0; j < 8; j++) acc[i][j] = 0.f;

    for (int l0 = 0; l0 < CH; l0 += 16) {
        __syncthreads();
        if (tid < 16) {
            int row = rowbase + l0 + tid;
            coef[tid] = g_dt[row * NH + h] * __expf(acs_last - g_acs[base + l0 + tid]);
        }
        __syncthreads();
#pragma unroll
        for (int e = tid; e < 16 * 64; e += 256) {
            int ll = e >> 6, p = e & 63;
            int row = rowbase + l0 + ll;
            xdw[ll][p] = g_xbc[(size_t)row * CONVD + h * HD + p] * coef[ll];
        }
#pragma unroll
        for (int e = tid; e < 16 * 128; e += 256) {
            int ll = e >> 7, n = e & 127;
            int row = rowbase + l0 + ll;
            bs[ll][n] = g_xbc[(size_t)row * CONVD + DI + n];
        }
        __syncthreads();
#pragma unroll
        for (int ll = 0; ll < 16; ll++) {
            float4 a4 = *(const float4*)&xdw[ll][ty * 4];
            float4 b0 = *(const float4*)&bs[ll][tx * 8];
            float4 b1 = *(const float4*)&bs[ll][tx * 8 + 4];
            float a[4] = {a4.x, a4.y, a4.z, a4.w};
            float bb[8] = {b0.x, b0.y, b0.z, b0.w, b1.x, b1.y, b1.z, b1.w};
#pragma unroll
            for (int i = 0; i < 4; i++)
#pragma unroll
                for (int j = 0; j < 8; j++) acc[i][j] += a[i] * bb[j];
        }
    }
    size_t out = (size_t)bid * HD * DS;
#pragma unroll
    for (int i = 0; i < 4; i++)
#pragma unroll
        for (int j = 0; j < 8; j++)
            g_states[out + (size_t)(ty * 4 + i) * DS + tx * 8 + j] = acc[i][j];
}

// ---------------- K7: chunk recurrence (serial over 8 chunks) ----------
__global__ void recur_kernel() {
    int idx = blockIdx.x * blockDim.x + threadIdx.x;
    int n = idx & 127;
    int p = (idx >> 7) & 63;
    int h = (idx >> 13) & 31;
    int b = idx >> 18;
    float run = 0.f;
#pragma unroll
    for (int c = 0; c < NCH; c++) {
        size_t sidx = ((size_t)((b * NCH + c) * NH + h) * HD + p) * DS + n;
        g_init[sidx] = run;
        float cs = g_acs[((b * NH + h) * NCH + c) * CH + CH - 1];
        run = run * __expf(cs) + g_states[sidx];
    }
}

// ---------------- K8: CB[l,s] = Cm[l]·Bm[s] per (b,c) ----------
__global__ __launch_bounds__(256) void cb_kernel() {
    int z = blockIdx.z;
    int b = z >> 3, c = z & 7;
    int l0 = blockIdx.y * 64, s0 = blockIdx.x * 64;
    int tid = threadIdx.x;
    int tx = tid & 15, ty = tid >> 4;
    __shared__ float ct[16][64];
    __shared__ float bt[16][64];
    int rowbase = b * L_ + c * CH;
    float acc[4][4];
#pragma unroll
    for (int i = 0; i < 4; i++)
#pragma unroll
        for (int j = 0; j < 4; j++) acc[i][j] = 0.f;

    for (int k0 = 0; k0 < DS; k0 += 16) {
        __syncthreads();
#pragma unroll
        for (int e = tid; e < 1024; e += 256) {
            int kk = e & 15, i = e >> 4;
            ct[kk][i] = g_xbc[(size_t)(rowbase + l0 + i) * CONVD + DI + DS + k0 + kk];
            bt[kk][i] = g_xbc[(size_t)(rowbase + s0 + i) * CONVD + DI + k0 + kk];
        }
        __syncthreads();
#pragma unroll
        for (int kk = 0; kk < 16; kk++) {
            float4 a4 = *(const float4*)&ct[kk][ty * 4];
            float4 b4 = *(const float4*)&bt[kk][tx * 4];
            float a[4] = {a4.x, a4.y, a4.z, a4.w};
            float bb[4] = {b4.x, b4.y, b4.z, b4.w};
#pragma unroll
            for (int i = 0; i < 4; i++)
#pragma unroll
                for (int j = 0; j < 4; j++) acc[i][j] += a[i] * bb[j];
        }
    }
#pragma unroll
    for (int i = 0; i < 4; i++)
#pragma unroll
        for (int j = 0; j < 4; j++)
            g_cb[((size_t)z * CH + l0 + ty * 4 + i) * CH + s0 + tx * 4 + j] = acc[i][j];
}

// ------ K9 (tensorized): Y[256,64] = exp(acs)*(Cm@init^T) + (CB·L)@xd + D*xh --
// Decay matrix built with factorized exp: off-diagonal slabs use
// exp(al-as) = exp(al-R)*exp(R-as) with R = slab-end acs (both factors <= 1,
// overflow-free); only the diagonal slab keeps per-pair expf.
#define YW 20
#define YA_H 0
#define YA_L (256 * YW)
#define YB_H (2 * 256 * YW)
#define YB_L (2 * 256 * YW + 64 * YW)
#define YACS (2 * 256 * YW + 2 * 64 * YW)
#define YCF  (YACS + 256)
#define YSMEM ((YCF + 256) * 4)
__global__ __launch_bounds__(256) void y_tc_kernel(const float* __restrict__ Dvec) {
    extern __shared__ __align__(16) uint32_t S[];
    uint32_t* Ah = S + YA_H;
    uint32_t* Al = S + YA_L;
    uint32_t* Bh = S + YB_H;
    uint32_t* Bl = S + YB_L;
    float* acs_s = (float*)(S + YACS);
    float* cf_s = (float*)(S + YCF);
    uint32_t sb = smem_u32(S);

    int bid = blockIdx.x;  // (b*NCH + c)*NH + h
    int b = bid >> 8, c = (bid >> 5) & 7, h = bid & 31;
    int z = b * NCH + c;
    int tid = threadIdx.x, warp = tid >> 5, lane = tid & 31;
    int wm = warp & 3, wn = warp >> 2;  // 4 M-warps x 2 N-warps
    int g = lane >> 2, tg = lane & 3;
    int base = ((b * NH + h) * NCH + c) * CH;
    acs_s[tid] = g_acs[base + tid];
    int rowbase = b * L_ + c * CH;
    size_t initbase = (size_t)bid * HD * DS;

    // ldmatrix addresses
    int mat = lane >> 3, mrow = lane & 7;
    uint32_t a_adh[4], a_adl[4], b_adh[2], b_adl[2];
#pragma unroll
    for (int mt = 0; mt < 4; mt++) {
        int r = wm * 64 + mt * 16 + (mat & 1) * 8 + mrow;
        uint32_t off = (uint32_t)(r * YW + (mat >> 1) * 4) * 4;
        a_adh[mt] = sb + YA_H * 4 + off;
        a_adl[mt] = sb + YA_L * 4 + off;
    }
#pragma unroll
    for (int p = 0; p < 2; p++) {
        int n = wn * 32 + p * 16 + (mat >> 1) * 8 + mrow;
        uint32_t off = (uint32_t)(n * YW + (mat & 1) * 4) * 4;
        b_adh[p] = sb + YB_H * 4 + off;
        b_adl[p] = sb + YB_L * 4 + off;
    }

    float acc[4][4][4];
#pragma unroll
    for (int mt = 0; mt < 4; mt++)
#pragma unroll
        for (int nt = 0; nt < 4; nt++)
#pragma unroll
            for (int q = 0; q < 4; q++) acc[mt][nt][q] = 0.f;

    auto do_mma = [&](void) {
#pragma unroll
        for (int kk = 0; kk < 2; kk++) {
            uint32_t kb = kk * 32;
            uint32_t ahi[4][4], alo[4][4];
#pragma unroll
            for (int mt = 0; mt < 4; mt++) {
                ldsm4(ahi[mt], a_adh[mt] + kb);
                ldsm4(alo[mt], a_adl[mt] + kb);
            }
            uint32_t bhi[4][2], blo[4][2];
#pragma unroll
            for (int p = 0; p < 2; p++) {
                uint32_t t4[4];
                ldsm4(t4, b_adh[p] + kb);
                bhi[p * 2][0] = t4[0]; bhi[p * 2][1] = t4[1];
                bhi[p * 2 + 1][0] = t4[2]; bhi[p * 2 + 1][1] = t4[3];
                ldsm4(t4, b_adl[p] + kb);
                blo[p * 2][0] = t4[0]; blo[p * 2][1] = t4[1];
                blo[p * 2 + 1][0] = t4[2]; blo[p * 2 + 1][1] = t4[3];
            }
#pragma unroll
            for (int mt = 0; mt < 4; mt++)
#pragma unroll
                for (int nt = 0; nt < 4; nt++) {
                    mma_bf16(acc[mt][nt], ahi[mt], bhi[nt]);
                    mma_bf16(acc[mt][nt], ahi[mt], blo[nt]);
                    mma_bf16(acc[mt][nt], alo[mt], bhi[nt]);
                }
        }
    };

    // ---------------- Phase 1: Cm @ init^T, K = DS = 128 (4 slabs) ----------
    for (int ks = 0; ks < 4; ks++) {
        __syncthreads();
        {
            const float* cm = &g_xbc[(size_t)(rowbase + tid) * CONVD + DI + DS + ks * 32];
            uint32_t* dah = &Ah[tid * YW];
            uint32_t* dal = &Al[tid * YW];
#pragma unroll
            for (int j2 = 0; j2 < 16; j2++) {
                float2 v = ((const float2*)cm)[j2];
                dah[j2] = pack_bf16(v.x, v.y);
                dal[j2] = pack_bf16(v.x - bf16r(v.x), v.y - bf16r(v.y));
            }
        }
        {
            int p = tid >> 2, q0 = tid & 3;
            const float* ir = &g_init[initbase + (size_t)p * DS + ks * 32 + q0 * 8];
            uint32_t* dbh = &Bh[p * YW + q0 * 4];
            uint32_t* dbl = &Bl[p * YW + q0 * 4];
#pragma unroll
            for (int q = 0; q < 4; q++) {
                float2 v = ((const float2*)ir)[q];
                dbh[q] = pack_bf16(v.x, v.y);
                dbl[q] = pack_bf16(v.x - bf16r(v.x), v.y - bf16r(v.y));
            }
        }
        __syncthreads();
        do_mma();
    }

    // scale by exp(acs[l])
#pragma unroll
    for (int mt = 0; mt < 4; mt++) {
        int r0 = wm * 64 + mt * 16 + g;
        float e0 = __expf(acs_s[r0]);
        float e1 = __expf(acs_s[r0 + 8]);
#pragma unroll
        for (int nt = 0; nt < 4; nt++) {
            acc[mt][nt][0] *= e0; acc[mt][nt][1] *= e0;
            acc[mt][nt][2] *= e1; acc[mt][nt][3] *= e1;
        }
    }

    // column decay factors: cf[s] = exp(acs[s|31] - acs[s])  (<= 1, safe)
    cf_s[tid] = __expf(acs_s[tid | 31] - acs_s[tid]);

    // ---------------- Phase 2: (CB ∘ L) @ xd^T, K = CH = 256 (8 slabs) -------
    int wlast = wm * 64 + 63;
    for (int ss = 0; ss < 8; ss++) {
        int s0 = ss * 32;
        __syncthreads();
        {   // A: row l = tid, decayed CB (factorized off-diagonal)
            int l = tid;
            float al = acs_s[l];
            float R = acs_s[s0 + 31];
            const float* cbr = &g_cb[((size_t)z * CH + l) * CH + s0];
            uint32_t* dah = &Ah[l * YW];
            uint32_t* dal = &Al[l * YW];
            if (l < s0) {
#pragma unroll
                for (int j2 = 0; j2 < 16; j2++) { dah[j2] = 0u; dal[j2] = 0u; }
            } else if (l < s0 + 32) {
                // diagonal slab: per-pair exp on causal triangle
#pragma unroll
                for (int j2 = 0; j2 < 16; j2++) {
                    int s = s0 + 2 * j2;
                    float va = (s <= l) ? cbr[2 * j2] * __expf(al - acs_s[s]) : 0.f;
                    float vb = (s + 1 <= l) ? cbr[2 * j2 + 1] * __expf(al - acs_s[s + 1]) : 0.f;
                    dah[j2] = pack_bf16(va, vb);
                    dal[j2] = pack_bf16(va - bf16r(va), vb - bf16r(vb));
                }
            } else {
                // off-diagonal: exp(al-as) = rf * cf[s], both factors <= 1
                float rf = __expf(al - R);
#pragma unroll
                for (int j2 = 0; j2 < 16; j2++) {
                    float va = cbr[2 * j2] * (rf * cf_s[s0 + 2 * j2]);
                    float vb = cbr[2 * j2 + 1] * (rf * cf_s[s0 + 2 * j2 + 1]);
                    dah[j2] = pack_bf16(va, vb);
                    dal[j2] = pack_bf16(va - bf16r(va), vb - bf16r(vb));
                }
            }
        }
        {   // B transpose: warp w handles p-group w (8 p), lane = s offset
            int s = s0 + lane;
            int row = rowbase + s;
            float dtv = g_dt[row * NH + h];
            const float* xr = &g_xbc[(size_t)row * CONVD + h * HD + warp * 8];
            __nv_bfloat16* BhH = (__nv_bfloat16*)Bh;
            __nv_bfloat16* BlH = (__nv_bfloat16*)Bl;
#pragma unroll
            for (int q = 0; q < 8; q++) {
                int p = warp * 8 + q;
                float v = xr[q] * dtv;
                float hv = bf16r(v);
                BhH[p * (2 * YW) + lane] = __float2bfloat16(v);
                BlH[p * (2 * YW) + lane] = __float2bfloat16(v - hv);
            }
        }
        __syncthreads();
        if (s0 <= wlast) do_mma();
    }

    // epilogue: + D*xh, write y (fp32)
    float Dh = Dvec[h];
#pragma unroll
    for (int mt = 0; mt < 4; mt++) {
        int r = wm * 64 + mt * 16 + g;
#pragma unroll
        for (int nt = 0; nt < 4; nt++) {
            int p = wn * 32 + nt * 8 + tg * 2;
            float* a = acc[mt][nt];
#pragma unroll
            for (int q = 0; q < 4; q++) {
                int row = rowbase + r + (q >> 1) * 8;
                int pp = p + (q & 1);
                float xh = g_xbc[(size_t)row * CONVD + h * HD + pp];
                g_y[(size_t)row * DI + h * HD + pp] = a[q] + Dh * xh;
            }
        }
    }
}

// -------- K10: gated rmsnorm: y = rmsnorm(y*silu(z))*gw -> bf16 hi/lo --------
__global__ void gated_norm_kernel(const float* __restrict__ gw) {
    int row = blockIdx.x, tid = threadIdx.x;
    int d0 = tid * 8;
    const float* zr = &g_zx[(size_t)row * DPROJ + d0];
    const float* yr = &g_y[(size_t)row * DI + d0];
    float v[8];
    float local = 0.f;
#pragma unroll
    for (int q = 0; q < 2; q++) {
        float4 z4 = *(const float4*)(zr + q * 4);
        float4 y4 = *(const float4*)(yr + q * 4);
        float zz[4] = {z4.x, z4.y, z4.z, z4.w};
        float yy[4] = {y4.x, y4.y, y4.z, y4.w};
#pragma unroll
        for (int j = 0; j < 4; j++) {
            float t = yy[j] * (zz[j] / (1.f + __expf(-zz[j])));
            v[q * 4 + j] = t;
            local += t * t;
        }
    }
    float tot = blockReduceSum256(local);
    float r = rsqrtf(tot / (float)DI + 1e-5f);
    int o = row * (DI / 2) + tid * 4;
#pragma unroll
    for (int j = 0; j < 4; j++) {
        float a = v[2 * j] * r * gw[d0 + 2 * j];
        float b = v[2 * j + 1] * r * gw[d0 + 2 * j + 1];
        g_yh[o + j] = pack_bf16(a, b);
        g_yl[o + j] = pack_bf16(a - bf16r(a), b - bf16r(b));
    }
}

// ---------------- launch ----------------
extern "C" void kernel_launch(void* const* d_in, const int* in_sizes, int n_in,
                              void* d_out, int out_size) {
    const float* x         = (const float*)d_in[0];
    const float* norm_w    = (const float*)d_in[1];
    const float* in_proj_w = (const float*)d_in[2];
    const float* conv_w    = (const float*)d_in[3];
    const float* conv_b    = (const float*)d_in[4];
    const float* dt_bias   = (const float*)d_in[5];
    const float* A_log     = (const float*)d_in[6];
    const float* Dv        = (const float*)d_in[7];
    const float* gnorm_w   = (const float*)d_in[8];
    const float* out_proj_w= (const float*)d_in[9];
    float* out = (float*)d_out;

    float *pzx;
    uint32_t *puh, *pul, *pyh, *pyl, *pwih, *pwil, *pwoh, *pwol;
    cudaGetSymbolAddress((void**)&pzx, g_zx);
    cudaGetSymbolAddress((void**)&puh, g_uh);
    cudaGetSymbolAddress((void**)&pul, g_ul);
    cudaGetSymbolAddress((void**)&pyh, g_yh);
    cudaGetSymbolAddress((void**)&pyl, g_yl);
    cudaGetSymbolAddress((void**)&pwih, g_wih);
    cudaGetSymbolAddress((void**)&pwil, g_wil);
    cudaGetSymbolAddress((void**)&pwoh, g_woh);
    cudaGetSymbolAddress((void**)&pwol, g_wol);

    cudaFuncSetAttribute(mma_nt_pre, cudaFuncAttributeMaxDynamicSharedMemorySize, GSMEM);
    cudaFuncSetAttribute(y_tc_kernel, cudaFuncAttributeMaxDynamicSharedMemorySize, YSMEM);

    cvt_pairs_kernel<<<(DPROJ * DM / 2 + 255) / 256, 256>>>(in_proj_w, pwih, pwil,
                                                            DPROJ * DM / 2);
    cvt_pairs_kernel<<<(DM * DI / 2 + 255) / 256, 256>>>(out_proj_w, pwoh, pwol,
                                                         DM * DI / 2);

    rmsnorm_x_kernel<<<ROWS, 256>>>(x, norm_w);
    mma_nt_pre<<<dim3((DPROJ + 127) / 128, ROWS / 128), 256, GSMEM>>>(
        puh, pul, pwih, pwil, pzx, nullptr, ROWS, DPROJ, DM, 0);
    conv_silu_kernel<<<(ROWS * CONVD) / 256, 256>>>(conv_w, conv_b);
    dt_kernel<<<(ROWS * NH) / 256, 256>>>(dt_bias);
    acs_kernel<<<B_ * NH * NCH, 256>>>(A_log);
    states_kernel<<<B_ * NCH * NH, 256>>>();
    recur_kernel<<<(B_ * NH * HD * DS) / 256, 256>>>();
    cb_kernel<<<dim3(4, 4, B_ * NCH), 256>>>();
    y_tc_kernel<<<B_ * NCH * NH, 256, YSMEM>>>(Dv);
    gated_norm_kernel<<<ROWS, 256>>>(gnorm_w);
    mma_nt_pre<<<dim3(DM / 128, ROWS / 128), 256, GSMEM>>>(
        pyh, pyl, pwoh, pwol, out, x, ROWS, DM, DI, 1);
}

// round 9
// speedup vs baseline: 2.3698x; 1.1114x over previous
#include <cuda_runtime.h>
#include <cuda_bf16.h>
#include <math.h>
#include <stdint.h>

// ---------------- problem constants ----------------
#define B_    2
#define L_    2048
#define DM    1024
#define DI    2048
#define NH    32
#define HD    64
#define DS    128
#define CONVD 2304
#define DPROJ 4384
#define NCH   8
#define CH    256
#define ROWS  4096
#define NBID  (B_ * NCH * NH)   // 512

// ---------------- scratch (device globals) ----------------
__device__ float g_zx[(size_t)ROWS * DPROJ];
__device__ float g_xbc[(size_t)ROWS * CONVD];
__device__ float g_dt[ROWS * NH];
__device__ float g_acs[B_ * NH * NCH * CH];
__device__ float g_states[(size_t)B_ * NCH * NH * HD * DS];
__device__ float g_init[(size_t)B_ * NCH * NH * HD * DS];
__device__ float g_cb[(size_t)B_ * NCH * CH * CH];
__device__ float g_y[(size_t)ROWS * DI];

// packed bf16x2 hi/lo operand arrays
__device__ uint32_t g_uh[ROWS * DM / 2];
__device__ uint32_t g_ul[ROWS * DM / 2];
__device__ uint32_t g_yh[(size_t)ROWS * DI / 2];
__device__ uint32_t g_yl[(size_t)ROWS * DI / 2];
__device__ uint32_t g_wih[(size_t)DPROJ * DM / 2];
__device__ uint32_t g_wil[(size_t)DPROJ * DM / 2];
__device__ uint32_t g_woh[(size_t)DM * DI / 2];
__device__ uint32_t g_wol[(size_t)DM * DI / 2];

// SSD precomputed operands (bf16x2 packed, [.. , k(l) contiguous])
__device__ uint32_t g_xdp_h[(size_t)NBID * HD * (CH / 2)];   // x*dt, [bid][p][l/2]
__device__ uint32_t g_xdp_l[(size_t)NBID * HD * (CH / 2)];
__device__ uint32_t g_xds_h[(size_t)NBID * HD * (CH / 2)];   // x*dt*decay_states
__device__ uint32_t g_xds_l[(size_t)NBID * HD * (CH / 2)];
__device__ uint32_t g_bmt_h[(size_t)B_ * NCH * DS * (CH / 2)];  // Bm^T [z][n][l/2]
__device__ uint32_t g_bmt_l[(size_t)B_ * NCH * DS * (CH / 2)];

// ---------------- helpers ----------------
__device__ __forceinline__ float blockReduceSum256(float v) {
    __shared__ float ws[8];
    __shared__ float tot;
    int lane = threadIdx.x & 31, wid = threadIdx.x >> 5;
#pragma unroll
    for (int o = 16; o; o >>= 1) v += __shfl_xor_sync(0xffffffffu, v, o);
    if (lane == 0) ws[wid] = v;
    __syncthreads();
    if (threadIdx.x == 0) {
        float s = 0.f;
#pragma unroll
        for (int i = 0; i < 8; i++) s += ws[i];
        tot = s;
    }
    __syncthreads();
    return tot;
}

__device__ __forceinline__ uint32_t pack_bf16(float a, float b) {
    __nv_bfloat162 h = __floats2bfloat162_rn(a, b);
    return *(uint32_t*)&h;
}

__device__ __forceinline__ float bf16r(float v) {
    return __bfloat162float(__float2bfloat16(v));
}

__device__ __forceinline__ uint32_t smem_u32(const void* p) {
    uint32_t a;
    asm("{ .reg .u64 t; cvta.to.shared.u64 t, %1; cvt.u32.u64 %0, t; }"
        : "=r"(a) : "l"(p));
    return a;
}

__device__ __forceinline__ void mma_bf16(float* d, const uint32_t* a, const uint32_t* b) {
    asm volatile(
        "mma.sync.aligned.m16n8k16.row.col.f32.bf16.bf16.f32 "
        "{%0,%1,%2,%3}, {%4,%5,%6,%7}, {%8,%9}, {%0,%1,%2,%3};"
        : "+f"(d[0]), "+f"(d[1]), "+f"(d[2]), "+f"(d[3])
        : "r"(a[0]), "r"(a[1]), "r"(a[2]), "r"(a[3]), "r"(b[0]), "r"(b[1]));
}

__device__ __forceinline__ void ldsm4(uint32_t* r, uint32_t addr) {
    asm volatile("ldmatrix.sync.aligned.m8n8.x4.shared.b16 {%0,%1,%2,%3}, [%4];"
                 : "=r"(r[0]), "=r"(r[1]), "=r"(r[2]), "=r"(r[3]) : "r"(addr));
}

__device__ __forceinline__ void cp16(uint32_t dst, const void* src, bool ok) {
    if (ok)
        asm volatile("cp.async.cg.shared.global [%0], [%1], 16;"
                     :: "r"(dst), "l"(src) : "memory");
    else
        asm volatile("cp.async.cg.shared.global [%0], [%1], 16, 0;"
                     :: "r"(dst), "l"(src) : "memory");
}

// ---------------- K0: split fp32 pairs -> bf16 hi/lo packed ----------
__global__ void cvt_pairs_kernel(const float* __restrict__ W,
                                 uint32_t* __restrict__ Wh,
                                 uint32_t* __restrict__ Wl, int npairs) {
    int i = blockIdx.x * blockDim.x + threadIdx.x;
    if (i < npairs) {
        float2 v = ((const float2*)W)[i];
        Wh[i] = pack_bf16(v.x, v.y);
        Wl[i] = pack_bf16(v.x - bf16r(v.x), v.y - bf16r(v.y));
    }
}

// ---------------- K1: rmsnorm(x) -> bf16 hi/lo ----------------
__global__ void rmsnorm_x_kernel(const float* __restrict__ x,
                                 const float* __restrict__ w) {
    int row = blockIdx.x, tid = threadIdx.x;
    const float4 v = ((const float4*)(x + (size_t)row * DM))[tid];
    const float4 wv = ((const float4*)w)[tid];
    float local = v.x * v.x + v.y * v.y + v.z * v.z + v.w * v.w;
    float tot = blockReduceSum256(local);
    float r = rsqrtf(tot / (float)DM + 1e-5f);
    float u0 = v.x * r * wv.x, u1 = v.y * r * wv.y;
    float u2 = v.z * r * wv.z, u3 = v.w * r * wv.w;
    int o = row * (DM / 2) + tid * 2;
    g_uh[o] = pack_bf16(u0, u1);
    g_uh[o + 1] = pack_bf16(u2, u3);
    g_ul[o] = pack_bf16(u0 - bf16r(u0), u1 - bf16r(u1));
    g_ul[o + 1] = pack_bf16(u2 - bf16r(u2), u3 - bf16r(u3));
}

// ------- tensor-core NT GEMM, preconverted bf16 hi/lo, cp.async 2-stage -------
#define UPS   (4 * 128 * 20)
#define GSMEM (2 * UPS * 4)
__global__ __launch_bounds__(256) void mma_nt_pre(const uint32_t* __restrict__ Ahg,
                                                  const uint32_t* __restrict__ Alg,
                                                  const uint32_t* __restrict__ Bhg,
                                                  const uint32_t* __restrict__ Blg,
                                                  float* __restrict__ C,
                                                  const float* __restrict__ resid,
                                                  int M, int N, int K, int addRes) {
    extern __shared__ __align__(16) uint32_t S[];
    uint32_t sbase = smem_u32(S);
    int tid = threadIdx.x;
    int warp = tid >> 5, lane = tid & 31;
    int wm = warp & 1, wn = warp >> 1;
    int bm = blockIdx.y * 128, bn = blockIdx.x * 128;
    int g = lane >> 2, tg = lane & 3;
    int K2 = K >> 1;

    int lrow = tid >> 1, lhalf = tid & 1;
    const uint32_t* pA[2] = {Ahg + (size_t)(bm + lrow) * K2 + lhalf * 8,
                             Alg + (size_t)(bm + lrow) * K2 + lhalf * 8};
    bool okB = (bn + lrow) < N;
    int brow = okB ? (bn + lrow) : 0;
    const uint32_t* pB[2] = {Bhg + (size_t)brow * K2 + lhalf * 8,
                             Blg + (size_t)brow * K2 + lhalf * 8};
    uint32_t dto = (uint32_t)(lrow * 20 + lhalf * 8) * 4;

    int mat = lane >> 3, mrow = lane & 7;
    uint32_t a_ad[4], b_ad[2];
#pragma unroll
    for (int mt = 0; mt < 4; mt++) {
        int r = wm * 64 + mt * 16 + (mat & 1) * 8 + mrow;
        a_ad[mt] = sbase + (uint32_t)(r * 20 + (mat >> 1) * 4) * 4;
    }
#pragma unroll
    for (int p = 0; p < 2; p++) {
        int n = wn * 32 + p * 16 + (mat >> 1) * 8 + mrow;
        b_ad[p] = sbase + (uint32_t)(n * 20 + (mat & 1) * 4) * 4;
    }

    float acc[4][4][4];
#pragma unroll
    for (int mt = 0; mt < 4; mt++)
#pragma unroll
        for (int nt = 0; nt < 4; nt++)
#pragma unroll
            for (int q = 0; q < 4; q++) acc[mt][nt][q] = 0.f;

    int nslab = K >> 5;

    auto issue = [&](int st, int sl) {
        int ko = sl * 16;
        uint32_t db = sbase + (uint32_t)(st * UPS) * 4 + dto;
#pragma unroll
        for (int t = 0; t < 2; t++) {
            cp16(db + (uint32_t)(t * 2560 * 4), pA[t] + ko, true);
            cp16(db + (uint32_t)(t * 2560 * 4) + 16, pA[t] + ko + 4, true);
            cp16(db + (uint32_t)((2 + t) * 2560 * 4), pB[t] + ko, okB);
            cp16(db + (uint32_t)((2 + t) * 2560 * 4) + 16, pB[t] + ko + 4, okB);
        }
        asm volatile("cp.async.commit_group;" ::: "memory");
    };

    issue(0, 0);
    int st = 0;
    for (int i = 0; i < nslab; i++) {
        if (i + 1 < nslab) {
            issue(st ^ 1, i + 1);
            asm volatile("cp.async.wait_group 1;" ::: "memory");
        } else {
            asm volatile("cp.async.wait_group 0;" ::: "memory");
        }
        __syncthreads();
        uint32_t so = (uint32_t)(st * UPS) * 4;
#pragma unroll
        for (int kk = 0; kk < 2; kk++) {
            uint32_t kb = so + kk * 32;
            uint32_t ahi[4][4], alo[4][4];
#pragma unroll
            for (int mt = 0; mt < 4; mt++) {
                ldsm4(ahi[mt], a_ad[mt] + kb);
                ldsm4(alo[mt], a_ad[mt] + kb + 2560 * 4);
            }
            uint32_t bhi[4][2], blo[4][2];
#pragma unroll
            for (int p = 0; p < 2; p++) {
                uint32_t t4[4];
                ldsm4(t4, b_ad[p] + kb + 2 * 2560 * 4);
                bhi[p * 2][0] = t4[0]; bhi[p * 2][1] = t4[1];
                bhi[p * 2 + 1][0] = t4[2]; bhi[p * 2 + 1][1] = t4[3];
                ldsm4(t4, b_ad[p] + kb + 3 * 2560 * 4);
                blo[p * 2][0] = t4[0]; blo[p * 2][1] = t4[1];
                blo[p * 2 + 1][0] = t4[2]; blo[p * 2 + 1][1] = t4[3];
            }
#pragma unroll
            for (int mt = 0; mt < 4; mt++)
#pragma unroll
                for (int nt = 0; nt < 4; nt++) {
                    mma_bf16(acc[mt][nt], ahi[mt], bhi[nt]);
                    mma_bf16(acc[mt][nt], ahi[mt], blo[nt]);
                    mma_bf16(acc[mt][nt], alo[mt], bhi[nt]);
                }
        }
        __syncthreads();
        st ^= 1;
    }

#pragma unroll
    for (int mt = 0; mt < 4; mt++) {
        int row = bm + wm * 64 + mt * 16 + g;
#pragma unroll
        for (int nt = 0; nt < 4; nt++) {
            int col = bn + wn * 32 + nt * 8 + tg * 2;
            if (col < N) {
                float* a = acc[mt][nt];
                size_t i0 = (size_t)row * N + col;
                size_t i1 = (size_t)(row + 8) * N + col;
                if (addRes) {
                    a[0] += resid[i0]; a[1] += resid[i0 + 1];
                    a[2] += resid[i1]; a[3] += resid[i1 + 1];
                }
                C[i0] = a[0]; C[i0 + 1] = a[1];
                C[i1] = a[2]; C[i1 + 1] = a[3];
            }
        }
    }
}

// ---------------- K3: depthwise causal conv (width 4) + bias + silu ----------
__global__ void conv_silu_kernel(const float* __restrict__ conv_w,
                                 const float* __restrict__ conv_b) {
    int idx = blockIdx.x * blockDim.x + threadIdx.x;
    int c = idx % CONVD;
    int row = idx / CONVD;
    int l = row & (L_ - 1);
    const float* w = conv_w + c * 4;
    float acc = conv_b[c];
#pragma unroll
    for (int j = 0; j < 4; j++) {
        int ls = l - 3 + j;
        if (ls >= 0)
            acc += w[j] * g_zx[(size_t)(row - 3 + j) * DPROJ + DI + c];
    }
    float s = acc / (1.f + __expf(-acc));
    g_xbc[(size_t)row * CONVD + c] = s;
}

// ---------------- K4: dt = softplus(dt_raw + dt_bias) ----------
__global__ void dt_kernel(const float* __restrict__ dt_bias) {
    int idx = blockIdx.x * blockDim.x + threadIdx.x;
    int h = idx & (NH - 1);
    int row = idx >> 5;
    float v = g_zx[(size_t)row * DPROJ + (DI + CONVD) + h] + dt_bias[h];
    float sp = (v > 20.f) ? v : log1pf(__expf(v));
    g_dt[row * NH + h] = sp;
}

// ---------------- K5: per-chunk cumsum of a = dt * A ----------
__global__ void acs_kernel(const float* __restrict__ A_log) {
    int bid = blockIdx.x;
    int b = bid >> 8, h = (bid >> 3) & 31, c = bid & 7;
    int l = threadIdx.x;
    int row = b * L_ + c * CH + l;
    float A = -__expf(A_log[h]);
    __shared__ float s[CH];
    s[l] = g_dt[row * NH + h] * A;
    __syncthreads();
#pragma unroll
    for (int off = 1; off < CH; off <<= 1) {
        float v = (l >= off) ? s[l - off] : 0.f;
        __syncthreads();
        s[l] += v;
        __syncthreads();
    }
    g_acs[bid * CH + l] = s[l];
}

// ----- K5b: xdT precompute: [bid][p][l] bf16 hi/lo, plain + decay-folded -----
#define XDT_SMEM (256 * 68 * 4)
__global__ __launch_bounds__(256) void xdt_kernel() {
    extern __shared__ float sx[];  // [256][68]
    __shared__ float sdt[CH], sdec[CH];
    int bid = blockIdx.x;  // (b*NCH + c)*NH + h
    int b = bid >> 8, c = (bid >> 5) & 7, h = bid & 31;
    int tid = threadIdx.x;
    int rowbase = b * L_ + c * CH;
    int base = ((b * NH + h) * NCH + c) * CH;
    float acs255 = g_acs[base + CH - 1];
    {
        int l = tid, row = rowbase + l;
        const float* xr = &g_xbc[(size_t)row * CONVD + h * HD];
#pragma unroll
        for (int p4 = 0; p4 < 16; p4++) {
            float4 v = ((const float4*)xr)[p4];
            *(float4*)&sx[l * 68 + p4 * 4] = v;
        }
        sdt[l] = g_dt[row * NH + h];
        sdec[l] = __expf(acs255 - g_acs[base + l]);
    }
    __syncthreads();
    int warp = tid >> 5, lane = tid & 31;
    size_t ob = (size_t)bid * HD * (CH / 2);
#pragma unroll
    for (int pp = 0; pp < 8; pp++) {
        int p = warp * 8 + pp;
        uint32_t oh[4], ol[4], osh[4], osl[4];
#pragma unroll
        for (int k = 0; k < 4; k++) {
            int cu = lane * 4 + k;
            int l = cu * 2;
            float va = sx[l * 68 + p] * sdt[l];
            float vb = sx[(l + 1) * 68 + p] * sdt[l + 1];
            oh[k] = pack_bf16(va, vb);
            ol[k] = pack_bf16(va - bf16r(va), vb - bf16r(vb));
            float wa = va * sdec[l], wb = vb * sdec[l + 1];
            osh[k] = pack_bf16(wa, wb);
            osl[k] = pack_bf16(wa - bf16r(wa), wb - bf16r(wb));
        }
        size_t o = ob + (size_t)p * (CH / 2) + lane * 4;
        *(uint4*)&g_xdp_h[o] = *(uint4*)oh;
        *(uint4*)&g_xdp_l[o] = *(uint4*)ol;
        *(uint4*)&g_xds_h[o] = *(uint4*)osh;
        *(uint4*)&g_xds_l[o] = *(uint4*)osl;
    }
}

// ----- K5c: Bm^T precompute per (b,c): [z][n][l] bf16 hi/lo -----
#define BMT_SMEM (128 * 132 * 4)
__global__ __launch_bounds__(256) void bmt_kernel() {
    extern __shared__ float sx[];  // [128][132]
    int z = blockIdx.y, pass = blockIdx.x;
    int b = z >> 3, c = z & 7;
    int tid = threadIdx.x;
    int rowbase = b * L_ + c * CH + pass * 128;
    {
        int l = tid & 127, half = tid >> 7;
        const float* br = &g_xbc[(size_t)(rowbase + l) * CONVD + DI + half * 64];
#pragma unroll
        for (int k4 = 0; k4 < 16; k4++) {
            float4 v = ((const float4*)br)[k4];
            *(float4*)&sx[l * 132 + half * 64 + k4 * 4] = v;
        }
    }
    __syncthreads();
    int warp = tid >> 5, lane = tid & 31;
#pragma unroll
    for (int nn = 0; nn < 16; nn++) {
        int n = warp * 16 + nn;
        uint32_t h2[2], l2[2];
#pragma unroll
        for (int k = 0; k < 2; k++) {
            int cu = lane * 2 + k;
            float va = sx[(2 * cu) * 132 + n];
            float vb = sx[(2 * cu + 1) * 132 + n];
            h2[k] = pack_bf16(va, vb);
            l2[k] = pack_bf16(va - bf16r(va), vb - bf16r(vb));
        }
        size_t o = ((size_t)z * DS + n) * (CH / 2) + pass * 64 + lane * 2;
        *(uint2*)&g_bmt_h[o] = *(uint2*)h2;
        *(uint2*)&g_bmt_l[o] = *(uint2*)l2;
    }
}

// ------ K6 (tensorized): states[n,p] = sum_l BmT[n,l] * xds[p,l] ------
#define SSW 20
#define S_AH 0
#define S_AL (128 * SSW)
#define S_BH (2 * 128 * SSW)
#define S_BL (2 * 128 * SSW + 64 * SSW)
__global__ __launch_bounds__(256) void states_tc_kernel() {
    __shared__ __align__(16) uint32_t S[2 * 128 * SSW + 2 * 64 * SSW];
    uint32_t sb = smem_u32(S);
    int bid = blockIdx.x;  // (b*NCH + c)*NH + h
    int b = bid >> 8, c = (bid >> 5) & 7;
    int z = b * NCH + c;
    int tid = threadIdx.x, warp = tid >> 5, lane = tid & 31;
    int wm = warp & 3, wn = warp >> 2;  // 4 M(n)-warps x 2 N(p)-warps
    int g = lane >> 2, tg = lane & 3;
    int mat = lane >> 3, mrow = lane & 7;

    uint32_t a_adh[2], a_adl[2], b_adh[2], b_adl[2];
#pragma unroll
    for (int mt = 0; mt < 2; mt++) {
        int r = wm * 32 + mt * 16 + (mat & 1) * 8 + mrow;
        uint32_t off = (uint32_t)(r * SSW + (mat >> 1) * 4) * 4;
        a_adh[mt] = sb + S_AH * 4 + off;
        a_adl[mt] = sb + S_AL * 4 + off;
    }
#pragma unroll
    for (int p = 0; p < 2; p++) {
        int n = wn * 32 + p * 16 + (mat >> 1) * 8 + mrow;
        uint32_t off = (uint32_t)(n * SSW + (mat & 1) * 4) * 4;
        b_adh[p] = sb + S_BH * 4 + off;
        b_adl[p] = sb + S_BL * 4 + off;
    }

    float acc[2][4][4];
#pragma unroll
    for (int mt = 0; mt < 2; mt++)
#pragma unroll
        for (int nt = 0; nt < 4; nt++)
#pragma unroll
            for (int q = 0; q < 4; q++) acc[mt][nt][q] = 0.f;

    for (int j = 0; j < 8; j++) {
        __syncthreads();
        {   // A: BmT rows n (128)
            int n = tid >> 1, half = tid & 1;
            size_t src = ((size_t)z * DS + n) * (CH / 2) + j * 16 + half * 8;
            uint32_t d = sb + (uint32_t)(S_AH + n * SSW + half * 8) * 4;
            cp16(d, &g_bmt_h[src], true);
            cp16(d + 16, &g_bmt_h[src + 4], true);
            uint32_t d2 = sb + (uint32_t)(S_AL + n * SSW + half * 8) * 4;
            cp16(d2, &g_bmt_l[src], true);
            cp16(d2 + 16, &g_bmt_l[src + 4], true);
        }
        {   // B: xds rows p (64)
            int p = tid >> 2, q = tid & 3;
            size_t src = ((size_t)bid * HD + p) * (CH / 2) + j * 16 + q * 4;
            cp16(sb + (uint32_t)(S_BH + p * SSW + q * 4) * 4, &g_xds_h[src], true);
            cp16(sb + (uint32_t)(S_BL + p * SSW + q * 4) * 4, &g_xds_l[src], true);
        }
        asm volatile("cp.async.commit_group;" ::: "memory");
        asm volatile("cp.async.wait_group 0;" ::: "memory");
        __syncthreads();
#pragma unroll
        for (int kk = 0; kk < 2; kk++) {
            uint32_t kb = kk * 32;
            uint32_t ahi[2][4], alo[2][4];
#pragma unroll
            for (int mt = 0; mt < 2; mt++) {
                ldsm4(ahi[mt], a_adh[mt] + kb);
                ldsm4(alo[mt], a_adl[mt] + kb);
            }
            uint32_t bhi[4][2], blo[4][2];
#pragma unroll
            for (int p = 0; p < 2; p++) {
                uint32_t t4[4];
                ldsm4(t4, b_adh[p] + kb);
                bhi[p * 2][0] = t4[0]; bhi[p * 2][1] = t4[1];
                bhi[p * 2 + 1][0] = t4[2]; bhi[p * 2 + 1][1] = t4[3];
                ldsm4(t4, b_adl[p] + kb);
                blo[p * 2][0] = t4[0]; blo[p * 2][1] = t4[1];
                blo[p * 2 + 1][0] = t4[2]; blo[p * 2 + 1][1] = t4[3];
            }
#pragma unroll
            for (int mt = 0; mt < 2; mt++)
#pragma unroll
                for (int nt = 0; nt < 4; nt++) {
                    mma_bf16(acc[mt][nt], ahi[mt], bhi[nt]);
                    mma_bf16(acc[mt][nt], ahi[mt], blo[nt]);
                    mma_bf16(acc[mt][nt], alo[mt], bhi[nt]);
                }
        }
    }

    size_t out = (size_t)bid * HD * DS;
#pragma unroll
    for (int mt = 0; mt < 2; mt++) {
#pragma unroll
        for (int nt = 0; nt < 4; nt++) {
            float* a = acc[mt][nt];
#pragma unroll
            for (int q = 0; q < 4; q++) {
                int n = wm * 32 + mt * 16 + g + (q >> 1) * 8;
                int p = wn * 32 + nt * 8 + tg * 2 + (q & 1);
                g_states[out + (size_t)p * DS + n] = a[q];
            }
        }
    }
}

// ---------------- K7: chunk recurrence (serial over 8 chunks) ----------
__global__ void recur_kernel() {
    int idx = blockIdx.x * blockDim.x + threadIdx.x;
    int n = idx & 127;
    int p = (idx >> 7) & 63;
    int h = (idx >> 13) & 31;
    int b = idx >> 18;
    float run = 0.f;
#pragma unroll
    for (int c = 0; c < NCH; c++) {
        size_t sidx = ((size_t)((b * NCH + c) * NH + h) * HD + p) * DS + n;
        g_init[sidx] = run;
        float cs = g_acs[((b * NH + h) * NCH + c) * CH + CH - 1];
        run = run * __expf(cs) + g_states[sidx];
    }
}

// ---------------- K8: CB[l,s] = Cm[l]·Bm[s] per (b,c) ----------
__global__ __launch_bounds__(256) void cb_kernel() {
    int z = blockIdx.z;
    int b = z >> 3, c = z & 7;
    int l0 = blockIdx.y * 64, s0 = blockIdx.x * 64;
    int tid = threadIdx.x;
    int tx = tid & 15, ty = tid >> 4;
    __shared__ float ct[16][64];
    __shared__ float bt[16][64];
    int rowbase = b * L_ + c * CH;
    float acc[4][4];
#pragma unroll
    for (int i = 0; i < 4; i++)
#pragma unroll
        for (int j = 0; j < 4; j++) acc[i][j] = 0.f;

    for (int k0 = 0; k0 < DS; k0 += 16) {
        __syncthreads();
#pragma unroll
        for (int e = tid; e < 1024; e += 256) {
            int kk = e & 15, i = e >> 4;
            ct[kk][i] = g_xbc[(size_t)(rowbase + l0 + i) * CONVD + DI + DS + k0 + kk];
            bt[kk][i] = g_xbc[(size_t)(rowbase + s0 + i) * CONVD + DI + k0 + kk];
        }
        __syncthreads();
#pragma unroll
        for (int kk = 0; kk < 16; kk++) {
            float4 a4 = *(const float4*)&ct[kk][ty * 4];
            float4 b4 = *(const float4*)&bt[kk][tx * 4];
            float a[4] = {a4.x, a4.y, a4.z, a4.w};
            float bb[4] = {b4.x, b4.y, b4.z, b4.w};
#pragma unroll
            for (int i = 0; i < 4; i++)
#pragma unroll
                for (int j = 0; j < 4; j++) acc[i][j] += a[i] * bb[j];
        }
    }
#pragma unroll
    for (int i = 0; i < 4; i++)
#pragma unroll
        for (int j = 0; j < 4; j++)
            g_cb[((size_t)z * CH + l0 + ty * 4 + i) * CH + s0 + tx * 4 + j] = acc[i][j];
}

// ------ K9 (tensorized): Y[256,64] = exp(acs)*(Cm@init^T) + (CB·L)@xd + D*xh --
#define YW 20
#define YA_H 0
#define YA_L (256 * YW)
#define YB_H (2 * 256 * YW)
#define YB_L (2 * 256 * YW + 64 * YW)
#define YACS (2 * 256 * YW + 2 * 64 * YW)
#define YCF  (YACS + 256)
#define YSMEM ((YCF + 256) * 4)
__global__ __launch_bounds__(256) void y_tc_kernel(const float* __restrict__ Dvec) {
    extern __shared__ __align__(16) uint32_t S[];
    uint32_t* Ah = S + YA_H;
    uint32_t* Al = S + YA_L;
    uint32_t* Bh = S + YB_H;
    uint32_t* Bl = S + YB_L;
    float* acs_s = (float*)(S + YACS);
    float* cf_s = (float*)(S + YCF);
    uint32_t sb = smem_u32(S);

    int bid = blockIdx.x;
    int b = bid >> 8, c = (bid >> 5) & 7, h = bid & 31;
    int z = b * NCH + c;
    int tid = threadIdx.x, warp = tid >> 5, lane = tid & 31;
    int wm = warp & 3, wn = warp >> 2;
    int g = lane >> 2, tg = lane & 3;
    int base = ((b * NH + h) * NCH + c) * CH;
    acs_s[tid] = g_acs[base + tid];
    int rowbase = b * L_ + c * CH;
    size_t initbase = (size_t)bid * HD * DS;

    int mat = lane >> 3, mrow = lane & 7;
    uint32_t a_adh[4], a_adl[4], b_adh[2], b_adl[2];
#pragma unroll
    for (int mt = 0; mt < 4; mt++) {
        int r = wm * 64 + mt * 16 + (mat & 1) * 8 + mrow;
        uint32_t off = (uint32_t)(r * YW + (mat >> 1) * 4) * 4;
        a_adh[mt] = sb + YA_H * 4 + off;
        a_adl[mt] = sb + YA_L * 4 + off;
    }
#pragma unroll
    for (int p = 0; p < 2; p++) {
        int n = wn * 32 + p * 16 + (mat >> 1) * 8 + mrow;
        uint32_t off = (uint32_t)(n * YW + (mat & 1) * 4) * 4;
        b_adh[p] = sb + YB_H * 4 + off;
        b_adl[p] = sb + YB_L * 4 + off;
    }

    float acc[4][4][4];
#pragma unroll
    for (int mt = 0; mt < 4; mt++)
#pragma unroll
        for (int nt = 0; nt < 4; nt++)
#pragma unroll
            for (int q = 0; q < 4; q++) acc[mt][nt][q] = 0.f;

    auto do_mma = [&](void) {
#pragma unroll
        for (int kk = 0; kk < 2; kk++) {
            uint32_t kb = kk * 32;
            uint32_t ahi[4][4], alo[4][4];
#pragma unroll
            for (int mt = 0; mt < 4; mt++) {
                ldsm4(ahi[mt], a_adh[mt] + kb);
                ldsm4(alo[mt], a_adl[mt] + kb);
            }
            uint32_t bhi[4][2], blo[4][2];
#pragma unroll
            for (int p = 0; p < 2; p++) {
                uint32_t t4[4];
                ldsm4(t4, b_adh[p] + kb);
                bhi[p * 2][0] = t4[0]; bhi[p * 2][1] = t4[1];
                bhi[p * 2 + 1][0] = t4[2]; bhi[p * 2 + 1][1] = t4[3];
                ldsm4(t4, b_adl[p] + kb);
                blo[p * 2][0] = t4[0]; blo[p * 2][1] = t4[1];
                blo[p * 2 + 1][0] = t4[2]; blo[p * 2 + 1][1] = t4[3];
            }
#pragma unroll
            for (int mt = 0; mt < 4; mt++)
#pragma unroll
                for (int nt = 0; nt < 4; nt++) {
                    mma_bf16(acc[mt][nt], ahi[mt], bhi[nt]);
                    mma_bf16(acc[mt][nt], ahi[mt], blo[nt]);
                    mma_bf16(acc[mt][nt], alo[mt], bhi[nt]);
                }
        }
    };

    // ---------------- Phase 1: Cm @ init^T ----------
    for (int ks = 0; ks < 4; ks++) {
        __syncthreads();
        {
            const float* cm = &g_xbc[(size_t)(rowbase + tid) * CONVD + DI + DS + ks * 32];
            uint32_t* dah = &Ah[tid * YW];
            uint32_t* dal = &Al[tid * YW];
#pragma unroll
            for (int j2 = 0; j2 < 16; j2++) {
                float2 v = ((const float2*)cm)[j2];
                dah[j2] = pack_bf16(v.x, v.y);
                dal[j2] = pack_bf16(v.x - bf16r(v.x), v.y - bf16r(v.y));
            }
        }
        {
            int p = tid >> 2, q0 = tid & 3;
            const float* ir = &g_init[initbase + (size_t)p * DS + ks * 32 + q0 * 8];
            uint32_t* dbh = &Bh[p * YW + q0 * 4];
            uint32_t* dbl = &Bl[p * YW + q0 * 4];
#pragma unroll
            for (int q = 0; q < 4; q++) {
                float2 v = ((const float2*)ir)[q];
                dbh[q] = pack_bf16(v.x, v.y);
                dbl[q] = pack_bf16(v.x - bf16r(v.x), v.y - bf16r(v.y));
            }
        }
        __syncthreads();
        do_mma();
    }

#pragma unroll
    for (int mt = 0; mt < 4; mt++) {
        int r0 = wm * 64 + mt * 16 + g;
        float e0 = __expf(acs_s[r0]);
        float e1 = __expf(acs_s[r0 + 8]);
#pragma unroll
        for (int nt = 0; nt < 4; nt++) {
            acc[mt][nt][0] *= e0; acc[mt][nt][1] *= e0;
            acc[mt][nt][2] *= e1; acc[mt][nt][3] *= e1;
        }
    }

    cf_s[tid] = __expf(acs_s[tid | 31] - acs_s[tid]);

    // ---------------- Phase 2: (CB ∘ L) @ xd^T ----------
    int wlast = wm * 64 + 63;
    for (int ss = 0; ss < 8; ss++) {
        int s0 = ss * 32;
        __syncthreads();
        {   // B: cp.async from precomputed xdT (plain)
            int p = tid >> 2, q = tid & 3;
            size_t src = ((size_t)bid * HD + p) * (CH / 2) + ss * 16 + q * 4;
            cp16(sb + (uint32_t)(YB_H + p * YW + q * 4) * 4, &g_xdp_h[src], true);
            cp16(sb + (uint32_t)(YB_L + p * YW + q * 4) * 4, &g_xdp_l[src], true);
            asm volatile("cp.async.commit_group;" ::: "memory");
        }
        {   // A: row l = tid, decayed CB (factorized off-diagonal)
            int l = tid;
            float al = acs_s[l];
            float R = acs_s[s0 + 31];
            const float* cbr = &g_cb[((size_t)z * CH + l) * CH + s0];
            uint32_t* dah = &Ah[l * YW];
            uint32_t* dal = &Al[l * YW];
            if (l < s0) {
#pragma unroll
                for (int j2 = 0; j2 < 16; j2++) { dah[j2] = 0u; dal[j2] = 0u; }
            } else if (l < s0 + 32) {
#pragma unroll
                for (int j2 = 0; j2 < 16; j2++) {
                    int s = s0 + 2 * j2;
                    float va = (s <= l) ? cbr[2 * j2] * __expf(al - acs_s[s]) : 0.f;
                    float vb = (s + 1 <= l) ? cbr[2 * j2 + 1] * __expf(al - acs_s[s + 1]) : 0.f;
                    dah[j2] = pack_bf16(va, vb);
                    dal[j2] = pack_bf16(va - bf16r(va), vb - bf16r(vb));
                }
            } else {
                float rf = __expf(al - R);
#pragma unroll
                for (int j2 = 0; j2 < 16; j2++) {
                    float va = cbr[2 * j2] * (rf * cf_s[s0 + 2 * j2]);
                    float vb = cbr[2 * j2 + 1] * (rf * cf_s[s0 + 2 * j2 + 1]);
                    dah[j2] = pack_bf16(va, vb);
                    dal[j2] = pack_bf16(va - bf16r(va), vb - bf16r(vb));
                }
            }
        }
        asm volatile("cp.async.wait_group 0;" ::: "memory");
        __syncthreads();
        if (s0 <= wlast) do_mma();
    }

    // epilogue: + D*xh, write y (fp32)
    float Dh = Dvec[h];
#pragma unroll
    for (int mt = 0; mt < 4; mt++) {
        int r = wm * 64 + mt * 16 + g;
#pragma unroll
        for (int nt = 0; nt < 4; nt++) {
            int p = wn * 32 + nt * 8 + tg * 2;
            float* a = acc[mt][nt];
#pragma unroll
            for (int q = 0; q < 4; q++) {
                int row = rowbase + r + (q >> 1) * 8;
                int pp = p + (q & 1);
                float xh = g_xbc[(size_t)row * CONVD + h * HD + pp];
                g_y[(size_t)row * DI + h * HD + pp] = a[q] + Dh * xh;
            }
        }
    }
}

// -------- K10: gated rmsnorm -> bf16 hi/lo --------
__global__ void gated_norm_kernel(const float* __restrict__ gw) {
    int row = blockIdx.x, tid = threadIdx.x;
    int d0 = tid * 8;
    const float* zr = &g_zx[(size_t)row * DPROJ + d0];
    const float* yr = &g_y[(size_t)row * DI + d0];
    float v[8];
    float local = 0.f;
#pragma unroll
    for (int q = 0; q < 2; q++) {
        float4 z4 = *(const float4*)(zr + q * 4);
        float4 y4 = *(const float4*)(yr + q * 4);
        float zz[4] = {z4.x, z4.y, z4.z, z4.w};
        float yy[4] = {y4.x, y4.y, y4.z, y4.w};
#pragma unroll
        for (int j = 0; j < 4; j++) {
            float t = yy[j] * (zz[j] / (1.f + __expf(-zz[j])));
            v[q * 4 + j] = t;
            local += t * t;
        }
    }
    float tot = blockReduceSum256(local);
    float r = rsqrtf(tot / (float)DI + 1e-5f);
    int o = row * (DI / 2) + tid * 4;
#pragma unroll
    for (int j = 0; j < 4; j++) {
        float a = v[2 * j] * r * gw[d0 + 2 * j];
        float b = v[2 * j + 1] * r * gw[d0 + 2 * j + 1];
        g_yh[o + j] = pack_bf16(a, b);
        g_yl[o + j] = pack_bf16(a - bf16r(a), b - bf16r(b));
    }
}

// ---------------- launch ----------------
extern "C" void kernel_launch(void* const* d_in, const int* in_sizes, int n_in,
                              void* d_out, int out_size) {
    const float* x         = (const float*)d_in[0];
    const float* norm_w    = (const float*)d_in[1];
    const float* in_proj_w = (const float*)d_in[2];
    const float* conv_w    = (const float*)d_in[3];
    const float* conv_b    = (const float*)d_in[4];
    const float* dt_bias   = (const float*)d_in[5];
    const float* A_log     = (const float*)d_in[6];
    const float* Dv        = (const float*)d_in[7];
    const float* gnorm_w   = (const float*)d_in[8];
    const float* out_proj_w= (const float*)d_in[9];
    float* out = (float*)d_out;

    float *pzx;
    uint32_t *puh, *pul, *pyh, *pyl, *pwih, *pwil, *pwoh, *pwol;
    cudaGetSymbolAddress((void**)&pzx, g_zx);
    cudaGetSymbolAddress((void**)&puh, g_uh);
    cudaGetSymbolAddress((void**)&pul, g_ul);
    cudaGetSymbolAddress((void**)&pyh, g_yh);
    cudaGetSymbolAddress((void**)&pyl, g_yl);
    cudaGetSymbolAddress((void**)&pwih, g_wih);
    cudaGetSymbolAddress((void**)&pwil, g_wil);
    cudaGetSymbolAddress((void**)&pwoh, g_woh);
    cudaGetSymbolAddress((void**)&pwol, g_wol);

    cudaFuncSetAttribute(mma_nt_pre, cudaFuncAttributeMaxDynamicSharedMemorySize, GSMEM);
    cudaFuncSetAttribute(y_tc_kernel, cudaFuncAttributeMaxDynamicSharedMemorySize, YSMEM);
    cudaFuncSetAttribute(xdt_kernel, cudaFuncAttributeMaxDynamicSharedMemorySize, XDT_SMEM);
    cudaFuncSetAttribute(bmt_kernel, cudaFuncAttributeMaxDynamicSharedMemorySize, BMT_SMEM);

    cvt_pairs_kernel<<<(DPROJ * DM / 2 + 255) / 256, 256>>>(in_proj_w, pwih, pwil,
                                                            DPROJ * DM / 2);
    cvt_pairs_kernel<<<(DM * DI / 2 + 255) / 256, 256>>>(out_proj_w, pwoh, pwol,
                                                         DM * DI / 2);

    rmsnorm_x_kernel<<<ROWS, 256>>>(x, norm_w);
    mma_nt_pre<<<dim3((DPROJ + 127) / 128, ROWS / 128), 256, GSMEM>>>(
        puh, pul, pwih, pwil, pzx, nullptr, ROWS, DPROJ, DM, 0);
    conv_silu_kernel<<<(ROWS * CONVD) / 256, 256>>>(conv_w, conv_b);
    dt_kernel<<<(ROWS * NH) / 256, 256>>>(dt_bias);
    acs_kernel<<<B_ * NH * NCH, 256>>>(A_log);
    xdt_kernel<<<NBID, 256, XDT_SMEM>>>();
    bmt_kernel<<<dim3(2, B_ * NCH), 256, BMT_SMEM>>>();
    states_tc_kernel<<<NBID, 256>>>();
    recur_kernel<<<(B_ * NH * HD * DS) / 256, 256>>>();
    cb_kernel<<<dim3(4, 4, B_ * NCH), 256>>>();
    y_tc_kernel<<<NBID, 256, YSMEM>>>(Dv);
    gated_norm_kernel<<<ROWS, 256>>>(gnorm_w);
    mma_nt_pre<<<dim3(DM / 128, ROWS / 128), 256, GSMEM>>>(
        pyh, pyl, pwoh, pwol, out, x, ROWS, DM, DI, 1);
}